// round 10
// baseline (speedup 1.0000x reference)
#include <cuda_runtime.h>
#include <math.h>
#include <stdint.h>

// ---------------- problem constants ----------------
#define NHH   4
#define DD    256
#define NN    8192
#define TT    2048
#define VOC   256
#define SPLITK 16
#define KSPL  2048              // NHH*NN/SPLITK
#define LNEPS 1e-5f
#define TWO_PI_F 6.28318530717958647692f

// ---------------- scratch (static device globals) ----
__device__ float g_x[TT * DD];
__device__ unsigned short g_xh[TT * DD];
__device__ unsigned short g_xl[TT * DD];
__device__ float g_xs[(size_t)NHH * TT * NN];
__device__ unsigned short g_sch[(size_t)NHH * TT * TT];   // scores hi (bf16)
__device__ unsigned short g_scl[(size_t)NHH * TT * TT];   // scores lo (bf16)
__device__ float g_ykv[(size_t)NHH * TT * DD];
__device__ unsigned short g_ykvh[(size_t)NHH * TT * DD];
__device__ unsigned short g_ykvl[(size_t)NHH * TT * DD];
__device__ float g_part[(size_t)SPLITK * TT * DD];
__device__ unsigned short g_qrh[(size_t)NHH * TT * NN];
__device__ unsigned short g_qrl[(size_t)NHH * TT * NN];
__device__ unsigned short g_xyh[(size_t)NHH * TT * NN];
__device__ unsigned short g_xyl[(size_t)NHH * TT * NN];
__device__ unsigned short g_ench[(size_t)NHH * DD * NN];
__device__ unsigned short g_encl[(size_t)NHH * DD * NN];
__device__ unsigned short g_encvh[(size_t)NHH * DD * NN];
__device__ unsigned short g_encvl[(size_t)NHH * DD * NN];
__device__ unsigned short g_dech[(size_t)NHH * NN * DD];
__device__ unsigned short g_decl[(size_t)NHH * NN * DD];

enum { EM_NONE = 0 };
enum { HM_NONE = 0, HM_ROPE = 1, HM_MULXY = 2 };

typedef unsigned long long u64;

// ---------------- packed f32x2 helpers ----------------
__device__ __forceinline__ void ffma2(u64& d, u64 a, u64 b) {
    asm("fma.rn.f32x2 %0, %1, %2, %0;" : "+l"(d) : "l"(a), "l"(b));
}
__device__ __forceinline__ u64 dup2(float x) {
    u64 r;
    asm("mov.b64 %0, {%1, %1};" : "=l"(r) : "r"(__float_as_uint(x)));
    return r;
}
__device__ __forceinline__ void unpack2(u64 v, float& lo, float& hi) {
    unsigned a, b;
    asm("mov.b64 {%0, %1}, %2;" : "=r"(a), "=r"(b) : "l"(v));
    lo = __uint_as_float(a); hi = __uint_as_float(b);
}

// ---------------- bf16 bit helpers ----------------
__device__ __forceinline__ unsigned short f2bf(float x) {
    unsigned u = __float_as_uint(x);
    unsigned r = (u + 0x7FFFu + ((u >> 16) & 1u)) >> 16;
    return (unsigned short)r;
}
__device__ __forceinline__ float bf2f(unsigned short b) {
    return __uint_as_float((unsigned)b << 16);
}
__device__ __forceinline__ unsigned pack_hl(float a, float b,
                                            unsigned short& la, unsigned short& lb) {
    unsigned short ha = f2bf(a), hb = f2bf(b);
    la = f2bf(a - bf2f(ha));
    lb = f2bf(b - bf2f(hb));
    return (unsigned)ha | ((unsigned)hb << 16);
}

// ---------------- warp-MMA helpers ----------------
__device__ __forceinline__ uint32_t smem_to_u32(const void* smem_ptr) {
    uint32_t addr;
    asm("{ .reg .u64 tmp; cvta.to.shared.u64 tmp, %1; cvt.u32.u64 %0, tmp; }"
        : "=r"(addr) : "l"(smem_ptr));
    return addr;
}
__device__ __forceinline__ void ldsm4(uint32_t* r, uint32_t addr) {
    asm volatile("ldmatrix.sync.aligned.m8n8.x4.shared.b16 {%0,%1,%2,%3}, [%4];"
        : "=r"(r[0]), "=r"(r[1]), "=r"(r[2]), "=r"(r[3]) : "r"(addr));
}
__device__ __forceinline__ void ldsm4t(uint32_t* r, uint32_t addr) {
    asm volatile("ldmatrix.sync.aligned.m8n8.x4.trans.shared.b16 {%0,%1,%2,%3}, [%4];"
        : "=r"(r[0]), "=r"(r[1]), "=r"(r[2]), "=r"(r[3]) : "r"(addr));
}
__device__ __forceinline__ void mma16816(float* c, const uint32_t* a, const uint32_t* b) {
    asm volatile(
        "mma.sync.aligned.m16n8k16.row.col.f32.bf16.bf16.f32 "
        "{%0,%1,%2,%3}, {%4,%5,%6,%7}, {%8,%9}, {%0,%1,%2,%3};"
        : "+f"(c[0]), "+f"(c[1]), "+f"(c[2]), "+f"(c[3])
        : "r"(a[0]), "r"(a[1]), "r"(a[2]), "r"(a[3]), "r"(b[0]), "r"(b[1]));
}
#define CP_ASYNC16(dst, src) \
    asm volatile("cp.async.cg.shared.global [%0], [%1], 16;" :: "r"(dst), "l"(src))
#define CP_COMMIT() asm volatile("cp.async.commit_group;" ::: "memory")
#define CP_WAIT(n)  asm volatile("cp.async.wait_group %0;" :: "n"(n) : "memory")

__device__ __forceinline__ uint32_t sw64(uint32_t b)  { return b ^ ((b >> 3) & 0x30); }
__device__ __forceinline__ uint32_t sw256(uint32_t b) { return b ^ ((b >> 4) & 0x70); }

// small-K / scores config: K-chunk 32, tiles 128 rows x 64B, 3 stages, 2 CTAs/SM
#define H32_A    8192            // 128 rows x 64B (hi or lo)
#define H32_B    8192
#define H32_STG  32768
#define H32_SMEM (3 * H32_STG + 1024)

// ================= HMMA scores kernel (Kc=32, 3-stage, 2 CTAs/SM) =============
// scores[h] = mask .* (QR @ QR^T); 4 tiles/stage: Ah, Al, Bh, Bl (all k-contig).
__global__ void __launch_bounds__(256, 2)
scores_hmma(const unsigned short* __restrict__ qh,
            const unsigned short* __restrict__ ql,
            unsigned short* __restrict__ sch,
            unsigned short* __restrict__ scl)
{
    const int br = blockIdx.y;
    const int bc = blockIdx.x;
    const int h  = blockIdx.z;
    if (bc > br) return;

    extern __shared__ char dsm[];
    const int tid  = threadIdx.x;
    const int wid  = tid >> 5;
    const int lane = tid & 31;
    const int wr   = wid & 3;
    const int wc   = wid >> 2;
    const int row0 = br * 128;
    const int col0 = bc * 128;

    const uint32_t raw = smem_to_u32(dsm);
    const uint32_t sb  = (raw + 1023u) & ~1023u;

    const size_t hb = (size_t)h * TT * NN;
    const unsigned short* srcs[4];
    srcs[0] = qh + hb + (size_t)row0 * NN;
    srcs[1] = ql + hb + (size_t)row0 * NN;
    srcs[2] = qh + hb + (size_t)col0 * NN;
    srcs[3] = ql + hb + (size_t)col0 * NN;

    float acc[2][8][4];
#pragma unroll
    for (int mi = 0; mi < 2; mi++)
#pragma unroll
        for (int ni = 0; ni < 8; ni++)
#pragma unroll
            for (int q = 0; q < 4; q++) acc[mi][ni][q] = 0.f;

    const int NITER = NN / 32;  // 256

    auto load_stage = [&](int st, int kc0) {
        const uint32_t stg = sb + st * H32_STG;
#pragma unroll
        for (int t4 = 0; t4 < 4; t4++) {
            const unsigned short* src = srcs[t4] + kc0;
            const uint32_t tb = stg + t4 * H32_A;
#pragma unroll
            for (int i = 0; i < 2; i++) {
                int idx = i * 256 + tid;
                int r = idx >> 2;
                int c = idx & 3;
                CP_ASYNC16(tb + sw64(r * 64 + c * 16), src + (size_t)r * NN + c * 8);
            }
        }
    };

    load_stage(0, 0);
    CP_COMMIT();
    load_stage(1, 32);
    CP_COMMIT();

    for (int it = 0; it < NITER; it++) {
        if (it + 1 < NITER) { CP_WAIT(1); }
        else                { CP_WAIT(0); }
        __syncthreads();
        if (it + 2 < NITER) {
            load_stage((it + 2) % 3, (it + 2) * 32);
            CP_COMMIT();
        }

        const uint32_t stg = sb + (it % 3) * H32_STG;
#pragma unroll
        for (int ks = 0; ks < 2; ks++) {
            const int lrow  = lane & 15;
            const int chunk = ks * 2 + (lane >> 4);

            uint32_t ah[2][4], al[2][4];
#pragma unroll
            for (int mi = 0; mi < 2; mi++) {
                int row = wr * 32 + mi * 16 + lrow;
                uint32_t off = sw64(row * 64 + chunk * 16);
                ldsm4(ah[mi], stg + 0 * H32_A + off);
                ldsm4(al[mi], stg + 1 * H32_A + off);
            }

#pragma unroll
            for (int ng = 0; ng < 4; ng++) {
                int row = wc * 64 + ng * 16 + lrow;
                uint32_t off = sw64(row * 64 + chunk * 16);
                uint32_t t0[4], t1[4];
                ldsm4(t0, stg + 2 * H32_A + off);
                ldsm4(t1, stg + 3 * H32_A + off);
                uint32_t bh0[2], bh1[2], bl0[2], bl1[2];
                bh0[0] = t0[0]; bh0[1] = t0[2];
                bh1[0] = t0[1]; bh1[1] = t0[3];
                bl0[0] = t1[0]; bl0[1] = t1[2];
                bl1[0] = t1[1]; bl1[1] = t1[3];
#pragma unroll
                for (int mi = 0; mi < 2; mi++) {
                    mma16816(acc[mi][2 * ng],     ah[mi], bh0);
                    mma16816(acc[mi][2 * ng],     ah[mi], bl0);
                    mma16816(acc[mi][2 * ng],     al[mi], bh0);
                    mma16816(acc[mi][2 * ng + 1], ah[mi], bh1);
                    mma16816(acc[mi][2 * ng + 1], ah[mi], bl1);
                    mma16816(acc[mi][2 * ng + 1], al[mi], bh1);
                }
            }
        }
    }

    // epilogue: strictly-lower mask, write bf16 hi/lo split
    unsigned short* dh = sch + (size_t)h * TT * TT;
    unsigned short* dl = scl + (size_t)h * TT * TT;
    const int rb = row0 + wr * 32;
    const int cb = col0 + wc * 64;
#pragma unroll
    for (int mi = 0; mi < 2; mi++) {
#pragma unroll
        for (int ni = 0; ni < 8; ni++) {
            int r = rb + mi * 16 + (lane >> 2);
            int s = cb + ni * 8 + (lane & 3) * 2;
#pragma unroll
            for (int half = 0; half < 2; half++) {
                int rr = r + half * 8;
                float v0 = (rr > s)     ? acc[mi][ni][half * 2 + 0] : 0.f;
                float v1 = (rr > s + 1) ? acc[mi][ni][half * 2 + 1] : 0.f;
                unsigned short l0, l1;
                unsigned hv = pack_hl(v0, v1, l0, l1);
                size_t base = (size_t)rr * TT + s;
                *(unsigned*)(dh + base) = hv;
                *(unsigned*)(dl + base) = (unsigned)l0 | ((unsigned)l1 << 16);
            }
        }
    }
}

// ================= generic HMMA GEMM (K-chunk 32, 3-stage, 2 CTAs/SM) ==========
// A [M,K] k-contig (64B rows, SW64), B [K,N] n-contig (256B rows, SW256).
// acc = Ah*Bh + Ah*Bl + Al*Bh (fp32).
template <int HM, int CAUSAL>
__global__ void __launch_bounds__(256, 2)
hmma_gemm(const unsigned short* __restrict__ Ah, const unsigned short* __restrict__ Al,
          const unsigned short* __restrict__ Bh, const unsigned short* __restrict__ Bl,
          float* __restrict__ C, int K, int lda, int ldb, int ldc,
          long offAz, long offBz, long offCz)
{
    const int z = blockIdx.z;
    Ah += (long)z * offAz;
    Al += (long)z * offAz;
    Bh += (long)z * offBz;
    Bl += (long)z * offBz;
    if (HM != HM_MULXY) C += (long)z * offCz;

    extern __shared__ char dsm[];
    const int tid  = threadIdx.x;
    const int wid  = tid >> 5;
    const int lane = tid & 31;
    const int wr   = wid & 3;
    const int wc   = wid >> 2;
    const int row0 = blockIdx.y * 128;
    const int col0 = blockIdx.x * 128;

    const uint32_t raw = smem_to_u32(dsm);
    const uint32_t sb  = (raw + 1023u) & ~1023u;

    const unsigned short* A0 = Ah + (size_t)row0 * lda;
    const unsigned short* A1 = Al + (size_t)row0 * lda;

    float acc[2][8][4];
#pragma unroll
    for (int mi = 0; mi < 2; mi++)
#pragma unroll
        for (int ni = 0; ni < 8; ni++)
#pragma unroll
            for (int q = 0; q < 4; q++) acc[mi][ni][q] = 0.f;

    const int NITER = (CAUSAL ? (row0 + 128) : K) / 32;

    auto load_stage = [&](int st, int k0) {
        const uint32_t stg = sb + st * H32_STG;
#pragma unroll
        for (int i = 0; i < 2; i++) {
            int idx = i * 256 + tid;
            int r = idx >> 2;
            int c = idx & 3;
            uint32_t off = sw64(r * 64 + c * 16);
            CP_ASYNC16(stg + off,          A0 + (size_t)r * lda + k0 + c * 8);
            CP_ASYNC16(stg + H32_A + off,  A1 + (size_t)r * lda + k0 + c * 8);
        }
#pragma unroll
        for (int i = 0; i < 2; i++) {
            int idx = i * 256 + tid;
            int r = idx >> 4;
            int c = idx & 15;
            uint32_t off = sw256(r * 256 + c * 16);
            CP_ASYNC16(stg + 2 * H32_A + off,         Bh + (size_t)(k0 + r) * ldb + col0 + c * 8);
            CP_ASYNC16(stg + 2 * H32_A + H32_B + off, Bl + (size_t)(k0 + r) * ldb + col0 + c * 8);
        }
    };

    load_stage(0, 0);
    CP_COMMIT();
    if (NITER > 1) { load_stage(1, 32); CP_COMMIT(); }

    for (int it = 0; it < NITER; it++) {
        if (it + 1 < NITER) { CP_WAIT(1); }
        else                { CP_WAIT(0); }
        __syncthreads();
        if (it + 2 < NITER) {
            load_stage((it + 2) % 3, (it + 2) * 32);
            CP_COMMIT();
        }

        const uint32_t stg = sb + (it % 3) * H32_STG;
#pragma unroll
        for (int ks = 0; ks < 2; ks++) {
            const int lrow = lane & 15;

            uint32_t ah[2][4], al[2][4];
#pragma unroll
            for (int mi = 0; mi < 2; mi++) {
                int row = wr * 32 + mi * 16 + lrow;
                uint32_t off = sw64(row * 64 + (ks * 2 + (lane >> 4)) * 16);
                ldsm4(ah[mi], stg + off);
                ldsm4(al[mi], stg + H32_A + off);
            }

#pragma unroll
            for (int ng = 0; ng < 4; ng++) {
                int kk = ks * 16 + lrow;
                int nc = wc * 64 + ng * 16 + (lane >> 4) * 8;
                uint32_t off = sw256(kk * 256 + nc * 2);
                uint32_t t0[4], t1[4];
                ldsm4t(t0, stg + 2 * H32_A + off);
                ldsm4t(t1, stg + 2 * H32_A + H32_B + off);
                uint32_t bh0[2], bh1[2], bl0[2], bl1[2];
                bh0[0] = t0[0]; bh0[1] = t0[1];
                bh1[0] = t0[2]; bh1[1] = t0[3];
                bl0[0] = t1[0]; bl0[1] = t1[1];
                bl1[0] = t1[2]; bl1[1] = t1[3];
#pragma unroll
                for (int mi = 0; mi < 2; mi++) {
                    mma16816(acc[mi][2 * ng],     ah[mi], bh0);
                    mma16816(acc[mi][2 * ng],     ah[mi], bl0);
                    mma16816(acc[mi][2 * ng],     al[mi], bh0);
                    mma16816(acc[mi][2 * ng + 1], ah[mi], bh1);
                    mma16816(acc[mi][2 * ng + 1], ah[mi], bl1);
                    mma16816(acc[mi][2 * ng + 1], al[mi], bh1);
                }
            }
        }
    }

    // ---------------- epilogues ----------------
    const int rb = row0 + wr * 32;
    const int cb = col0 + wc * 64;

    if (HM == HM_NONE) {
#pragma unroll
        for (int mi = 0; mi < 2; mi++) {
#pragma unroll
            for (int ni = 0; ni < 8; ni++) {
                int r = rb + mi * 16 + (lane >> 2);
                int s = cb + ni * 8 + (lane & 3) * 2;
                *(float2*)(C + (size_t)r * ldc + s) =
                    make_float2(acc[mi][ni][0], acc[mi][ni][1]);
                *(float2*)(C + (size_t)(r + 8) * ldc + s) =
                    make_float2(acc[mi][ni][2], acc[mi][ni][3]);
            }
        }
    } else if (HM == HM_ROPE) {
        unsigned short* Qh = g_qrh + (size_t)z * TT * NN;
        unsigned short* Ql = g_qrl + (size_t)z * TT * NN;
#pragma unroll
        for (int ni = 0; ni < 8; ni++) {
            int n0 = cb + ni * 8 + (lane & 3) * 2;
            float fr = (float)exp2(-(double)n0 / 512.0) / TWO_PI_F;
#pragma unroll
            for (int mi = 0; mi < 2; mi++) {
                int rbase = rb + mi * 16 + (lane >> 2);
#pragma unroll
                for (int half = 0; half < 2; half++) {
                    int r = rbase + half * 8;
                    float v0 = fmaxf(acc[mi][ni][half * 2 + 0], 0.f);
                    float v1 = fmaxf(acc[mi][ni][half * 2 + 1], 0.f);
                    *(float2*)(C + (size_t)r * ldc + n0) = make_float2(v0, v1);
                    float ph   = (float)r * fr;
                    float frac = ph - floorf(ph);
                    float ang  = frac * TWO_PI_F;
                    float si, co;
                    sincosf(ang, &si, &co);
                    float q0 = v0 * co - v1 * si;
                    float q1 = v1 * co + v0 * si;
                    unsigned short l0, l1;
                    unsigned hv = pack_hl(q0, q1, l0, l1);
                    *(unsigned*)(Qh + (size_t)r * NN + n0) = hv;
                    *(unsigned*)(Ql + (size_t)r * NN + n0) = (unsigned)l0 | ((unsigned)l1 << 16);
                }
            }
        }
    } else if (HM == HM_MULXY) {
        const float* xsrc = g_xs + (size_t)z * TT * NN;
        unsigned short* Xh = g_xyh;
        unsigned short* Xl = g_xyl;
        const int colz = z * NN;
#pragma unroll
        for (int mi = 0; mi < 2; mi++) {
#pragma unroll
            for (int ni = 0; ni < 8; ni++) {
                int n0 = cb + ni * 8 + (lane & 3) * 2;
                int rbase = rb + mi * 16 + (lane >> 2);
#pragma unroll
                for (int half = 0; half < 2; half++) {
                    int r = rbase + half * 8;
                    float2 xv = *(const float2*)(xsrc + (size_t)r * NN + n0);
                    float v0 = fmaxf(acc[mi][ni][half * 2 + 0], 0.f) * xv.x;
                    float v1 = fmaxf(acc[mi][ni][half * 2 + 1], 0.f) * xv.y;
                    unsigned short l0, l1;
                    unsigned hv = pack_hl(v0, v1, l0, l1);
                    size_t base = (size_t)r * (NHH * NN) + colz + n0;
                    *(unsigned*)(Xh + base) = hv;
                    *(unsigned*)(Xl + base) = (unsigned)l0 | ((unsigned)l1 << 16);
                }
            }
        }
    }
}

// ---------------- weight split conversion ----------------
__global__ void cvt_split(const float* __restrict__ src,
                          unsigned short* __restrict__ h,
                          unsigned short* __restrict__ l, long n)
{
    long i = ((long)blockIdx.x * blockDim.x + threadIdx.x) * 4;
    if (i >= n) return;
    float4 v = *(const float4*)(src + i);
    unsigned short l0, l1, l2, l3;
    uint2 hv, lv;
    hv.x = pack_hl(v.x, v.y, l0, l1);
    hv.y = pack_hl(v.z, v.w, l2, l3);
    lv.x = (unsigned)l0 | ((unsigned)l1 << 16);
    lv.y = (unsigned)l2 | ((unsigned)l3 << 16);
    *(uint2*)(h + i) = hv;
    *(uint2*)(l + i) = lv;
}

// ---------------- block reduction over 256 threads ----------------
__device__ __forceinline__ float blk_sum(float v, float* sb) {
    int tid = threadIdx.x;
#pragma unroll
    for (int o = 16; o > 0; o >>= 1) v += __shfl_down_sync(0xffffffffu, v, o);
    if ((tid & 31) == 0) sb[tid >> 5] = v;
    __syncthreads();
    if (tid < 32) {
        float w = (tid < 8) ? sb[tid] : 0.f;
#pragma unroll
        for (int o = 4; o > 0; o >>= 1) w += __shfl_down_sync(0xffffffffu, w, o);
        if (tid == 0) sb[0] = w;
    }
    __syncthreads();
    float r = sb[0];
    __syncthreads();
    return r;
}

// ---------------- fp32 SGEMM (kept for lm_head) ----------------
template <int MODE>
__global__ void __launch_bounds__(256)
sgemm_kernel(const float* __restrict__ A, const float* __restrict__ B,
             float* __restrict__ C, int K,
             int lda, int ldb, int ldc,
             long offAz, long offBz, long offCz)
{
    const int z = blockIdx.z;
    A += (long)z * offAz;
    B += (long)z * offBz;
    C += (long)z * offCz;

    const int br = blockIdx.y, bc = blockIdx.x;
    const int row0 = br * 128, col0 = bc * 128;
    const int tid = threadIdx.x;
    const int tx = tid & 15, ty = tid >> 4;

    __shared__ __align__(16) float As[8][132];
    __shared__ __align__(16) float Bs[8][132];

    u64 acc2[8][4];
#pragma unroll
    for (int i = 0; i < 8; i++) {
#pragma unroll
        for (int j = 0; j < 4; j++) acc2[i][j] = 0ull;
    }

    const int ar = tid >> 1;
    const int ak = (tid & 1) * 4;
    const int bkr = tid >> 5;
    const int bcc = (tid & 31) * 4;

    const float* Ap = A + (long)(row0 + ar) * lda + ak;
    const float* Bp = B + (long)bkr * ldb + col0 + bcc;

    float4 a4 = *(const float4*)Ap;  Ap += 8;
    float4 b4 = *(const float4*)Bp;  Bp += (long)8 * ldb;

    for (int k0 = 0; k0 < K; k0 += 8) {
        As[ak + 0][ar] = a4.x; As[ak + 1][ar] = a4.y;
        As[ak + 2][ar] = a4.z; As[ak + 3][ar] = a4.w;
        Bs[bkr][bcc + 0] = b4.x; Bs[bkr][bcc + 1] = b4.y;
        Bs[bkr][bcc + 2] = b4.z; Bs[bkr][bcc + 3] = b4.w;
        __syncthreads();

        if (k0 + 8 < K) {
            a4 = *(const float4*)Ap;  Ap += 8;
            b4 = *(const float4*)Bp;  Bp += (long)8 * ldb;
        }

#pragma unroll
        for (int k = 0; k < 8; k++) {
            float a[8];
            *(float4*)&a[0] = *(const float4*)&As[k][ty * 8];
            *(float4*)&a[4] = *(const float4*)&As[k][ty * 8 + 4];
            ulonglong2 bu0 = *(const ulonglong2*)&Bs[k][tx * 8];
            ulonglong2 bu1 = *(const ulonglong2*)&Bs[k][tx * 8 + 4];
            u64 b2[4];
            b2[0] = bu0.x; b2[1] = bu0.y; b2[2] = bu1.x; b2[3] = bu1.y;
            u64 a2[8];
#pragma unroll
            for (int i = 0; i < 8; i++) a2[i] = dup2(a[i]);
#pragma unroll
            for (int i = 0; i < 8; i++) {
#pragma unroll
                for (int j = 0; j < 4; j++) ffma2(acc2[i][j], a2[i], b2[j]);
            }
        }
        __syncthreads();
    }

    float acc[8][8];
#pragma unroll
    for (int i = 0; i < 8; i++) {
#pragma unroll
        for (int j = 0; j < 4; j++) unpack2(acc2[i][j], acc[i][2 * j], acc[i][2 * j + 1]);
    }

#pragma unroll
    for (int i = 0; i < 8; i++) {
        long base = (long)(row0 + ty * 8 + i) * ldc + col0 + tx * 8;
        *(float4*)(C + base)     = make_float4(acc[i][0], acc[i][1], acc[i][2], acc[i][3]);
        *(float4*)(C + base + 4) = make_float4(acc[i][4], acc[i][5], acc[i][6], acc[i][7]);
    }
}

// ---------------- small elementwise kernels ----------------
__global__ void embed_ln_kernel(const int* __restrict__ idx,
                                const float* __restrict__ embed)
{
    __shared__ float sb[8];
    int t = blockIdx.x, d = threadIdx.x;
    float v   = embed[idx[t] * DD + d];
    float mu  = blk_sum(v, sb) * (1.f / DD);
    float dv  = v - mu;
    float var = blk_sum(dv * dv, sb) * (1.f / DD);
    float o = dv / sqrtf(var + LNEPS);
    g_x[t * DD + d] = o;
    unsigned short hh = f2bf(o);
    g_xh[t * DD + d] = hh;
    g_xl[t * DD + d] = f2bf(o - bf2f(hh));
}

__global__ void ln_rows_kernel(float* __restrict__ buf)
{
    __shared__ float sb[8];
    long r = blockIdx.x;
    int  d = threadIdx.x;
    float v   = buf[r * DD + d];
    float mu  = blk_sum(v, sb) * (1.f / DD);
    float dv  = v - mu;
    float var = blk_sum(dv * dv, sb) * (1.f / DD);
    float o = dv / sqrtf(var + LNEPS);
    buf[r * DD + d] = o;
    unsigned short hh = f2bf(o);
    g_ykvh[r * DD + d] = hh;
    g_ykvl[r * DD + d] = f2bf(o - bf2f(hh));
}

__global__ void mlp_finish_kernel()
{
    __shared__ float sb[8];
    int t = blockIdx.x, d = threadIdx.x;
    float s = 0.f;
#pragma unroll
    for (int kz = 0; kz < SPLITK; kz++)
        s += g_part[(size_t)kz * TT * DD + t * DD + d];

    float mu  = blk_sum(s, sb) * (1.f / DD);
    float dv  = s - mu;
    float var = blk_sum(dv * dv, sb) * (1.f / DD);
    float a   = dv / sqrtf(var + LNEPS);

    float b = g_x[t * DD + d] + a;
    mu  = blk_sum(b, sb) * (1.f / DD);
    dv  = b - mu;
    var = blk_sum(dv * dv, sb) * (1.f / DD);
    float o = dv / sqrtf(var + LNEPS);
    g_x[t * DD + d] = o;
    unsigned short hh = f2bf(o);
    g_xh[t * DD + d] = hh;
    g_xl[t * DD + d] = f2bf(o - bf2f(hh));
}

// ---------------- launch ----------------
extern "C" void kernel_launch(void* const* d_in, const int* in_sizes, int n_in,
                              void* d_out, int out_size)
{
    (void)in_sizes; (void)n_in; (void)out_size;
    const int*   idx       = (const int*)d_in[0];
    const float* embed     = (const float*)d_in[1];
    const float* encoder   = (const float*)d_in[2];
    const float* encoder_v = (const float*)d_in[3];
    const float* decoder   = (const float*)d_in[4];
    const float* lm_head   = (const float*)d_in[5];
    float*       out       = (float*)d_out;

    float* x = 0; float* xs = 0; float* ykv = 0; float* part = 0;
    unsigned short *sch = 0, *scl = 0;
    unsigned short *qrh = 0, *qrl = 0, *xyh = 0, *xyl = 0;
    unsigned short *xh = 0, *xl = 0, *ykvh = 0, *ykvl = 0;
    unsigned short *ench = 0, *encl = 0, *encvh = 0, *encvl = 0, *dech = 0, *decl = 0;
    cudaGetSymbolAddress((void**)&x,      g_x);
    cudaGetSymbolAddress((void**)&xs,     g_xs);
    cudaGetSymbolAddress((void**)&sch,    g_sch);
    cudaGetSymbolAddress((void**)&scl,    g_scl);
    cudaGetSymbolAddress((void**)&ykv,    g_ykv);
    cudaGetSymbolAddress((void**)&part,   g_part);
    cudaGetSymbolAddress((void**)&qrh,    g_qrh);
    cudaGetSymbolAddress((void**)&qrl,    g_qrl);
    cudaGetSymbolAddress((void**)&xyh,    g_xyh);
    cudaGetSymbolAddress((void**)&xyl,    g_xyl);
    cudaGetSymbolAddress((void**)&xh,     g_xh);
    cudaGetSymbolAddress((void**)&xl,     g_xl);
    cudaGetSymbolAddress((void**)&ykvh,   g_ykvh);
    cudaGetSymbolAddress((void**)&ykvl,   g_ykvl);
    cudaGetSymbolAddress((void**)&ench,   g_ench);
    cudaGetSymbolAddress((void**)&encl,   g_encl);
    cudaGetSymbolAddress((void**)&encvh,  g_encvh);
    cudaGetSymbolAddress((void**)&encvl,  g_encvl);
    cudaGetSymbolAddress((void**)&dech,   g_dech);
    cudaGetSymbolAddress((void**)&decl,   g_decl);

    cudaFuncSetAttribute(scores_hmma, cudaFuncAttributeMaxDynamicSharedMemorySize, H32_SMEM);
    cudaFuncSetAttribute(hmma_gemm<HM_NONE, 0>,  cudaFuncAttributeMaxDynamicSharedMemorySize, H32_SMEM);
    cudaFuncSetAttribute(hmma_gemm<HM_NONE, 1>,  cudaFuncAttributeMaxDynamicSharedMemorySize, H32_SMEM);
    cudaFuncSetAttribute(hmma_gemm<HM_ROPE, 0>,  cudaFuncAttributeMaxDynamicSharedMemorySize, H32_SMEM);
    cudaFuncSetAttribute(hmma_gemm<HM_MULXY, 0>, cudaFuncAttributeMaxDynamicSharedMemorySize, H32_SMEM);

    const long WN = (long)NHH * DD * NN;
    cvt_split<<<(int)(WN / 4 / 256), 256>>>(encoder,   ench,  encl,  WN);
    cvt_split<<<(int)(WN / 4 / 256), 256>>>(encoder_v, encvh, encvl, WN);
    cvt_split<<<(int)(WN / 4 / 256), 256>>>(decoder,   dech,  decl,  WN);

    embed_ln_kernel<<<TT, 256>>>(idx, embed);

    for (int l = 0; l < 2; l++) {
        // x_sparse = relu(x @ encoder) fp32 -> g_xs; QR hi/lo -> g_qrh/l
        hmma_gemm<HM_ROPE, 0><<<dim3(NN / 128, TT / 128, NHH), 256, H32_SMEM>>>(
            xh, xl, ench, encl, xs, DD, DD, NN, NN,
            0L, (long)DD * NN, (long)TT * NN);

        // scores = mask .* (QR @ QR^T) -> bf16 hi/lo
        scores_hmma<<<dim3(TT / 128, TT / 128, NHH), 256, H32_SMEM>>>(qrh, qrl, sch, scl);

        // yKV = scores @ x — causal-bounded HMMA
        hmma_gemm<HM_NONE, 1><<<dim3(DD / 128, TT / 128, NHH), 256, H32_SMEM>>>(
            sch, scl, xh, xl, ykv, TT, TT, DD, DD,
            (long)TT * TT, 0L, (long)TT * DD);

        ln_rows_kernel<<<NHH * TT, 256>>>(ykv);

        // xy = relu(yKV @ encoder_v) * x_sparse -> bf16 hi/lo
        hmma_gemm<HM_MULXY, 0><<<dim3(NN / 128, TT / 128, NHH), 256, H32_SMEM>>>(
            ykvh, ykvl, encvh, encvl, xs, DD, DD, NN, 0,
            (long)TT * DD, (long)DD * NN, 0L);

        // yMLP partials = xy @ decoder (split-K 16)
        hmma_gemm<HM_NONE, 0><<<dim3(DD / 128, TT / 128, SPLITK), 256, H32_SMEM>>>(
            xyh, xyl, dech, decl, part, KSPL, NHH * NN, DD, DD,
            (long)KSPL, (long)KSPL * DD, (long)TT * DD);

        mlp_finish_kernel<<<TT, 256>>>();
    }

    sgemm_kernel<EM_NONE><<<dim3(VOC / 128, TT / 128, 1), 256>>>(
        x, lm_head, out, DD, DD, VOC, VOC, 0L, 0L, 0L);
}

// round 11
// speedup vs baseline: 1.2457x; 1.2457x over previous
#include <cuda_runtime.h>
#include <math.h>
#include <stdint.h>

// ---------------- problem constants ----------------
#define NHH   4
#define DD    256
#define NN    8192
#define TT    2048
#define VOC   256
#define SPLITK 16
#define KSPL  2048              // NHH*NN/SPLITK
#define LNEPS 1e-5f
#define TWO_PI_F 6.28318530717958647692f

// ---------------- scratch (static device globals) ----
__device__ float g_x[TT * DD];
__device__ unsigned short g_xh[TT * DD];
__device__ unsigned short g_xl[TT * DD];
__device__ float g_xs[(size_t)NHH * TT * NN];
__device__ unsigned short g_sch[(size_t)NHH * TT * TT];   // scores hi (bf16)
__device__ unsigned short g_scl[(size_t)NHH * TT * TT];   // scores lo (bf16)
__device__ float g_ykv[(size_t)NHH * TT * DD];
__device__ unsigned short g_ykvh[(size_t)NHH * TT * DD];
__device__ unsigned short g_ykvl[(size_t)NHH * TT * DD];
__device__ float g_part[(size_t)SPLITK * TT * DD];
__device__ unsigned short g_qrh[(size_t)NHH * TT * NN];   // QR hi (fp16 bits)
__device__ unsigned short g_qrl[(size_t)NHH * TT * NN];   // QR lo (fp16 bits)
__device__ unsigned short g_xyh[(size_t)NHH * TT * NN];
__device__ unsigned short g_xyl[(size_t)NHH * TT * NN];
__device__ unsigned short g_ench[(size_t)NHH * DD * NN];
__device__ unsigned short g_encl[(size_t)NHH * DD * NN];
__device__ unsigned short g_encvh[(size_t)NHH * DD * NN];
__device__ unsigned short g_encvl[(size_t)NHH * DD * NN];
__device__ unsigned short g_dech[(size_t)NHH * NN * DD];
__device__ unsigned short g_decl[(size_t)NHH * NN * DD];

enum { EM_NONE = 0 };
enum { HM_NONE = 0, HM_ROPE = 1, HM_MULXY = 2 };

typedef unsigned long long u64;

// ---------------- packed f32x2 helpers ----------------
__device__ __forceinline__ void ffma2(u64& d, u64 a, u64 b) {
    asm("fma.rn.f32x2 %0, %1, %2, %0;" : "+l"(d) : "l"(a), "l"(b));
}
__device__ __forceinline__ u64 dup2(float x) {
    u64 r;
    asm("mov.b64 %0, {%1, %1};" : "=l"(r) : "r"(__float_as_uint(x)));
    return r;
}
__device__ __forceinline__ void unpack2(u64 v, float& lo, float& hi) {
    unsigned a, b;
    asm("mov.b64 {%0, %1}, %2;" : "=r"(a), "=r"(b) : "l"(v));
    lo = __uint_as_float(a); hi = __uint_as_float(b);
}

// ---------------- bf16 bit helpers ----------------
__device__ __forceinline__ unsigned short f2bf(float x) {
    unsigned u = __float_as_uint(x);
    unsigned r = (u + 0x7FFFu + ((u >> 16) & 1u)) >> 16;
    return (unsigned short)r;
}
__device__ __forceinline__ float bf2f(unsigned short b) {
    return __uint_as_float((unsigned)b << 16);
}
__device__ __forceinline__ unsigned pack_hl(float a, float b,
                                            unsigned short& la, unsigned short& lb) {
    unsigned short ha = f2bf(a), hb = f2bf(b);
    la = f2bf(a - bf2f(ha));
    lb = f2bf(b - bf2f(hb));
    return (unsigned)ha | ((unsigned)hb << 16);
}

// ---------------- fp16 bit helpers ----------------
__device__ __forceinline__ unsigned short f2h(float x) {
    unsigned short r;
    asm("cvt.rn.f16.f32 %0, %1;" : "=h"(r) : "f"(x));
    return r;
}
__device__ __forceinline__ float h2f(unsigned short h) {
    float r;
    asm("cvt.f32.f16 %0, %1;" : "=f"(r) : "h"(h));
    return r;
}
__device__ __forceinline__ unsigned pack_hl_h(float a, float b,
                                              unsigned short& la, unsigned short& lb) {
    unsigned short ha = f2h(a), hb = f2h(b);
    la = f2h(a - h2f(ha));
    lb = f2h(b - h2f(hb));
    return (unsigned)ha | ((unsigned)hb << 16);
}

// ---------------- warp-MMA helpers ----------------
__device__ __forceinline__ uint32_t smem_to_u32(const void* smem_ptr) {
    uint32_t addr;
    asm("{ .reg .u64 tmp; cvta.to.shared.u64 tmp, %1; cvt.u32.u64 %0, tmp; }"
        : "=r"(addr) : "l"(smem_ptr));
    return addr;
}
__device__ __forceinline__ void ldsm4(uint32_t* r, uint32_t addr) {
    asm volatile("ldmatrix.sync.aligned.m8n8.x4.shared.b16 {%0,%1,%2,%3}, [%4];"
        : "=r"(r[0]), "=r"(r[1]), "=r"(r[2]), "=r"(r[3]) : "r"(addr));
}
__device__ __forceinline__ void ldsm4t(uint32_t* r, uint32_t addr) {
    asm volatile("ldmatrix.sync.aligned.m8n8.x4.trans.shared.b16 {%0,%1,%2,%3}, [%4];"
        : "=r"(r[0]), "=r"(r[1]), "=r"(r[2]), "=r"(r[3]) : "r"(addr));
}
__device__ __forceinline__ void mma16816(float* c, const uint32_t* a, const uint32_t* b) {
    asm volatile(
        "mma.sync.aligned.m16n8k16.row.col.f32.bf16.bf16.f32 "
        "{%0,%1,%2,%3}, {%4,%5,%6,%7}, {%8,%9}, {%0,%1,%2,%3};"
        : "+f"(c[0]), "+f"(c[1]), "+f"(c[2]), "+f"(c[3])
        : "r"(a[0]), "r"(a[1]), "r"(a[2]), "r"(a[3]), "r"(b[0]), "r"(b[1]));
}
__device__ __forceinline__ void mma16816h(float* c, const uint32_t* a, const uint32_t* b) {
    asm volatile(
        "mma.sync.aligned.m16n8k16.row.col.f32.f16.f16.f32 "
        "{%0,%1,%2,%3}, {%4,%5,%6,%7}, {%8,%9}, {%0,%1,%2,%3};"
        : "+f"(c[0]), "+f"(c[1]), "+f"(c[2]), "+f"(c[3])
        : "r"(a[0]), "r"(a[1]), "r"(a[2]), "r"(a[3]), "r"(b[0]), "r"(b[1]));
}
#define CP_ASYNC16(dst, src) \
    asm volatile("cp.async.cg.shared.global [%0], [%1], 16;" :: "r"(dst), "l"(src))
#define CP_COMMIT() asm volatile("cp.async.commit_group;" ::: "memory")
#define CP_WAIT(n)  asm volatile("cp.async.wait_group %0;" :: "n"(n) : "memory")

__device__ __forceinline__ uint32_t sw64(uint32_t b)  { return b ^ ((b >> 3) & 0x30); }
__device__ __forceinline__ uint32_t sw128(uint32_t b) { return b ^ ((b >> 3) & 0x70); }
__device__ __forceinline__ uint32_t sw256(uint32_t b) { return b ^ ((b >> 4) & 0x70); }

// generic small-K config: K-chunk 32, 3 stages of 32KB, 2 CTAs/SM
#define H32_A    8192            // 128 rows x 64B (hi or lo)
#define H32_B    8192
#define H32_STG  32768
#define H32_SMEM (3 * H32_STG + 1024)

// scores config: fp16 2-pass, Kc=64, 3 tiles/stage (Ah, Al, Bh), 2 stages, 2 CTAs/SM
#define SC_T     16384           // 128 rows x 128B
#define SC_STG   (3 * SC_T)      // 48KB
#define SC_SMEM  (2 * SC_STG + 1024)

// ================= HMMA scores kernel =================
// scores[h] = mask .* (QR @ QR^T); QR = hi + lo (fp16 splits)
// acc = (hi_a + lo_a) * hi_b  (2 MMA passes; drops a*lo_b ~ 2^-11)
__global__ void __launch_bounds__(256, 2)
scores_hmma(const unsigned short* __restrict__ qh,
            const unsigned short* __restrict__ ql,
            unsigned short* __restrict__ sch,
            unsigned short* __restrict__ scl)
{
    const int br = blockIdx.y;
    const int bc = blockIdx.x;
    const int h  = blockIdx.z;
    if (bc > br) return;

    extern __shared__ char dsm[];
    const int tid  = threadIdx.x;
    const int wid  = tid >> 5;
    const int lane = tid & 31;
    const int wr   = wid & 3;
    const int wc   = wid >> 2;
    const int row0 = br * 128;
    const int col0 = bc * 128;

    const uint32_t raw = smem_to_u32(dsm);
    const uint32_t sb  = (raw + 1023u) & ~1023u;

    const size_t hb = (size_t)h * TT * NN;
    const unsigned short* srcs[3];
    srcs[0] = qh + hb + (size_t)row0 * NN;   // A hi
    srcs[1] = ql + hb + (size_t)row0 * NN;   // A lo
    srcs[2] = qh + hb + (size_t)col0 * NN;   // B hi

    float acc[2][8][4];
#pragma unroll
    for (int mi = 0; mi < 2; mi++)
#pragma unroll
        for (int ni = 0; ni < 8; ni++)
#pragma unroll
            for (int q = 0; q < 4; q++) acc[mi][ni][q] = 0.f;

    const int NITER = NN / 64;  // 128

    auto load_stage = [&](int st, int kc0) {
        const uint32_t stg = sb + st * SC_STG;
#pragma unroll
        for (int t3 = 0; t3 < 3; t3++) {
            const unsigned short* src = srcs[t3] + kc0;
            const uint32_t tb = stg + t3 * SC_T;
#pragma unroll
            for (int i = 0; i < 4; i++) {
                int idx = i * 256 + tid;
                int r = idx >> 3;
                int c = idx & 7;
                CP_ASYNC16(tb + sw128(r * 128 + c * 16), src + (size_t)r * NN + c * 8);
            }
        }
    };

    load_stage(0, 0);
    CP_COMMIT();

    for (int it = 0; it < NITER; it++) {
        CP_WAIT(0);
        __syncthreads();
        if (it + 1 < NITER) {
            load_stage((it + 1) & 1, (it + 1) * 64);
            CP_COMMIT();
        }

        const uint32_t stg = sb + (it & 1) * SC_STG;
#pragma unroll
        for (int ks = 0; ks < 4; ks++) {
            const int lrow  = lane & 15;
            const int chunk = ks * 2 + (lane >> 4);

            uint32_t ah[2][4], al[2][4];
#pragma unroll
            for (int mi = 0; mi < 2; mi++) {
                int row = wr * 32 + mi * 16 + lrow;
                uint32_t off = sw128(row * 128 + chunk * 16);
                ldsm4(ah[mi], stg + 0 * SC_T + off);
                ldsm4(al[mi], stg + 1 * SC_T + off);
            }

#pragma unroll
            for (int ng = 0; ng < 4; ng++) {
                int row = wc * 64 + ng * 16 + lrow;
                uint32_t off = sw128(row * 128 + chunk * 16);
                uint32_t t0[4];
                ldsm4(t0, stg + 2 * SC_T + off);
                uint32_t bh0[2], bh1[2];
                bh0[0] = t0[0]; bh0[1] = t0[2];
                bh1[0] = t0[1]; bh1[1] = t0[3];
#pragma unroll
                for (int mi = 0; mi < 2; mi++) {
                    mma16816h(acc[mi][2 * ng],     ah[mi], bh0);
                    mma16816h(acc[mi][2 * ng],     al[mi], bh0);
                    mma16816h(acc[mi][2 * ng + 1], ah[mi], bh1);
                    mma16816h(acc[mi][2 * ng + 1], al[mi], bh1);
                }
            }
        }
    }

    // epilogue: strictly-lower mask, write scores as bf16 hi/lo split
    unsigned short* dh = sch + (size_t)h * TT * TT;
    unsigned short* dl = scl + (size_t)h * TT * TT;
    const int rb = row0 + wr * 32;
    const int cb = col0 + wc * 64;
#pragma unroll
    for (int mi = 0; mi < 2; mi++) {
#pragma unroll
        for (int ni = 0; ni < 8; ni++) {
            int r = rb + mi * 16 + (lane >> 2);
            int s = cb + ni * 8 + (lane & 3) * 2;
#pragma unroll
            for (int half = 0; half < 2; half++) {
                int rr = r + half * 8;
                float v0 = (rr > s)     ? acc[mi][ni][half * 2 + 0] : 0.f;
                float v1 = (rr > s + 1) ? acc[mi][ni][half * 2 + 1] : 0.f;
                unsigned short l0, l1;
                unsigned hv = pack_hl(v0, v1, l0, l1);
                size_t base = (size_t)rr * TT + s;
                *(unsigned*)(dh + base) = hv;
                *(unsigned*)(dl + base) = (unsigned)l0 | ((unsigned)l1 << 16);
            }
        }
    }
}

// ================= generic HMMA GEMM (K-chunk 32, 3-stage, 2 CTAs/SM) ==========
// A [M,K] k-contig (64B rows, SW64), B [K,N] n-contig (256B rows, SW256).
// acc = Ah*Bh + Ah*Bl + Al*Bh (bf16, fp32 accum).
template <int HM, int CAUSAL>
__global__ void __launch_bounds__(256, 2)
hmma_gemm(const unsigned short* __restrict__ Ah, const unsigned short* __restrict__ Al,
          const unsigned short* __restrict__ Bh, const unsigned short* __restrict__ Bl,
          float* __restrict__ C, int K, int lda, int ldb, int ldc,
          long offAz, long offBz, long offCz)
{
    const int z = blockIdx.z;
    Ah += (long)z * offAz;
    Al += (long)z * offAz;
    Bh += (long)z * offBz;
    Bl += (long)z * offBz;
    if (HM != HM_MULXY) C += (long)z * offCz;

    extern __shared__ char dsm[];
    const int tid  = threadIdx.x;
    const int wid  = tid >> 5;
    const int lane = tid & 31;
    const int wr   = wid & 3;
    const int wc   = wid >> 2;
    const int row0 = blockIdx.y * 128;
    const int col0 = blockIdx.x * 128;

    const uint32_t raw = smem_to_u32(dsm);
    const uint32_t sb  = (raw + 1023u) & ~1023u;

    const unsigned short* A0 = Ah + (size_t)row0 * lda;
    const unsigned short* A1 = Al + (size_t)row0 * lda;

    float acc[2][8][4];
#pragma unroll
    for (int mi = 0; mi < 2; mi++)
#pragma unroll
        for (int ni = 0; ni < 8; ni++)
#pragma unroll
            for (int q = 0; q < 4; q++) acc[mi][ni][q] = 0.f;

    const int NITER = (CAUSAL ? (row0 + 128) : K) / 32;

    auto load_stage = [&](int st, int k0) {
        const uint32_t stg = sb + st * H32_STG;
#pragma unroll
        for (int i = 0; i < 2; i++) {
            int idx = i * 256 + tid;
            int r = idx >> 2;
            int c = idx & 3;
            uint32_t off = sw64(r * 64 + c * 16);
            CP_ASYNC16(stg + off,          A0 + (size_t)r * lda + k0 + c * 8);
            CP_ASYNC16(stg + H32_A + off,  A1 + (size_t)r * lda + k0 + c * 8);
        }
#pragma unroll
        for (int i = 0; i < 2; i++) {
            int idx = i * 256 + tid;
            int r = idx >> 4;
            int c = idx & 15;
            uint32_t off = sw256(r * 256 + c * 16);
            CP_ASYNC16(stg + 2 * H32_A + off,         Bh + (size_t)(k0 + r) * ldb + col0 + c * 8);
            CP_ASYNC16(stg + 2 * H32_A + H32_B + off, Bl + (size_t)(k0 + r) * ldb + col0 + c * 8);
        }
    };

    load_stage(0, 0);
    CP_COMMIT();
    if (NITER > 1) { load_stage(1, 32); CP_COMMIT(); }

    for (int it = 0; it < NITER; it++) {
        if (it + 1 < NITER) { CP_WAIT(1); }
        else                { CP_WAIT(0); }
        __syncthreads();
        if (it + 2 < NITER) {
            load_stage((it + 2) % 3, (it + 2) * 32);
            CP_COMMIT();
        }

        const uint32_t stg = sb + (it % 3) * H32_STG;
#pragma unroll
        for (int ks = 0; ks < 2; ks++) {
            const int lrow = lane & 15;

            uint32_t ah[2][4], al[2][4];
#pragma unroll
            for (int mi = 0; mi < 2; mi++) {
                int row = wr * 32 + mi * 16 + lrow;
                uint32_t off = sw64(row * 64 + (ks * 2 + (lane >> 4)) * 16);
                ldsm4(ah[mi], stg + off);
                ldsm4(al[mi], stg + H32_A + off);
            }

#pragma unroll
            for (int ng = 0; ng < 4; ng++) {
                int kk = ks * 16 + lrow;
                int nc = wc * 64 + ng * 16 + (lane >> 4) * 8;
                uint32_t off = sw256(kk * 256 + nc * 2);
                uint32_t t0[4], t1[4];
                ldsm4t(t0, stg + 2 * H32_A + off);
                ldsm4t(t1, stg + 2 * H32_A + H32_B + off);
                uint32_t bh0[2], bh1[2], bl0[2], bl1[2];
                bh0[0] = t0[0]; bh0[1] = t0[1];
                bh1[0] = t0[2]; bh1[1] = t0[3];
                bl0[0] = t1[0]; bl0[1] = t1[1];
                bl1[0] = t1[2]; bl1[1] = t1[3];
#pragma unroll
                for (int mi = 0; mi < 2; mi++) {
                    mma16816(acc[mi][2 * ng],     ah[mi], bh0);
                    mma16816(acc[mi][2 * ng],     ah[mi], bl0);
                    mma16816(acc[mi][2 * ng],     al[mi], bh0);
                    mma16816(acc[mi][2 * ng + 1], ah[mi], bh1);
                    mma16816(acc[mi][2 * ng + 1], ah[mi], bl1);
                    mma16816(acc[mi][2 * ng + 1], al[mi], bh1);
                }
            }
        }
    }

    // ---------------- epilogues ----------------
    const int rb = row0 + wr * 32;
    const int cb = col0 + wc * 64;

    if (HM == HM_NONE) {
#pragma unroll
        for (int mi = 0; mi < 2; mi++) {
#pragma unroll
            for (int ni = 0; ni < 8; ni++) {
                int r = rb + mi * 16 + (lane >> 2);
                int s = cb + ni * 8 + (lane & 3) * 2;
                *(float2*)(C + (size_t)r * ldc + s) =
                    make_float2(acc[mi][ni][0], acc[mi][ni][1]);
                *(float2*)(C + (size_t)(r + 8) * ldc + s) =
                    make_float2(acc[mi][ni][2], acc[mi][ni][3]);
            }
        }
    } else if (HM == HM_ROPE) {
        unsigned short* Qh = g_qrh + (size_t)z * TT * NN;
        unsigned short* Ql = g_qrl + (size_t)z * TT * NN;
#pragma unroll
        for (int ni = 0; ni < 8; ni++) {
            int n0 = cb + ni * 8 + (lane & 3) * 2;
            float fr = (float)exp2(-(double)n0 / 512.0) / TWO_PI_F;
#pragma unroll
            for (int mi = 0; mi < 2; mi++) {
                int rbase = rb + mi * 16 + (lane >> 2);
#pragma unroll
                for (int half = 0; half < 2; half++) {
                    int r = rbase + half * 8;
                    float v0 = fmaxf(acc[mi][ni][half * 2 + 0], 0.f);
                    float v1 = fmaxf(acc[mi][ni][half * 2 + 1], 0.f);
                    *(float2*)(C + (size_t)r * ldc + n0) = make_float2(v0, v1);
                    float ph   = (float)r * fr;
                    float frac = ph - floorf(ph);
                    float ang  = frac * TWO_PI_F;
                    float si, co;
                    sincosf(ang, &si, &co);
                    float q0 = v0 * co - v1 * si;
                    float q1 = v1 * co + v0 * si;
                    unsigned short l0, l1;
                    unsigned hv = pack_hl_h(q0, q1, l0, l1);   // fp16 split for scores
                    *(unsigned*)(Qh + (size_t)r * NN + n0) = hv;
                    *(unsigned*)(Ql + (size_t)r * NN + n0) = (unsigned)l0 | ((unsigned)l1 << 16);
                }
            }
        }
    } else if (HM == HM_MULXY) {
        const float* xsrc = g_xs + (size_t)z * TT * NN;
        unsigned short* Xh = g_xyh;
        unsigned short* Xl = g_xyl;
        const int colz = z * NN;
#pragma unroll
        for (int mi = 0; mi < 2; mi++) {
#pragma unroll
            for (int ni = 0; ni < 8; ni++) {
                int n0 = cb + ni * 8 + (lane & 3) * 2;
                int rbase = rb + mi * 16 + (lane >> 2);
#pragma unroll
                for (int half = 0; half < 2; half++) {
                    int r = rbase + half * 8;
                    float2 xv = *(const float2*)(xsrc + (size_t)r * NN + n0);
                    float v0 = fmaxf(acc[mi][ni][half * 2 + 0], 0.f) * xv.x;
                    float v1 = fmaxf(acc[mi][ni][half * 2 + 1], 0.f) * xv.y;
                    unsigned short l0, l1;
                    unsigned hv = pack_hl(v0, v1, l0, l1);
                    size_t base = (size_t)r * (NHH * NN) + colz + n0;
                    *(unsigned*)(Xh + base) = hv;
                    *(unsigned*)(Xl + base) = (unsigned)l0 | ((unsigned)l1 << 16);
                }
            }
        }
    }
}

// ---------------- weight split conversion ----------------
__global__ void cvt_split(const float* __restrict__ src,
                          unsigned short* __restrict__ h,
                          unsigned short* __restrict__ l, long n)
{
    long i = ((long)blockIdx.x * blockDim.x + threadIdx.x) * 4;
    if (i >= n) return;
    float4 v = *(const float4*)(src + i);
    unsigned short l0, l1, l2, l3;
    uint2 hv, lv;
    hv.x = pack_hl(v.x, v.y, l0, l1);
    hv.y = pack_hl(v.z, v.w, l2, l3);
    lv.x = (unsigned)l0 | ((unsigned)l1 << 16);
    lv.y = (unsigned)l2 | ((unsigned)l3 << 16);
    *(uint2*)(h + i) = hv;
    *(uint2*)(l + i) = lv;
}

// ---------------- block reduction over 256 threads ----------------
__device__ __forceinline__ float blk_sum(float v, float* sb) {
    int tid = threadIdx.x;
#pragma unroll
    for (int o = 16; o > 0; o >>= 1) v += __shfl_down_sync(0xffffffffu, v, o);
    if ((tid & 31) == 0) sb[tid >> 5] = v;
    __syncthreads();
    if (tid < 32) {
        float w = (tid < 8) ? sb[tid] : 0.f;
#pragma unroll
        for (int o = 4; o > 0; o >>= 1) w += __shfl_down_sync(0xffffffffu, w, o);
        if (tid == 0) sb[0] = w;
    }
    __syncthreads();
    float r = sb[0];
    __syncthreads();
    return r;
}

// ---------------- fp32 SGEMM (kept for lm_head) ----------------
template <int MODE>
__global__ void __launch_bounds__(256)
sgemm_kernel(const float* __restrict__ A, const float* __restrict__ B,
             float* __restrict__ C, int K,
             int lda, int ldb, int ldc,
             long offAz, long offBz, long offCz)
{
    const int z = blockIdx.z;
    A += (long)z * offAz;
    B += (long)z * offBz;
    C += (long)z * offCz;

    const int br = blockIdx.y, bc = blockIdx.x;
    const int row0 = br * 128, col0 = bc * 128;
    const int tid = threadIdx.x;
    const int tx = tid & 15, ty = tid >> 4;

    __shared__ __align__(16) float As[8][132];
    __shared__ __align__(16) float Bs[8][132];

    u64 acc2[8][4];
#pragma unroll
    for (int i = 0; i < 8; i++) {
#pragma unroll
        for (int j = 0; j < 4; j++) acc2[i][j] = 0ull;
    }

    const int ar = tid >> 1;
    const int ak = (tid & 1) * 4;
    const int bkr = tid >> 5;
    const int bcc = (tid & 31) * 4;

    const float* Ap = A + (long)(row0 + ar) * lda + ak;
    const float* Bp = B + (long)bkr * ldb + col0 + bcc;

    float4 a4 = *(const float4*)Ap;  Ap += 8;
    float4 b4 = *(const float4*)Bp;  Bp += (long)8 * ldb;

    for (int k0 = 0; k0 < K; k0 += 8) {
        As[ak + 0][ar] = a4.x; As[ak + 1][ar] = a4.y;
        As[ak + 2][ar] = a4.z; As[ak + 3][ar] = a4.w;
        Bs[bkr][bcc + 0] = b4.x; Bs[bkr][bcc + 1] = b4.y;
        Bs[bkr][bcc + 2] = b4.z; Bs[bkr][bcc + 3] = b4.w;
        __syncthreads();

        if (k0 + 8 < K) {
            a4 = *(const float4*)Ap;  Ap += 8;
            b4 = *(const float4*)Bp;  Bp += (long)8 * ldb;
        }

#pragma unroll
        for (int k = 0; k < 8; k++) {
            float a[8];
            *(float4*)&a[0] = *(const float4*)&As[k][ty * 8];
            *(float4*)&a[4] = *(const float4*)&As[k][ty * 8 + 4];
            ulonglong2 bu0 = *(const ulonglong2*)&Bs[k][tx * 8];
            ulonglong2 bu1 = *(const ulonglong2*)&Bs[k][tx * 8 + 4];
            u64 b2[4];
            b2[0] = bu0.x; b2[1] = bu0.y; b2[2] = bu1.x; b2[3] = bu1.y;
            u64 a2[8];
#pragma unroll
            for (int i = 0; i < 8; i++) a2[i] = dup2(a[i]);
#pragma unroll
            for (int i = 0; i < 8; i++) {
#pragma unroll
                for (int j = 0; j < 4; j++) ffma2(acc2[i][j], a2[i], b2[j]);
            }
        }
        __syncthreads();
    }

    float acc[8][8];
#pragma unroll
    for (int i = 0; i < 8; i++) {
#pragma unroll
        for (int j = 0; j < 4; j++) unpack2(acc2[i][j], acc[i][2 * j], acc[i][2 * j + 1]);
    }

#pragma unroll
    for (int i = 0; i < 8; i++) {
        long base = (long)(row0 + ty * 8 + i) * ldc + col0 + tx * 8;
        *(float4*)(C + base)     = make_float4(acc[i][0], acc[i][1], acc[i][2], acc[i][3]);
        *(float4*)(C + base + 4) = make_float4(acc[i][4], acc[i][5], acc[i][6], acc[i][7]);
    }
}

// ---------------- small elementwise kernels ----------------
__global__ void embed_ln_kernel(const int* __restrict__ idx,
                                const float* __restrict__ embed)
{
    __shared__ float sb[8];
    int t = blockIdx.x, d = threadIdx.x;
    float v   = embed[idx[t] * DD + d];
    float mu  = blk_sum(v, sb) * (1.f / DD);
    float dv  = v - mu;
    float var = blk_sum(dv * dv, sb) * (1.f / DD);
    float o = dv / sqrtf(var + LNEPS);
    g_x[t * DD + d] = o;
    unsigned short hh = f2bf(o);
    g_xh[t * DD + d] = hh;
    g_xl[t * DD + d] = f2bf(o - bf2f(hh));
}

__global__ void ln_rows_kernel(float* __restrict__ buf)
{
    __shared__ float sb[8];
    long r = blockIdx.x;
    int  d = threadIdx.x;
    float v   = buf[r * DD + d];
    float mu  = blk_sum(v, sb) * (1.f / DD);
    float dv  = v - mu;
    float var = blk_sum(dv * dv, sb) * (1.f / DD);
    float o = dv / sqrtf(var + LNEPS);
    buf[r * DD + d] = o;
    unsigned short hh = f2bf(o);
    g_ykvh[r * DD + d] = hh;
    g_ykvl[r * DD + d] = f2bf(o - bf2f(hh));
}

__global__ void mlp_finish_kernel()
{
    __shared__ float sb[8];
    int t = blockIdx.x, d = threadIdx.x;
    float s = 0.f;
#pragma unroll
    for (int kz = 0; kz < SPLITK; kz++)
        s += g_part[(size_t)kz * TT * DD + t * DD + d];

    float mu  = blk_sum(s, sb) * (1.f / DD);
    float dv  = s - mu;
    float var = blk_sum(dv * dv, sb) * (1.f / DD);
    float a   = dv / sqrtf(var + LNEPS);

    float b = g_x[t * DD + d] + a;
    mu  = blk_sum(b, sb) * (1.f / DD);
    dv  = b - mu;
    var = blk_sum(dv * dv, sb) * (1.f / DD);
    float o = dv / sqrtf(var + LNEPS);
    g_x[t * DD + d] = o;
    unsigned short hh = f2bf(o);
    g_xh[t * DD + d] = hh;
    g_xl[t * DD + d] = f2bf(o - bf2f(hh));
}

// ---------------- launch ----------------
extern "C" void kernel_launch(void* const* d_in, const int* in_sizes, int n_in,
                              void* d_out, int out_size)
{
    (void)in_sizes; (void)n_in; (void)out_size;
    const int*   idx       = (const int*)d_in[0];
    const float* embed     = (const float*)d_in[1];
    const float* encoder   = (const float*)d_in[2];
    const float* encoder_v = (const float*)d_in[3];
    const float* decoder   = (const float*)d_in[4];
    const float* lm_head   = (const float*)d_in[5];
    float*       out       = (float*)d_out;

    float* x = 0; float* xs = 0; float* ykv = 0; float* part = 0;
    unsigned short *sch = 0, *scl = 0;
    unsigned short *qrh = 0, *qrl = 0, *xyh = 0, *xyl = 0;
    unsigned short *xh = 0, *xl = 0, *ykvh = 0, *ykvl = 0;
    unsigned short *ench = 0, *encl = 0, *encvh = 0, *encvl = 0, *dech = 0, *decl = 0;
    cudaGetSymbolAddress((void**)&x,      g_x);
    cudaGetSymbolAddress((void**)&xs,     g_xs);
    cudaGetSymbolAddress((void**)&sch,    g_sch);
    cudaGetSymbolAddress((void**)&scl,    g_scl);
    cudaGetSymbolAddress((void**)&ykv,    g_ykv);
    cudaGetSymbolAddress((void**)&part,   g_part);
    cudaGetSymbolAddress((void**)&qrh,    g_qrh);
    cudaGetSymbolAddress((void**)&qrl,    g_qrl);
    cudaGetSymbolAddress((void**)&xyh,    g_xyh);
    cudaGetSymbolAddress((void**)&xyl,    g_xyl);
    cudaGetSymbolAddress((void**)&xh,     g_xh);
    cudaGetSymbolAddress((void**)&xl,     g_xl);
    cudaGetSymbolAddress((void**)&ykvh,   g_ykvh);
    cudaGetSymbolAddress((void**)&ykvl,   g_ykvl);
    cudaGetSymbolAddress((void**)&ench,   g_ench);
    cudaGetSymbolAddress((void**)&encl,   g_encl);
    cudaGetSymbolAddress((void**)&encvh,  g_encvh);
    cudaGetSymbolAddress((void**)&encvl,  g_encvl);
    cudaGetSymbolAddress((void**)&dech,   g_dech);
    cudaGetSymbolAddress((void**)&decl,   g_decl);

    cudaFuncSetAttribute(scores_hmma, cudaFuncAttributeMaxDynamicSharedMemorySize, SC_SMEM);
    cudaFuncSetAttribute(hmma_gemm<HM_NONE, 0>,  cudaFuncAttributeMaxDynamicSharedMemorySize, H32_SMEM);
    cudaFuncSetAttribute(hmma_gemm<HM_NONE, 1>,  cudaFuncAttributeMaxDynamicSharedMemorySize, H32_SMEM);
    cudaFuncSetAttribute(hmma_gemm<HM_ROPE, 0>,  cudaFuncAttributeMaxDynamicSharedMemorySize, H32_SMEM);
    cudaFuncSetAttribute(hmma_gemm<HM_MULXY, 0>, cudaFuncAttributeMaxDynamicSharedMemorySize, H32_SMEM);

    const long WN = (long)NHH * DD * NN;
    cvt_split<<<(int)(WN / 4 / 256), 256>>>(encoder,   ench,  encl,  WN);
    cvt_split<<<(int)(WN / 4 / 256), 256>>>(encoder_v, encvh, encvl, WN);
    cvt_split<<<(int)(WN / 4 / 256), 256>>>(decoder,   dech,  decl,  WN);

    embed_ln_kernel<<<TT, 256>>>(idx, embed);

    for (int l = 0; l < 2; l++) {
        // x_sparse = relu(x @ encoder) fp32 -> g_xs; QR fp16 hi/lo -> g_qrh/l
        hmma_gemm<HM_ROPE, 0><<<dim3(NN / 128, TT / 128, NHH), 256, H32_SMEM>>>(
            xh, xl, ench, encl, xs, DD, DD, NN, NN,
            0L, (long)DD * NN, (long)TT * NN);

        // scores = mask .* (QR @ QR^T) — fp16 2-pass -> bf16 hi/lo out
        scores_hmma<<<dim3(TT / 128, TT / 128, NHH), 256, SC_SMEM>>>(qrh, qrl, sch, scl);

        // yKV = scores @ x — causal-bounded HMMA (bf16 3-pass)
        hmma_gemm<HM_NONE, 1><<<dim3(DD / 128, TT / 128, NHH), 256, H32_SMEM>>>(
            sch, scl, xh, xl, ykv, TT, TT, DD, DD,
            (long)TT * TT, 0L, (long)TT * DD);

        ln_rows_kernel<<<NHH * TT, 256>>>(ykv);

        // xy = relu(yKV @ encoder_v) * x_sparse -> bf16 hi/lo
        hmma_gemm<HM_MULXY, 0><<<dim3(NN / 128, TT / 128, NHH), 256, H32_SMEM>>>(
            ykvh, ykvl, encvh, encvl, xs, DD, DD, NN, 0,
            (long)TT * DD, (long)DD * NN, 0L);

        // yMLP partials = xy @ decoder (split-K 16)
        hmma_gemm<HM_NONE, 0><<<dim3(DD / 128, TT / 128, SPLITK), 256, H32_SMEM>>>(
            xyh, xyl, dech, decl, part, KSPL, NHH * NN, DD, DD,
            (long)KSPL, (long)KSPL * DD, (long)TT * DD);

        mlp_finish_kernel<<<TT, 256>>>();
    }

    sgemm_kernel<EM_NONE><<<dim3(VOC / 128, TT / 128, 1), 256>>>(
        x, lm_head, out, DD, DD, VOC, VOC, 0L, 0L, 0L);
}

// round 12
// speedup vs baseline: 1.3395x; 1.0753x over previous
#include <cuda_runtime.h>
#include <math.h>
#include <stdint.h>

// ---------------- problem constants ----------------
#define NHH   4
#define DD    256
#define NN    8192
#define TT    2048
#define VOC   256
#define SPLITK 16
#define KSPL  2048              // NHH*NN/SPLITK
#define LNEPS 1e-5f
#define TWO_PI_F 6.28318530717958647692f

// ---------------- scratch (static device globals) ----
__device__ float g_x[TT * DD];
__device__ unsigned short g_xh[TT * DD];
__device__ unsigned short g_xl[TT * DD];
__device__ float g_xs[(size_t)NHH * TT * NN];
__device__ unsigned short g_sch[(size_t)NHH * TT * TT];   // scores hi (fp16)
__device__ unsigned short g_scl[(size_t)NHH * TT * TT];   // scores lo (fp16)
__device__ float g_ykv[(size_t)NHH * TT * DD];
__device__ unsigned short g_ykvh[(size_t)NHH * TT * DD];
__device__ unsigned short g_ykvl[(size_t)NHH * TT * DD];
__device__ float g_part[(size_t)SPLITK * TT * DD];
__device__ unsigned short g_qrh[(size_t)NHH * TT * NN];   // QR hi (fp16)
__device__ unsigned short g_qrl[(size_t)NHH * TT * NN];   // QR lo (fp16)
__device__ unsigned short g_xyh[(size_t)NHH * TT * NN];
__device__ unsigned short g_xyl[(size_t)NHH * TT * NN];
__device__ unsigned short g_ench[(size_t)NHH * DD * NN];
__device__ unsigned short g_encvh[(size_t)NHH * DD * NN];
__device__ unsigned short g_dech[(size_t)NHH * NN * DD];

enum { EM_NONE = 0 };
enum { HM_NONE = 0, HM_ROPE = 1, HM_MULXY = 2 };

typedef unsigned long long u64;

// ---------------- packed f32x2 helpers ----------------
__device__ __forceinline__ void ffma2(u64& d, u64 a, u64 b) {
    asm("fma.rn.f32x2 %0, %1, %2, %0;" : "+l"(d) : "l"(a), "l"(b));
}
__device__ __forceinline__ u64 dup2(float x) {
    u64 r;
    asm("mov.b64 %0, {%1, %1};" : "=l"(r) : "r"(__float_as_uint(x)));
    return r;
}
__device__ __forceinline__ void unpack2(u64 v, float& lo, float& hi) {
    unsigned a, b;
    asm("mov.b64 {%0, %1}, %2;" : "=r"(a), "=r"(b) : "l"(v));
    lo = __uint_as_float(a); hi = __uint_as_float(b);
}

// ---------------- fp16 bit helpers ----------------
__device__ __forceinline__ unsigned short f2h(float x) {
    unsigned short r;
    asm("cvt.rn.f16.f32 %0, %1;" : "=h"(r) : "f"(x));
    return r;
}
__device__ __forceinline__ float h2f(unsigned short h) {
    float r;
    asm("cvt.f32.f16 %0, %1;" : "=f"(r) : "h"(h));
    return r;
}
__device__ __forceinline__ unsigned pack_hl_h(float a, float b,
                                              unsigned short& la, unsigned short& lb) {
    unsigned short ha = f2h(a), hb = f2h(b);
    la = f2h(a - h2f(ha));
    lb = f2h(b - h2f(hb));
    return (unsigned)ha | ((unsigned)hb << 16);
}

// ---------------- warp-MMA helpers ----------------
__device__ __forceinline__ uint32_t smem_to_u32(const void* smem_ptr) {
    uint32_t addr;
    asm("{ .reg .u64 tmp; cvta.to.shared.u64 tmp, %1; cvt.u32.u64 %0, tmp; }"
        : "=r"(addr) : "l"(smem_ptr));
    return addr;
}
__device__ __forceinline__ void ldsm4(uint32_t* r, uint32_t addr) {
    asm volatile("ldmatrix.sync.aligned.m8n8.x4.shared.b16 {%0,%1,%2,%3}, [%4];"
        : "=r"(r[0]), "=r"(r[1]), "=r"(r[2]), "=r"(r[3]) : "r"(addr));
}
__device__ __forceinline__ void ldsm4t(uint32_t* r, uint32_t addr) {
    asm volatile("ldmatrix.sync.aligned.m8n8.x4.trans.shared.b16 {%0,%1,%2,%3}, [%4];"
        : "=r"(r[0]), "=r"(r[1]), "=r"(r[2]), "=r"(r[3]) : "r"(addr));
}
__device__ __forceinline__ void mma16816h(float* c, const uint32_t* a, const uint32_t* b) {
    asm volatile(
        "mma.sync.aligned.m16n8k16.row.col.f32.f16.f16.f32 "
        "{%0,%1,%2,%3}, {%4,%5,%6,%7}, {%8,%9}, {%0,%1,%2,%3};"
        : "+f"(c[0]), "+f"(c[1]), "+f"(c[2]), "+f"(c[3])
        : "r"(a[0]), "r"(a[1]), "r"(a[2]), "r"(a[3]), "r"(b[0]), "r"(b[1]));
}
#define CP_ASYNC16(dst, src) \
    asm volatile("cp.async.cg.shared.global [%0], [%1], 16;" :: "r"(dst), "l"(src))
#define CP_COMMIT() asm volatile("cp.async.commit_group;" ::: "memory")
#define CP_WAIT(n)  asm volatile("cp.async.wait_group %0;" :: "n"(n) : "memory")

__device__ __forceinline__ uint32_t sw64(uint32_t b)  { return b ^ ((b >> 3) & 0x30); }
__device__ __forceinline__ uint32_t sw128(uint32_t b) { return b ^ ((b >> 3) & 0x70); }
__device__ __forceinline__ uint32_t sw256(uint32_t b) { return b ^ ((b >> 4) & 0x70); }

// generic small-K config: K-chunk 32, 3 stages (Ah, Al, Bh) of 24KB, 2 CTAs/SM
#define H32_A    8192            // 128 rows x 64B
#define H32_B    8192            // 32 rows x 256B
#define H32_STG  24576
#define H32_SMEM (3 * H32_STG + 1024)

// scores config: fp16 2-pass, Kc=64, 3 tiles/stage (Ah, Al, Bh), 2 stages, 2 CTAs/SM
#define SC_T     16384           // 128 rows x 128B
#define SC_STG   (3 * SC_T)      // 48KB
#define SC_SMEM  (2 * SC_STG + 1024)

// ================= HMMA scores kernel =================
// scores[h] = mask .* (QR @ QR^T); QR = hi + lo (fp16 splits)
// acc = (hi_a + lo_a) * hi_b  (2 MMA passes)
__global__ void __launch_bounds__(256, 2)
scores_hmma(const unsigned short* __restrict__ qh,
            const unsigned short* __restrict__ ql,
            unsigned short* __restrict__ sch,
            unsigned short* __restrict__ scl)
{
    const int br = blockIdx.y;
    const int bc = blockIdx.x;
    const int h  = blockIdx.z;
    if (bc > br) return;

    extern __shared__ char dsm[];
    const int tid  = threadIdx.x;
    const int wid  = tid >> 5;
    const int lane = tid & 31;
    const int wr   = wid & 3;
    const int wc   = wid >> 2;
    const int row0 = br * 128;
    const int col0 = bc * 128;

    const uint32_t raw = smem_to_u32(dsm);
    const uint32_t sb  = (raw + 1023u) & ~1023u;

    const size_t hb = (size_t)h * TT * NN;
    const unsigned short* srcs[3];
    srcs[0] = qh + hb + (size_t)row0 * NN;
    srcs[1] = ql + hb + (size_t)row0 * NN;
    srcs[2] = qh + hb + (size_t)col0 * NN;

    float acc[2][8][4];
#pragma unroll
    for (int mi = 0; mi < 2; mi++)
#pragma unroll
        for (int ni = 0; ni < 8; ni++)
#pragma unroll
            for (int q = 0; q < 4; q++) acc[mi][ni][q] = 0.f;

    const int NITER = NN / 64;  // 128

    auto load_stage = [&](int st, int kc0) {
        const uint32_t stg = sb + st * SC_STG;
#pragma unroll
        for (int t3 = 0; t3 < 3; t3++) {
            const unsigned short* src = srcs[t3] + kc0;
            const uint32_t tb = stg + t3 * SC_T;
#pragma unroll
            for (int i = 0; i < 4; i++) {
                int idx = i * 256 + tid;
                int r = idx >> 3;
                int c = idx & 7;
                CP_ASYNC16(tb + sw128(r * 128 + c * 16), src + (size_t)r * NN + c * 8);
            }
        }
    };

    load_stage(0, 0);
    CP_COMMIT();

    for (int it = 0; it < NITER; it++) {
        CP_WAIT(0);
        __syncthreads();
        if (it + 1 < NITER) {
            load_stage((it + 1) & 1, (it + 1) * 64);
            CP_COMMIT();
        }

        const uint32_t stg = sb + (it & 1) * SC_STG;
#pragma unroll
        for (int ks = 0; ks < 4; ks++) {
            const int lrow  = lane & 15;
            const int chunk = ks * 2 + (lane >> 4);

            uint32_t ah[2][4], al[2][4];
#pragma unroll
            for (int mi = 0; mi < 2; mi++) {
                int row = wr * 32 + mi * 16 + lrow;
                uint32_t off = sw128(row * 128 + chunk * 16);
                ldsm4(ah[mi], stg + 0 * SC_T + off);
                ldsm4(al[mi], stg + 1 * SC_T + off);
            }

#pragma unroll
            for (int ng = 0; ng < 4; ng++) {
                int row = wc * 64 + ng * 16 + lrow;
                uint32_t off = sw128(row * 128 + chunk * 16);
                uint32_t t0[4];
                ldsm4(t0, stg + 2 * SC_T + off);
                uint32_t bh0[2], bh1[2];
                bh0[0] = t0[0]; bh0[1] = t0[2];
                bh1[0] = t0[1]; bh1[1] = t0[3];
#pragma unroll
                for (int mi = 0; mi < 2; mi++) {
                    mma16816h(acc[mi][2 * ng],     ah[mi], bh0);
                    mma16816h(acc[mi][2 * ng],     al[mi], bh0);
                    mma16816h(acc[mi][2 * ng + 1], ah[mi], bh1);
                    mma16816h(acc[mi][2 * ng + 1], al[mi], bh1);
                }
            }
        }
    }

    // epilogue: strictly-lower mask, write scores as fp16 hi/lo split
    unsigned short* dh = sch + (size_t)h * TT * TT;
    unsigned short* dl = scl + (size_t)h * TT * TT;
    const int rb = row0 + wr * 32;
    const int cb = col0 + wc * 64;
#pragma unroll
    for (int mi = 0; mi < 2; mi++) {
#pragma unroll
        for (int ni = 0; ni < 8; ni++) {
            int r = rb + mi * 16 + (lane >> 2);
            int s = cb + ni * 8 + (lane & 3) * 2;
#pragma unroll
            for (int half = 0; half < 2; half++) {
                int rr = r + half * 8;
                float v0 = (rr > s)     ? acc[mi][ni][half * 2 + 0] : 0.f;
                float v1 = (rr > s + 1) ? acc[mi][ni][half * 2 + 1] : 0.f;
                unsigned short l0, l1;
                unsigned hv = pack_hl_h(v0, v1, l0, l1);
                size_t base = (size_t)rr * TT + s;
                *(unsigned*)(dh + base) = hv;
                *(unsigned*)(dl + base) = (unsigned)l0 | ((unsigned)l1 << 16);
            }
        }
    }
}

// ================= generic HMMA GEMM (fp16 2-pass, Kc=32, 3-stage, 2 CTAs/SM) ==
// A [M,K] k-contig (64B rows, SW64) hi+lo, B [K,N] n-contig (256B rows, SW256) hi.
// acc = (Ah + Al) * Bh (fp32 accum).
template <int HM, int CAUSAL>
__global__ void __launch_bounds__(256, 2)
hmma_gemm(const unsigned short* __restrict__ Ah, const unsigned short* __restrict__ Al,
          const unsigned short* __restrict__ Bh,
          float* __restrict__ C, int K, int lda, int ldb, int ldc,
          long offAz, long offBz, long offCz)
{
    const int z = blockIdx.z;
    Ah += (long)z * offAz;
    Al += (long)z * offAz;
    Bh += (long)z * offBz;
    if (HM != HM_MULXY) C += (long)z * offCz;

    extern __shared__ char dsm[];
    const int tid  = threadIdx.x;
    const int wid  = tid >> 5;
    const int lane = tid & 31;
    const int wr   = wid & 3;
    const int wc   = wid >> 2;
    const int row0 = blockIdx.y * 128;
    const int col0 = blockIdx.x * 128;

    const uint32_t raw = smem_to_u32(dsm);
    const uint32_t sb  = (raw + 1023u) & ~1023u;

    const unsigned short* A0 = Ah + (size_t)row0 * lda;
    const unsigned short* A1 = Al + (size_t)row0 * lda;

    float acc[2][8][4];
#pragma unroll
    for (int mi = 0; mi < 2; mi++)
#pragma unroll
        for (int ni = 0; ni < 8; ni++)
#pragma unroll
            for (int q = 0; q < 4; q++) acc[mi][ni][q] = 0.f;

    const int NITER = (CAUSAL ? (row0 + 128) : K) / 32;

    auto load_stage = [&](int st, int k0) {
        const uint32_t stg = sb + st * H32_STG;
#pragma unroll
        for (int i = 0; i < 2; i++) {
            int idx = i * 256 + tid;
            int r = idx >> 2;
            int c = idx & 3;
            uint32_t off = sw64(r * 64 + c * 16);
            CP_ASYNC16(stg + off,          A0 + (size_t)r * lda + k0 + c * 8);
            CP_ASYNC16(stg + H32_A + off,  A1 + (size_t)r * lda + k0 + c * 8);
        }
#pragma unroll
        for (int i = 0; i < 2; i++) {
            int idx = i * 256 + tid;
            int r = idx >> 4;
            int c = idx & 15;
            uint32_t off = sw256(r * 256 + c * 16);
            CP_ASYNC16(stg + 2 * H32_A + off, Bh + (size_t)(k0 + r) * ldb + col0 + c * 8);
        }
    };

    load_stage(0, 0);
    CP_COMMIT();
    if (NITER > 1) { load_stage(1, 32); CP_COMMIT(); }

    for (int it = 0; it < NITER; it++) {
        if (it + 1 < NITER) { CP_WAIT(1); }
        else                { CP_WAIT(0); }
        __syncthreads();
        if (it + 2 < NITER) {
            load_stage((it + 2) % 3, (it + 2) * 32);
            CP_COMMIT();
        }

        const uint32_t stg = sb + (it % 3) * H32_STG;
#pragma unroll
        for (int ks = 0; ks < 2; ks++) {
            const int lrow = lane & 15;

            uint32_t ah[2][4], al[2][4];
#pragma unroll
            for (int mi = 0; mi < 2; mi++) {
                int row = wr * 32 + mi * 16 + lrow;
                uint32_t off = sw64(row * 64 + (ks * 2 + (lane >> 4)) * 16);
                ldsm4(ah[mi], stg + off);
                ldsm4(al[mi], stg + H32_A + off);
            }

#pragma unroll
            for (int ng = 0; ng < 4; ng++) {
                int kk = ks * 16 + lrow;
                int nc = wc * 64 + ng * 16 + (lane >> 4) * 8;
                uint32_t off = sw256(kk * 256 + nc * 2);
                uint32_t t0[4];
                ldsm4t(t0, stg + 2 * H32_A + off);
                uint32_t bh0[2], bh1[2];
                bh0[0] = t0[0]; bh0[1] = t0[1];
                bh1[0] = t0[2]; bh1[1] = t0[3];
#pragma unroll
                for (int mi = 0; mi < 2; mi++) {
                    mma16816h(acc[mi][2 * ng],     ah[mi], bh0);
                    mma16816h(acc[mi][2 * ng],     al[mi], bh0);
                    mma16816h(acc[mi][2 * ng + 1], ah[mi], bh1);
                    mma16816h(acc[mi][2 * ng + 1], al[mi], bh1);
                }
            }
        }
    }

    // ---------------- epilogues ----------------
    const int rb = row0 + wr * 32;
    const int cb = col0 + wc * 64;

    if (HM == HM_NONE) {
#pragma unroll
        for (int mi = 0; mi < 2; mi++) {
#pragma unroll
            for (int ni = 0; ni < 8; ni++) {
                int r = rb + mi * 16 + (lane >> 2);
                int s = cb + ni * 8 + (lane & 3) * 2;
                *(float2*)(C + (size_t)r * ldc + s) =
                    make_float2(acc[mi][ni][0], acc[mi][ni][1]);
                *(float2*)(C + (size_t)(r + 8) * ldc + s) =
                    make_float2(acc[mi][ni][2], acc[mi][ni][3]);
            }
        }
    } else if (HM == HM_ROPE) {
        unsigned short* Qh = g_qrh + (size_t)z * TT * NN;
        unsigned short* Ql = g_qrl + (size_t)z * TT * NN;
#pragma unroll
        for (int ni = 0; ni < 8; ni++) {
            int n0 = cb + ni * 8 + (lane & 3) * 2;
            float fr = (float)exp2(-(double)n0 / 512.0) / TWO_PI_F;
#pragma unroll
            for (int mi = 0; mi < 2; mi++) {
                int rbase = rb + mi * 16 + (lane >> 2);
#pragma unroll
                for (int half = 0; half < 2; half++) {
                    int r = rbase + half * 8;
                    float v0 = fmaxf(acc[mi][ni][half * 2 + 0], 0.f);
                    float v1 = fmaxf(acc[mi][ni][half * 2 + 1], 0.f);
                    *(float2*)(C + (size_t)r * ldc + n0) = make_float2(v0, v1);
                    float ph   = (float)r * fr;
                    float frac = ph - floorf(ph);
                    float ang  = frac * TWO_PI_F;
                    float si, co;
                    sincosf(ang, &si, &co);
                    float q0 = v0 * co - v1 * si;
                    float q1 = v1 * co + v0 * si;
                    unsigned short l0, l1;
                    unsigned hv = pack_hl_h(q0, q1, l0, l1);
                    *(unsigned*)(Qh + (size_t)r * NN + n0) = hv;
                    *(unsigned*)(Ql + (size_t)r * NN + n0) = (unsigned)l0 | ((unsigned)l1 << 16);
                }
            }
        }
    } else if (HM == HM_MULXY) {
        const float* xsrc = g_xs + (size_t)z * TT * NN;
        unsigned short* Xh = g_xyh;
        unsigned short* Xl = g_xyl;
        const int colz = z * NN;
#pragma unroll
        for (int mi = 0; mi < 2; mi++) {
#pragma unroll
            for (int ni = 0; ni < 8; ni++) {
                int n0 = cb + ni * 8 + (lane & 3) * 2;
                int rbase = rb + mi * 16 + (lane >> 2);
#pragma unroll
                for (int half = 0; half < 2; half++) {
                    int r = rbase + half * 8;
                    float2 xv = *(const float2*)(xsrc + (size_t)r * NN + n0);
                    float v0 = fmaxf(acc[mi][ni][half * 2 + 0], 0.f) * xv.x;
                    float v1 = fmaxf(acc[mi][ni][half * 2 + 1], 0.f) * xv.y;
                    unsigned short l0, l1;
                    unsigned hv = pack_hl_h(v0, v1, l0, l1);
                    size_t base = (size_t)r * (NHH * NN) + colz + n0;
                    *(unsigned*)(Xh + base) = hv;
                    *(unsigned*)(Xl + base) = (unsigned)l0 | ((unsigned)l1 << 16);
                }
            }
        }
    }
}

// ---------------- weight conversion (fp16 hi only for B operands) -------------
__global__ void cvt_h(const float* __restrict__ src,
                      unsigned short* __restrict__ h, long n)
{
    long i = ((long)blockIdx.x * blockDim.x + threadIdx.x) * 4;
    if (i >= n) return;
    float4 v = *(const float4*)(src + i);
    uint2 hv;
    hv.x = (unsigned)f2h(v.x) | ((unsigned)f2h(v.y) << 16);
    hv.y = (unsigned)f2h(v.z) | ((unsigned)f2h(v.w) << 16);
    *(uint2*)(h + i) = hv;
}

// ---------------- block reduction over 256 threads ----------------
__device__ __forceinline__ float blk_sum(float v, float* sb) {
    int tid = threadIdx.x;
#pragma unroll
    for (int o = 16; o > 0; o >>= 1) v += __shfl_down_sync(0xffffffffu, v, o);
    if ((tid & 31) == 0) sb[tid >> 5] = v;
    __syncthreads();
    if (tid < 32) {
        float w = (tid < 8) ? sb[tid] : 0.f;
#pragma unroll
        for (int o = 4; o > 0; o >>= 1) w += __shfl_down_sync(0xffffffffu, w, o);
        if (tid == 0) sb[0] = w;
    }
    __syncthreads();
    float r = sb[0];
    __syncthreads();
    return r;
}

// ---------------- fp32 SGEMM (kept for lm_head) ----------------
template <int MODE>
__global__ void __launch_bounds__(256)
sgemm_kernel(const float* __restrict__ A, const float* __restrict__ B,
             float* __restrict__ C, int K,
             int lda, int ldb, int ldc,
             long offAz, long offBz, long offCz)
{
    const int z = blockIdx.z;
    A += (long)z * offAz;
    B += (long)z * offBz;
    C += (long)z * offCz;

    const int br = blockIdx.y, bc = blockIdx.x;
    const int row0 = br * 128, col0 = bc * 128;
    const int tid = threadIdx.x;
    const int tx = tid & 15, ty = tid >> 4;

    __shared__ __align__(16) float As[8][132];
    __shared__ __align__(16) float Bs[8][132];

    u64 acc2[8][4];
#pragma unroll
    for (int i = 0; i < 8; i++) {
#pragma unroll
        for (int j = 0; j < 4; j++) acc2[i][j] = 0ull;
    }

    const int ar = tid >> 1;
    const int ak = (tid & 1) * 4;
    const int bkr = tid >> 5;
    const int bcc = (tid & 31) * 4;

    const float* Ap = A + (long)(row0 + ar) * lda + ak;
    const float* Bp = B + (long)bkr * ldb + col0 + bcc;

    float4 a4 = *(const float4*)Ap;  Ap += 8;
    float4 b4 = *(const float4*)Bp;  Bp += (long)8 * ldb;

    for (int k0 = 0; k0 < K; k0 += 8) {
        As[ak + 0][ar] = a4.x; As[ak + 1][ar] = a4.y;
        As[ak + 2][ar] = a4.z; As[ak + 3][ar] = a4.w;
        Bs[bkr][bcc + 0] = b4.x; Bs[bkr][bcc + 1] = b4.y;
        Bs[bkr][bcc + 2] = b4.z; Bs[bkr][bcc + 3] = b4.w;
        __syncthreads();

        if (k0 + 8 < K) {
            a4 = *(const float4*)Ap;  Ap += 8;
            b4 = *(const float4*)Bp;  Bp += (long)8 * ldb;
        }

#pragma unroll
        for (int k = 0; k < 8; k++) {
            float a[8];
            *(float4*)&a[0] = *(const float4*)&As[k][ty * 8];
            *(float4*)&a[4] = *(const float4*)&As[k][ty * 8 + 4];
            ulonglong2 bu0 = *(const ulonglong2*)&Bs[k][tx * 8];
            ulonglong2 bu1 = *(const ulonglong2*)&Bs[k][tx * 8 + 4];
            u64 b2[4];
            b2[0] = bu0.x; b2[1] = bu0.y; b2[2] = bu1.x; b2[3] = bu1.y;
            u64 a2[8];
#pragma unroll
            for (int i = 0; i < 8; i++) a2[i] = dup2(a[i]);
#pragma unroll
            for (int i = 0; i < 8; i++) {
#pragma unroll
                for (int j = 0; j < 4; j++) ffma2(acc2[i][j], a2[i], b2[j]);
            }
        }
        __syncthreads();
    }

    float acc[8][8];
#pragma unroll
    for (int i = 0; i < 8; i++) {
#pragma unroll
        for (int j = 0; j < 4; j++) unpack2(acc2[i][j], acc[i][2 * j], acc[i][2 * j + 1]);
    }

#pragma unroll
    for (int i = 0; i < 8; i++) {
        long base = (long)(row0 + ty * 8 + i) * ldc + col0 + tx * 8;
        *(float4*)(C + base)     = make_float4(acc[i][0], acc[i][1], acc[i][2], acc[i][3]);
        *(float4*)(C + base + 4) = make_float4(acc[i][4], acc[i][5], acc[i][6], acc[i][7]);
    }
}

// ---------------- small elementwise kernels ----------------
__global__ void embed_ln_kernel(const int* __restrict__ idx,
                                const float* __restrict__ embed)
{
    __shared__ float sb[8];
    int t = blockIdx.x, d = threadIdx.x;
    float v   = embed[idx[t] * DD + d];
    float mu  = blk_sum(v, sb) * (1.f / DD);
    float dv  = v - mu;
    float var = blk_sum(dv * dv, sb) * (1.f / DD);
    float o = dv / sqrtf(var + LNEPS);
    g_x[t * DD + d] = o;
    unsigned short hh = f2h(o);
    g_xh[t * DD + d] = hh;
    g_xl[t * DD + d] = f2h(o - h2f(hh));
}

__global__ void ln_rows_kernel(float* __restrict__ buf)
{
    __shared__ float sb[8];
    long r = blockIdx.x;
    int  d = threadIdx.x;
    float v   = buf[r * DD + d];
    float mu  = blk_sum(v, sb) * (1.f / DD);
    float dv  = v - mu;
    float var = blk_sum(dv * dv, sb) * (1.f / DD);
    float o = dv / sqrtf(var + LNEPS);
    buf[r * DD + d] = o;
    unsigned short hh = f2h(o);
    g_ykvh[r * DD + d] = hh;
    g_ykvl[r * DD + d] = f2h(o - h2f(hh));
}

__global__ void mlp_finish_kernel()
{
    __shared__ float sb[8];
    int t = blockIdx.x, d = threadIdx.x;
    float s = 0.f;
#pragma unroll
    for (int kz = 0; kz < SPLITK; kz++)
        s += g_part[(size_t)kz * TT * DD + t * DD + d];

    float mu  = blk_sum(s, sb) * (1.f / DD);
    float dv  = s - mu;
    float var = blk_sum(dv * dv, sb) * (1.f / DD);
    float a   = dv / sqrtf(var + LNEPS);

    float b = g_x[t * DD + d] + a;
    mu  = blk_sum(b, sb) * (1.f / DD);
    dv  = b - mu;
    var = blk_sum(dv * dv, sb) * (1.f / DD);
    float o = dv / sqrtf(var + LNEPS);
    g_x[t * DD + d] = o;
    unsigned short hh = f2h(o);
    g_xh[t * DD + d] = hh;
    g_xl[t * DD + d] = f2h(o - h2f(hh));
}

// ---------------- launch ----------------
extern "C" void kernel_launch(void* const* d_in, const int* in_sizes, int n_in,
                              void* d_out, int out_size)
{
    (void)in_sizes; (void)n_in; (void)out_size;
    const int*   idx       = (const int*)d_in[0];
    const float* embed     = (const float*)d_in[1];
    const float* encoder   = (const float*)d_in[2];
    const float* encoder_v = (const float*)d_in[3];
    const float* decoder   = (const float*)d_in[4];
    const float* lm_head   = (const float*)d_in[5];
    float*       out       = (float*)d_out;

    float* x = 0; float* xs = 0; float* ykv = 0; float* part = 0;
    unsigned short *sch = 0, *scl = 0;
    unsigned short *qrh = 0, *qrl = 0, *xyh = 0, *xyl = 0;
    unsigned short *xh = 0, *xl = 0, *ykvh = 0, *ykvl = 0;
    unsigned short *ench = 0, *encvh = 0, *dech = 0;
    cudaGetSymbolAddress((void**)&x,      g_x);
    cudaGetSymbolAddress((void**)&xs,     g_xs);
    cudaGetSymbolAddress((void**)&sch,    g_sch);
    cudaGetSymbolAddress((void**)&scl,    g_scl);
    cudaGetSymbolAddress((void**)&ykv,    g_ykv);
    cudaGetSymbolAddress((void**)&part,   g_part);
    cudaGetSymbolAddress((void**)&qrh,    g_qrh);
    cudaGetSymbolAddress((void**)&qrl,    g_qrl);
    cudaGetSymbolAddress((void**)&xyh,    g_xyh);
    cudaGetSymbolAddress((void**)&xyl,    g_xyl);
    cudaGetSymbolAddress((void**)&xh,     g_xh);
    cudaGetSymbolAddress((void**)&xl,     g_xl);
    cudaGetSymbolAddress((void**)&ykvh,   g_ykvh);
    cudaGetSymbolAddress((void**)&ykvl,   g_ykvl);
    cudaGetSymbolAddress((void**)&ench,   g_ench);
    cudaGetSymbolAddress((void**)&encvh,  g_encvh);
    cudaGetSymbolAddress((void**)&dech,   g_dech);

    cudaFuncSetAttribute(scores_hmma, cudaFuncAttributeMaxDynamicSharedMemorySize, SC_SMEM);
    cudaFuncSetAttribute(hmma_gemm<HM_NONE, 0>,  cudaFuncAttributeMaxDynamicSharedMemorySize, H32_SMEM);
    cudaFuncSetAttribute(hmma_gemm<HM_NONE, 1>,  cudaFuncAttributeMaxDynamicSharedMemorySize, H32_SMEM);
    cudaFuncSetAttribute(hmma_gemm<HM_ROPE, 0>,  cudaFuncAttributeMaxDynamicSharedMemorySize, H32_SMEM);
    cudaFuncSetAttribute(hmma_gemm<HM_MULXY, 0>, cudaFuncAttributeMaxDynamicSharedMemorySize, H32_SMEM);

    const long WN = (long)NHH * DD * NN;
    cvt_h<<<(int)(WN / 4 / 256), 256>>>(encoder,   ench,  WN);
    cvt_h<<<(int)(WN / 4 / 256), 256>>>(encoder_v, encvh, WN);
    cvt_h<<<(int)(WN / 4 / 256), 256>>>(decoder,   dech,  WN);

    embed_ln_kernel<<<TT, 256>>>(idx, embed);

    for (int l = 0; l < 2; l++) {
        // x_sparse = relu(x @ encoder) fp32 -> g_xs; QR fp16 hi/lo -> g_qrh/l
        hmma_gemm<HM_ROPE, 0><<<dim3(NN / 128, TT / 128, NHH), 256, H32_SMEM>>>(
            xh, xl, ench, xs, DD, DD, NN, NN,
            0L, (long)DD * NN, (long)TT * NN);

        // scores = mask .* (QR @ QR^T) — fp16 2-pass -> fp16 hi/lo out
        scores_hmma<<<dim3(TT / 128, TT / 128, NHH), 256, SC_SMEM>>>(qrh, qrl, sch, scl);

        // yKV = scores @ x — causal-bounded fp16 2-pass
        hmma_gemm<HM_NONE, 1><<<dim3(DD / 128, TT / 128, NHH), 256, H32_SMEM>>>(
            sch, scl, xh, ykv, TT, TT, DD, DD,
            (long)TT * TT, 0L, (long)TT * DD);

        ln_rows_kernel<<<NHH * TT, 256>>>(ykv);

        // xy = relu(yKV @ encoder_v) * x_sparse -> fp16 hi/lo
        hmma_gemm<HM_MULXY, 0><<<dim3(NN / 128, TT / 128, NHH), 256, H32_SMEM>>>(
            ykvh, ykvl, encvh, xs, DD, DD, NN, 0,
            (long)TT * DD, (long)DD * NN, 0L);

        // yMLP partials = xy @ decoder (split-K 16)
        hmma_gemm<HM_NONE, 0><<<dim3(DD / 128, TT / 128, SPLITK), 256, H32_SMEM>>>(
            xyh, xyl, dech, part, KSPL, NHH * NN, DD, DD,
            (long)KSPL, (long)KSPL * DD, (long)TT * DD);

        mlp_finish_kernel<<<TT, 256>>>();
    }

    sgemm_kernel<EM_NONE><<<dim3(VOC / 128, TT / 128, 1), 256>>>(
        x, lm_head, out, DD, DD, VOC, VOC, 0L, 0L, 0L);
}

// round 13
// speedup vs baseline: 1.4635x; 1.0926x over previous
#include <cuda_runtime.h>
#include <math.h>
#include <stdint.h>

// ---------------- problem constants ----------------
#define NHH   4
#define DD    256
#define NN    8192
#define TT    2048
#define VOC   256
#define SPLITK 16
#define KSPL  2048              // NHH*NN/SPLITK
#define LNEPS 1e-5f
#define TWO_PI_F 6.28318530717958647692f

// ---------------- scratch (static device globals) ----
__device__ float g_x[TT * DD];
__device__ unsigned short g_xh[TT * DD];
__device__ unsigned short g_xl[TT * DD];
__device__ float g_xs[(size_t)NHH * TT * NN];
__device__ unsigned short g_sch[(size_t)NHH * TT * TT];   // scores hi (fp16)
__device__ unsigned short g_scl[(size_t)NHH * TT * TT];   // scores lo (fp16)
__device__ float g_ykv[(size_t)NHH * TT * DD];
__device__ unsigned short g_ykvh[(size_t)NHH * TT * DD];
__device__ unsigned short g_ykvl[(size_t)NHH * TT * DD];
__device__ float g_part[(size_t)SPLITK * TT * DD];
__device__ unsigned short g_qrh[(size_t)NHH * TT * NN];   // QR hi (fp16)
__device__ unsigned short g_qrl[(size_t)NHH * TT * NN];   // QR lo (fp16)
__device__ unsigned short g_xyh[(size_t)NHH * TT * NN];
__device__ unsigned short g_xyl[(size_t)NHH * TT * NN];
__device__ unsigned short g_ench[(size_t)NHH * DD * NN];
__device__ unsigned short g_encvh[(size_t)NHH * DD * NN];
__device__ unsigned short g_dech[(size_t)NHH * NN * DD];
__device__ float g_fr[NN / 2];                            // rope freq / 2pi per even n

enum { EM_NONE = 0 };
enum { HM_NONE = 0, HM_ROPE = 1, HM_MULXY = 2 };

typedef unsigned long long u64;

// ---------------- packed f32x2 helpers ----------------
__device__ __forceinline__ void ffma2(u64& d, u64 a, u64 b) {
    asm("fma.rn.f32x2 %0, %1, %2, %0;" : "+l"(d) : "l"(a), "l"(b));
}
__device__ __forceinline__ u64 dup2(float x) {
    u64 r;
    asm("mov.b64 %0, {%1, %1};" : "=l"(r) : "r"(__float_as_uint(x)));
    return r;
}
__device__ __forceinline__ void unpack2(u64 v, float& lo, float& hi) {
    unsigned a, b;
    asm("mov.b64 {%0, %1}, %2;" : "=r"(a), "=r"(b) : "l"(v));
    lo = __uint_as_float(a); hi = __uint_as_float(b);
}

// ---------------- fp16 bit helpers ----------------
__device__ __forceinline__ unsigned short f2h(float x) {
    unsigned short r;
    asm("cvt.rn.f16.f32 %0, %1;" : "=h"(r) : "f"(x));
    return r;
}
__device__ __forceinline__ float h2f(unsigned short h) {
    float r;
    asm("cvt.f32.f16 %0, %1;" : "=f"(r) : "h"(h));
    return r;
}
__device__ __forceinline__ unsigned pack_hl_h(float a, float b,
                                              unsigned short& la, unsigned short& lb) {
    unsigned short ha = f2h(a), hb = f2h(b);
    la = f2h(a - h2f(ha));
    lb = f2h(b - h2f(hb));
    return (unsigned)ha | ((unsigned)hb << 16);
}

// ---------------- warp-MMA helpers ----------------
__device__ __forceinline__ uint32_t smem_to_u32(const void* smem_ptr) {
    uint32_t addr;
    asm("{ .reg .u64 tmp; cvta.to.shared.u64 tmp, %1; cvt.u32.u64 %0, tmp; }"
        : "=r"(addr) : "l"(smem_ptr));
    return addr;
}
__device__ __forceinline__ void ldsm4(uint32_t* r, uint32_t addr) {
    asm volatile("ldmatrix.sync.aligned.m8n8.x4.shared.b16 {%0,%1,%2,%3}, [%4];"
        : "=r"(r[0]), "=r"(r[1]), "=r"(r[2]), "=r"(r[3]) : "r"(addr));
}
__device__ __forceinline__ void ldsm4t(uint32_t* r, uint32_t addr) {
    asm volatile("ldmatrix.sync.aligned.m8n8.x4.trans.shared.b16 {%0,%1,%2,%3}, [%4];"
        : "=r"(r[0]), "=r"(r[1]), "=r"(r[2]), "=r"(r[3]) : "r"(addr));
}
__device__ __forceinline__ void mma16816h(float* c, const uint32_t* a, const uint32_t* b) {
    asm volatile(
        "mma.sync.aligned.m16n8k16.row.col.f32.f16.f16.f32 "
        "{%0,%1,%2,%3}, {%4,%5,%6,%7}, {%8,%9}, {%0,%1,%2,%3};"
        : "+f"(c[0]), "+f"(c[1]), "+f"(c[2]), "+f"(c[3])
        : "r"(a[0]), "r"(a[1]), "r"(a[2]), "r"(a[3]), "r"(b[0]), "r"(b[1]));
}
#define CP_ASYNC16(dst, src) \
    asm volatile("cp.async.cg.shared.global [%0], [%1], 16;" :: "r"(dst), "l"(src))
#define CP_COMMIT() asm volatile("cp.async.commit_group;" ::: "memory")
#define CP_WAIT(n)  asm volatile("cp.async.wait_group %0;" :: "n"(n) : "memory")

__device__ __forceinline__ uint32_t sw64(uint32_t b)  { return b ^ ((b >> 3) & 0x30); }
__device__ __forceinline__ uint32_t sw128(uint32_t b) { return b ^ ((b >> 3) & 0x70); }
__device__ __forceinline__ uint32_t sw256(uint32_t b) { return b ^ ((b >> 4) & 0x70); }

// generic small-K config: K-chunk 32, 3 stages (Ah, Al, Bh) of 24KB, 2 CTAs/SM
#define H32_A    8192            // 128 rows x 64B
#define H32_B    8192            // 32 rows x 256B
#define H32_STG  24576
#define H32_SMEM (3 * H32_STG + 1024)

// scores config: fp16 2-pass, Kc=64, 3 tiles/stage (Ah, Al, Bh), 2 stages, 2 CTAs/SM
#define SC_T     16384           // 128 rows x 128B
#define SC_STG   (3 * SC_T)      // 48KB
#define SC_SMEM  (2 * SC_STG + 1024)

// ---------------- rope freq table init (removes per-thread fp64) -------------
__global__ void init_freq()
{
    int i = blockIdx.x * blockDim.x + threadIdx.x;   // 0..NN/2-1
    if (i >= NN / 2) return;
    int n0 = i * 2;
    float a = (float)exp2(-(double)n0 / 512.0);      // identical expression to before
    g_fr[i] = a / TWO_PI_F;
}

// ================= HMMA scores kernel =================
// scores[h] = mask .* (QR @ QR^T); QR = hi + lo (fp16 splits)
// acc = (hi_a + lo_a) * hi_b  (2 MMA passes)
__global__ void __launch_bounds__(256, 2)
scores_hmma(const unsigned short* __restrict__ qh,
            const unsigned short* __restrict__ ql,
            unsigned short* __restrict__ sch,
            unsigned short* __restrict__ scl)
{
    const int br = blockIdx.y;
    const int bc = blockIdx.x;
    const int h  = blockIdx.z;
    if (bc > br) return;

    extern __shared__ char dsm[];
    const int tid  = threadIdx.x;
    const int wid  = tid >> 5;
    const int lane = tid & 31;
    const int wr   = wid & 3;
    const int wc   = wid >> 2;
    const int row0 = br * 128;
    const int col0 = bc * 128;

    const uint32_t raw = smem_to_u32(dsm);
    const uint32_t sb  = (raw + 1023u) & ~1023u;

    const size_t hb = (size_t)h * TT * NN;
    const unsigned short* srcs[3];
    srcs[0] = qh + hb + (size_t)row0 * NN;
    srcs[1] = ql + hb + (size_t)row0 * NN;
    srcs[2] = qh + hb + (size_t)col0 * NN;

    float acc[2][8][4];
#pragma unroll
    for (int mi = 0; mi < 2; mi++)
#pragma unroll
        for (int ni = 0; ni < 8; ni++)
#pragma unroll
            for (int q = 0; q < 4; q++) acc[mi][ni][q] = 0.f;

    const int NITER = NN / 64;  // 128

    auto load_stage = [&](int st, int kc0) {
        const uint32_t stg = sb + st * SC_STG;
#pragma unroll
        for (int t3 = 0; t3 < 3; t3++) {
            const unsigned short* src = srcs[t3] + kc0;
            const uint32_t tb = stg + t3 * SC_T;
#pragma unroll
            for (int i = 0; i < 4; i++) {
                int idx = i * 256 + tid;
                int r = idx >> 3;
                int c = idx & 7;
                CP_ASYNC16(tb + sw128(r * 128 + c * 16), src + (size_t)r * NN + c * 8);
            }
        }
    };

    load_stage(0, 0);
    CP_COMMIT();

    for (int it = 0; it < NITER; it++) {
        CP_WAIT(0);
        __syncthreads();
        if (it + 1 < NITER) {
            load_stage((it + 1) & 1, (it + 1) * 64);
            CP_COMMIT();
        }

        const uint32_t stg = sb + (it & 1) * SC_STG;
#pragma unroll
        for (int ks = 0; ks < 4; ks++) {
            const int lrow  = lane & 15;
            const int chunk = ks * 2 + (lane >> 4);

            uint32_t ah[2][4], al[2][4];
#pragma unroll
            for (int mi = 0; mi < 2; mi++) {
                int row = wr * 32 + mi * 16 + lrow;
                uint32_t off = sw128(row * 128 + chunk * 16);
                ldsm4(ah[mi], stg + 0 * SC_T + off);
                ldsm4(al[mi], stg + 1 * SC_T + off);
            }

#pragma unroll
            for (int ng = 0; ng < 4; ng++) {
                int row = wc * 64 + ng * 16 + lrow;
                uint32_t off = sw128(row * 128 + chunk * 16);
                uint32_t t0[4];
                ldsm4(t0, stg + 2 * SC_T + off);
                uint32_t bh0[2], bh1[2];
                bh0[0] = t0[0]; bh0[1] = t0[2];
                bh1[0] = t0[1]; bh1[1] = t0[3];
#pragma unroll
                for (int mi = 0; mi < 2; mi++) {
                    mma16816h(acc[mi][2 * ng],     ah[mi], bh0);
                    mma16816h(acc[mi][2 * ng],     al[mi], bh0);
                    mma16816h(acc[mi][2 * ng + 1], ah[mi], bh1);
                    mma16816h(acc[mi][2 * ng + 1], al[mi], bh1);
                }
            }
        }
    }

    // epilogue: strictly-lower mask, write scores as fp16 hi/lo split
    unsigned short* dh = sch + (size_t)h * TT * TT;
    unsigned short* dl = scl + (size_t)h * TT * TT;
    const int rb = row0 + wr * 32;
    const int cb = col0 + wc * 64;
#pragma unroll
    for (int mi = 0; mi < 2; mi++) {
#pragma unroll
        for (int ni = 0; ni < 8; ni++) {
            int r = rb + mi * 16 + (lane >> 2);
            int s = cb + ni * 8 + (lane & 3) * 2;
#pragma unroll
            for (int half = 0; half < 2; half++) {
                int rr = r + half * 8;
                float v0 = (rr > s)     ? acc[mi][ni][half * 2 + 0] : 0.f;
                float v1 = (rr > s + 1) ? acc[mi][ni][half * 2 + 1] : 0.f;
                unsigned short l0, l1;
                unsigned hv = pack_hl_h(v0, v1, l0, l1);
                size_t base = (size_t)rr * TT + s;
                *(unsigned*)(dh + base) = hv;
                *(unsigned*)(dl + base) = (unsigned)l0 | ((unsigned)l1 << 16);
            }
        }
    }
}

// ================= generic HMMA GEMM (fp16 2-pass, Kc=32, 3-stage, 2 CTAs/SM) ==
// A [M,K] k-contig (64B rows, SW64) hi+lo, B [K,N] n-contig (256B rows, SW256) hi.
// acc = (Ah + Al) * Bh (fp32 accum).
template <int HM, int CAUSAL>
__global__ void __launch_bounds__(256, 2)
hmma_gemm(const unsigned short* __restrict__ Ah, const unsigned short* __restrict__ Al,
          const unsigned short* __restrict__ Bh,
          float* __restrict__ C, int K, int lda, int ldb, int ldc,
          long offAz, long offBz, long offCz)
{
    const int z = blockIdx.z;
    Ah += (long)z * offAz;
    Al += (long)z * offAz;
    Bh += (long)z * offBz;
    if (HM != HM_MULXY) C += (long)z * offCz;

    extern __shared__ char dsm[];
    const int tid  = threadIdx.x;
    const int wid  = tid >> 5;
    const int lane = tid & 31;
    const int wr   = wid & 3;
    const int wc   = wid >> 2;
    const int row0 = blockIdx.y * 128;
    const int col0 = blockIdx.x * 128;

    const uint32_t raw = smem_to_u32(dsm);
    const uint32_t sb  = (raw + 1023u) & ~1023u;

    const unsigned short* A0 = Ah + (size_t)row0 * lda;
    const unsigned short* A1 = Al + (size_t)row0 * lda;

    float acc[2][8][4];
#pragma unroll
    for (int mi = 0; mi < 2; mi++)
#pragma unroll
        for (int ni = 0; ni < 8; ni++)
#pragma unroll
            for (int q = 0; q < 4; q++) acc[mi][ni][q] = 0.f;

    const int NITER = (CAUSAL ? (row0 + 128) : K) / 32;

    auto load_stage = [&](int st, int k0) {
        const uint32_t stg = sb + st * H32_STG;
#pragma unroll
        for (int i = 0; i < 2; i++) {
            int idx = i * 256 + tid;
            int r = idx >> 2;
            int c = idx & 3;
            uint32_t off = sw64(r * 64 + c * 16);
            CP_ASYNC16(stg + off,          A0 + (size_t)r * lda + k0 + c * 8);
            CP_ASYNC16(stg + H32_A + off,  A1 + (size_t)r * lda + k0 + c * 8);
        }
#pragma unroll
        for (int i = 0; i < 2; i++) {
            int idx = i * 256 + tid;
            int r = idx >> 4;
            int c = idx & 15;
            uint32_t off = sw256(r * 256 + c * 16);
            CP_ASYNC16(stg + 2 * H32_A + off, Bh + (size_t)(k0 + r) * ldb + col0 + c * 8);
        }
    };

    load_stage(0, 0);
    CP_COMMIT();
    if (NITER > 1) { load_stage(1, 32); CP_COMMIT(); }

    for (int it = 0; it < NITER; it++) {
        if (it + 1 < NITER) { CP_WAIT(1); }
        else                { CP_WAIT(0); }
        __syncthreads();
        if (it + 2 < NITER) {
            load_stage((it + 2) % 3, (it + 2) * 32);
            CP_COMMIT();
        }

        const uint32_t stg = sb + (it % 3) * H32_STG;
#pragma unroll
        for (int ks = 0; ks < 2; ks++) {
            const int lrow = lane & 15;

            uint32_t ah[2][4], al[2][4];
#pragma unroll
            for (int mi = 0; mi < 2; mi++) {
                int row = wr * 32 + mi * 16 + lrow;
                uint32_t off = sw64(row * 64 + (ks * 2 + (lane >> 4)) * 16);
                ldsm4(ah[mi], stg + off);
                ldsm4(al[mi], stg + H32_A + off);
            }

#pragma unroll
            for (int ng = 0; ng < 4; ng++) {
                int kk = ks * 16 + lrow;
                int nc = wc * 64 + ng * 16 + (lane >> 4) * 8;
                uint32_t off = sw256(kk * 256 + nc * 2);
                uint32_t t0[4];
                ldsm4t(t0, stg + 2 * H32_A + off);
                uint32_t bh0[2], bh1[2];
                bh0[0] = t0[0]; bh0[1] = t0[1];
                bh1[0] = t0[2]; bh1[1] = t0[3];
#pragma unroll
                for (int mi = 0; mi < 2; mi++) {
                    mma16816h(acc[mi][2 * ng],     ah[mi], bh0);
                    mma16816h(acc[mi][2 * ng],     al[mi], bh0);
                    mma16816h(acc[mi][2 * ng + 1], ah[mi], bh1);
                    mma16816h(acc[mi][2 * ng + 1], al[mi], bh1);
                }
            }
        }
    }

    // ---------------- epilogues ----------------
    const int rb = row0 + wr * 32;
    const int cb = col0 + wc * 64;

    if (HM == HM_NONE) {
#pragma unroll
        for (int mi = 0; mi < 2; mi++) {
#pragma unroll
            for (int ni = 0; ni < 8; ni++) {
                int r = rb + mi * 16 + (lane >> 2);
                int s = cb + ni * 8 + (lane & 3) * 2;
                *(float2*)(C + (size_t)r * ldc + s) =
                    make_float2(acc[mi][ni][0], acc[mi][ni][1]);
                *(float2*)(C + (size_t)(r + 8) * ldc + s) =
                    make_float2(acc[mi][ni][2], acc[mi][ni][3]);
            }
        }
    } else if (HM == HM_ROPE) {
        unsigned short* Qh = g_qrh + (size_t)z * TT * NN;
        unsigned short* Ql = g_qrl + (size_t)z * TT * NN;
#pragma unroll
        for (int ni = 0; ni < 8; ni++) {
            int n0 = cb + ni * 8 + (lane & 3) * 2;
            float fr = g_fr[n0 >> 1];
#pragma unroll
            for (int mi = 0; mi < 2; mi++) {
                int rbase = rb + mi * 16 + (lane >> 2);
#pragma unroll
                for (int half = 0; half < 2; half++) {
                    int r = rbase + half * 8;
                    float v0 = fmaxf(acc[mi][ni][half * 2 + 0], 0.f);
                    float v1 = fmaxf(acc[mi][ni][half * 2 + 1], 0.f);
                    *(float2*)(C + (size_t)r * ldc + n0) = make_float2(v0, v1);
                    float ph   = (float)r * fr;
                    float frac = ph - floorf(ph);
                    float ang  = frac * TWO_PI_F;
                    float si, co;
                    __sincosf(ang, &si, &co);
                    float q0 = v0 * co - v1 * si;
                    float q1 = v1 * co + v0 * si;
                    unsigned short l0, l1;
                    unsigned hv = pack_hl_h(q0, q1, l0, l1);
                    *(unsigned*)(Qh + (size_t)r * NN + n0) = hv;
                    *(unsigned*)(Ql + (size_t)r * NN + n0) = (unsigned)l0 | ((unsigned)l1 << 16);
                }
            }
        }
    } else if (HM == HM_MULXY) {
        const float* xsrc = g_xs + (size_t)z * TT * NN;
        unsigned short* Xh = g_xyh;
        unsigned short* Xl = g_xyl;
        const int colz = z * NN;
#pragma unroll
        for (int mi = 0; mi < 2; mi++) {
#pragma unroll
            for (int ni = 0; ni < 8; ni++) {
                int n0 = cb + ni * 8 + (lane & 3) * 2;
                int rbase = rb + mi * 16 + (lane >> 2);
#pragma unroll
                for (int half = 0; half < 2; half++) {
                    int r = rbase + half * 8;
                    float2 xv = *(const float2*)(xsrc + (size_t)r * NN + n0);
                    float v0 = fmaxf(acc[mi][ni][half * 2 + 0], 0.f) * xv.x;
                    float v1 = fmaxf(acc[mi][ni][half * 2 + 1], 0.f) * xv.y;
                    unsigned short l0, l1;
                    unsigned hv = pack_hl_h(v0, v1, l0, l1);
                    size_t base = (size_t)r * (NHH * NN) + colz + n0;
                    *(unsigned*)(Xh + base) = hv;
                    *(unsigned*)(Xl + base) = (unsigned)l0 | ((unsigned)l1 << 16);
                }
            }
        }
    }
}

// ---------------- weight conversion (fp16 hi only for B operands) -------------
__global__ void cvt_h(const float* __restrict__ src,
                      unsigned short* __restrict__ h, long n)
{
    long i = ((long)blockIdx.x * blockDim.x + threadIdx.x) * 4;
    if (i >= n) return;
    float4 v = *(const float4*)(src + i);
    uint2 hv;
    hv.x = (unsigned)f2h(v.x) | ((unsigned)f2h(v.y) << 16);
    hv.y = (unsigned)f2h(v.z) | ((unsigned)f2h(v.w) << 16);
    *(uint2*)(h + i) = hv;
}

// ---------------- block reduction over 256 threads ----------------
__device__ __forceinline__ float blk_sum(float v, float* sb) {
    int tid = threadIdx.x;
#pragma unroll
    for (int o = 16; o > 0; o >>= 1) v += __shfl_down_sync(0xffffffffu, v, o);
    if ((tid & 31) == 0) sb[tid >> 5] = v;
    __syncthreads();
    if (tid < 32) {
        float w = (tid < 8) ? sb[tid] : 0.f;
#pragma unroll
        for (int o = 4; o > 0; o >>= 1) w += __shfl_down_sync(0xffffffffu, w, o);
        if (tid == 0) sb[0] = w;
    }
    __syncthreads();
    float r = sb[0];
    __syncthreads();
    return r;
}

// ---------------- fp32 SGEMM (kept for lm_head) ----------------
template <int MODE>
__global__ void __launch_bounds__(256)
sgemm_kernel(const float* __restrict__ A, const float* __restrict__ B,
             float* __restrict__ C, int K,
             int lda, int ldb, int ldc,
             long offAz, long offBz, long offCz)
{
    const int z = blockIdx.z;
    A += (long)z * offAz;
    B += (long)z * offBz;
    C += (long)z * offCz;

    const int br = blockIdx.y, bc = blockIdx.x;
    const int row0 = br * 128, col0 = bc * 128;
    const int tid = threadIdx.x;
    const int tx = tid & 15, ty = tid >> 4;

    __shared__ __align__(16) float As[8][132];
    __shared__ __align__(16) float Bs[8][132];

    u64 acc2[8][4];
#pragma unroll
    for (int i = 0; i < 8; i++) {
#pragma unroll
        for (int j = 0; j < 4; j++) acc2[i][j] = 0ull;
    }

    const int ar = tid >> 1;
    const int ak = (tid & 1) * 4;
    const int bkr = tid >> 5;
    const int bcc = (tid & 31) * 4;

    const float* Ap = A + (long)(row0 + ar) * lda + ak;
    const float* Bp = B + (long)bkr * ldb + col0 + bcc;

    float4 a4 = *(const float4*)Ap;  Ap += 8;
    float4 b4 = *(const float4*)Bp;  Bp += (long)8 * ldb;

    for (int k0 = 0; k0 < K; k0 += 8) {
        As[ak + 0][ar] = a4.x; As[ak + 1][ar] = a4.y;
        As[ak + 2][ar] = a4.z; As[ak + 3][ar] = a4.w;
        Bs[bkr][bcc + 0] = b4.x; Bs[bkr][bcc + 1] = b4.y;
        Bs[bkr][bcc + 2] = b4.z; Bs[bkr][bcc + 3] = b4.w;
        __syncthreads();

        if (k0 + 8 < K) {
            a4 = *(const float4*)Ap;  Ap += 8;
            b4 = *(const float4*)Bp;  Bp += (long)8 * ldb;
        }

#pragma unroll
        for (int k = 0; k < 8; k++) {
            float a[8];
            *(float4*)&a[0] = *(const float4*)&As[k][ty * 8];
            *(float4*)&a[4] = *(const float4*)&As[k][ty * 8 + 4];
            ulonglong2 bu0 = *(const ulonglong2*)&Bs[k][tx * 8];
            ulonglong2 bu1 = *(const ulonglong2*)&Bs[k][tx * 8 + 4];
            u64 b2[4];
            b2[0] = bu0.x; b2[1] = bu0.y; b2[2] = bu1.x; b2[3] = bu1.y;
            u64 a2[8];
#pragma unroll
            for (int i = 0; i < 8; i++) a2[i] = dup2(a[i]);
#pragma unroll
            for (int i = 0; i < 8; i++) {
#pragma unroll
                for (int j = 0; j < 4; j++) ffma2(acc2[i][j], a2[i], b2[j]);
            }
        }
        __syncthreads();
    }

    float acc[8][8];
#pragma unroll
    for (int i = 0; i < 8; i++) {
#pragma unroll
        for (int j = 0; j < 4; j++) unpack2(acc2[i][j], acc[i][2 * j], acc[i][2 * j + 1]);
    }

#pragma unroll
    for (int i = 0; i < 8; i++) {
        long base = (long)(row0 + ty * 8 + i) * ldc + col0 + tx * 8;
        *(float4*)(C + base)     = make_float4(acc[i][0], acc[i][1], acc[i][2], acc[i][3]);
        *(float4*)(C + base + 4) = make_float4(acc[i][4], acc[i][5], acc[i][6], acc[i][7]);
    }
}

// ---------------- small elementwise kernels ----------------
__global__ void embed_ln_kernel(const int* __restrict__ idx,
                                const float* __restrict__ embed)
{
    __shared__ float sb[8];
    int t = blockIdx.x, d = threadIdx.x;
    float v   = embed[idx[t] * DD + d];
    float mu  = blk_sum(v, sb) * (1.f / DD);
    float dv  = v - mu;
    float var = blk_sum(dv * dv, sb) * (1.f / DD);
    float o = dv / sqrtf(var + LNEPS);
    g_x[t * DD + d] = o;
    unsigned short hh = f2h(o);
    g_xh[t * DD + d] = hh;
    g_xl[t * DD + d] = f2h(o - h2f(hh));
}

__global__ void ln_rows_kernel(float* __restrict__ buf)
{
    __shared__ float sb[8];
    long r = blockIdx.x;
    int  d = threadIdx.x;
    float v   = buf[r * DD + d];
    float mu  = blk_sum(v, sb) * (1.f / DD);
    float dv  = v - mu;
    float var = blk_sum(dv * dv, sb) * (1.f / DD);
    float o = dv / sqrtf(var + LNEPS);
    buf[r * DD + d] = o;
    unsigned short hh = f2h(o);
    g_ykvh[r * DD + d] = hh;
    g_ykvl[r * DD + d] = f2h(o - h2f(hh));
}

__global__ void mlp_finish_kernel()
{
    __shared__ float sb[8];
    int t = blockIdx.x, d = threadIdx.x;
    float s = 0.f;
#pragma unroll
    for (int kz = 0; kz < SPLITK; kz++)
        s += g_part[(size_t)kz * TT * DD + t * DD + d];

    float mu  = blk_sum(s, sb) * (1.f / DD);
    float dv  = s - mu;
    float var = blk_sum(dv * dv, sb) * (1.f / DD);
    float a   = dv / sqrtf(var + LNEPS);

    float b = g_x[t * DD + d] + a;
    mu  = blk_sum(b, sb) * (1.f / DD);
    dv  = b - mu;
    var = blk_sum(dv * dv, sb) * (1.f / DD);
    float o = dv / sqrtf(var + LNEPS);
    g_x[t * DD + d] = o;
    unsigned short hh = f2h(o);
    g_xh[t * DD + d] = hh;
    g_xl[t * DD + d] = f2h(o - h2f(hh));
}

// ---------------- launch ----------------
extern "C" void kernel_launch(void* const* d_in, const int* in_sizes, int n_in,
                              void* d_out, int out_size)
{
    (void)in_sizes; (void)n_in; (void)out_size;
    const int*   idx       = (const int*)d_in[0];
    const float* embed     = (const float*)d_in[1];
    const float* encoder   = (const float*)d_in[2];
    const float* encoder_v = (const float*)d_in[3];
    const float* decoder   = (const float*)d_in[4];
    const float* lm_head   = (const float*)d_in[5];
    float*       out       = (float*)d_out;

    float* x = 0; float* xs = 0; float* ykv = 0; float* part = 0;
    unsigned short *sch = 0, *scl = 0;
    unsigned short *qrh = 0, *qrl = 0, *xyh = 0, *xyl = 0;
    unsigned short *xh = 0, *xl = 0, *ykvh = 0, *ykvl = 0;
    unsigned short *ench = 0, *encvh = 0, *dech = 0;
    cudaGetSymbolAddress((void**)&x,      g_x);
    cudaGetSymbolAddress((void**)&xs,     g_xs);
    cudaGetSymbolAddress((void**)&sch,    g_sch);
    cudaGetSymbolAddress((void**)&scl,    g_scl);
    cudaGetSymbolAddress((void**)&ykv,    g_ykv);
    cudaGetSymbolAddress((void**)&part,   g_part);
    cudaGetSymbolAddress((void**)&qrh,    g_qrh);
    cudaGetSymbolAddress((void**)&qrl,    g_qrl);
    cudaGetSymbolAddress((void**)&xyh,    g_xyh);
    cudaGetSymbolAddress((void**)&xyl,    g_xyl);
    cudaGetSymbolAddress((void**)&xh,     g_xh);
    cudaGetSymbolAddress((void**)&xl,     g_xl);
    cudaGetSymbolAddress((void**)&ykvh,   g_ykvh);
    cudaGetSymbolAddress((void**)&ykvl,   g_ykvl);
    cudaGetSymbolAddress((void**)&ench,   g_ench);
    cudaGetSymbolAddress((void**)&encvh,  g_encvh);
    cudaGetSymbolAddress((void**)&dech,   g_dech);

    cudaFuncSetAttribute(scores_hmma, cudaFuncAttributeMaxDynamicSharedMemorySize, SC_SMEM);
    cudaFuncSetAttribute(hmma_gemm<HM_NONE, 0>,  cudaFuncAttributeMaxDynamicSharedMemorySize, H32_SMEM);
    cudaFuncSetAttribute(hmma_gemm<HM_NONE, 1>,  cudaFuncAttributeMaxDynamicSharedMemorySize, H32_SMEM);
    cudaFuncSetAttribute(hmma_gemm<HM_ROPE, 0>,  cudaFuncAttributeMaxDynamicSharedMemorySize, H32_SMEM);
    cudaFuncSetAttribute(hmma_gemm<HM_MULXY, 0>, cudaFuncAttributeMaxDynamicSharedMemorySize, H32_SMEM);

    const long WN = (long)NHH * DD * NN;
    init_freq<<<(NN / 2 + 255) / 256, 256>>>();
    cvt_h<<<(int)(WN / 4 / 256), 256>>>(encoder,   ench,  WN);
    cvt_h<<<(int)(WN / 4 / 256), 256>>>(encoder_v, encvh, WN);
    cvt_h<<<(int)(WN / 4 / 256), 256>>>(decoder,   dech,  WN);

    embed_ln_kernel<<<TT, 256>>>(idx, embed);

    for (int l = 0; l < 2; l++) {
        // x_sparse = relu(x @ encoder) fp32 -> g_xs; QR fp16 hi/lo -> g_qrh/l
        hmma_gemm<HM_ROPE, 0><<<dim3(NN / 128, TT / 128, NHH), 256, H32_SMEM>>>(
            xh, xl, ench, xs, DD, DD, NN, NN,
            0L, (long)DD * NN, (long)TT * NN);

        // scores = mask .* (QR @ QR^T) — fp16 2-pass -> fp16 hi/lo out
        scores_hmma<<<dim3(TT / 128, TT / 128, NHH), 256, SC_SMEM>>>(qrh, qrl, sch, scl);

        // yKV = scores @ x — causal-bounded fp16 2-pass
        hmma_gemm<HM_NONE, 1><<<dim3(DD / 128, TT / 128, NHH), 256, H32_SMEM>>>(
            sch, scl, xh, ykv, TT, TT, DD, DD,
            (long)TT * TT, 0L, (long)TT * DD);

        ln_rows_kernel<<<NHH * TT, 256>>>(ykv);

        // xy = relu(yKV @ encoder_v) * x_sparse -> fp16 hi/lo
        hmma_gemm<HM_MULXY, 0><<<dim3(NN / 128, TT / 128, NHH), 256, H32_SMEM>>>(
            ykvh, ykvl, encvh, xs, DD, DD, NN, 0,
            (long)TT * DD, (long)DD * NN, 0L);

        // yMLP partials = xy @ decoder (split-K 16)
        hmma_gemm<HM_NONE, 0><<<dim3(DD / 128, TT / 128, SPLITK), 256, H32_SMEM>>>(
            xyh, xyl, dech, part, KSPL, NHH * NN, DD, DD,
            (long)KSPL, (long)KSPL * DD, (long)TT * DD);

        mlp_finish_kernel<<<TT, 256>>>();
    }

    sgemm_kernel<EM_NONE><<<dim3(VOC / 128, TT / 128, 1), 256>>>(
        x, lm_head, out, DD, DD, VOC, VOC, 0L, 0L, 0L);
}

// round 14
// speedup vs baseline: 1.4805x; 1.0116x over previous
#include <cuda_runtime.h>
#include <math.h>
#include <stdint.h>

// ---------------- problem constants ----------------
#define NHH   4
#define DD    256
#define NN    8192
#define TT    2048
#define VOC   256
#define SPLITK 16
#define KSPL  2048              // NHH*NN/SPLITK
#define LNEPS 1e-5f
#define TWO_PI_F 6.28318530717958647692f

// ---------------- scratch (static device globals) ----
__device__ float g_x[TT * DD];
__device__ unsigned short g_xh[TT * DD];
__device__ unsigned short g_xl[TT * DD];
__device__ unsigned short g_xsh[(size_t)NHH * TT * NN];   // x_sparse (fp16)
__device__ unsigned short g_sch[(size_t)NHH * TT * TT];   // scores hi (fp16)
__device__ unsigned short g_scl[(size_t)NHH * TT * TT];   // scores lo (fp16)
__device__ float g_ykv[(size_t)NHH * TT * DD];
__device__ unsigned short g_ykvh[(size_t)NHH * TT * DD];
__device__ unsigned short g_ykvl[(size_t)NHH * TT * DD];
__device__ float g_part[(size_t)SPLITK * TT * DD];
__device__ unsigned short g_qrh[(size_t)NHH * TT * NN];   // QR hi (fp16)
__device__ unsigned short g_qrl[(size_t)NHH * TT * NN];   // QR lo (fp16)
__device__ unsigned short g_xyh[(size_t)NHH * TT * NN];
__device__ unsigned short g_xyl[(size_t)NHH * TT * NN];
__device__ unsigned short g_ench[(size_t)NHH * DD * NN];
__device__ unsigned short g_encvh[(size_t)NHH * DD * NN];
__device__ unsigned short g_dech[(size_t)NHH * NN * DD];
__device__ float g_fr[NN / 2];                            // rope freq / 2pi per even n

enum { EM_NONE = 0 };
enum { HM_NONE = 0, HM_ROPE = 1, HM_MULXY = 2 };

typedef unsigned long long u64;

// ---------------- packed f32x2 helpers ----------------
__device__ __forceinline__ void ffma2(u64& d, u64 a, u64 b) {
    asm("fma.rn.f32x2 %0, %1, %2, %0;" : "+l"(d) : "l"(a), "l"(b));
}
__device__ __forceinline__ u64 dup2(float x) {
    u64 r;
    asm("mov.b64 %0, {%1, %1};" : "=l"(r) : "r"(__float_as_uint(x)));
    return r;
}
__device__ __forceinline__ void unpack2(u64 v, float& lo, float& hi) {
    unsigned a, b;
    asm("mov.b64 {%0, %1}, %2;" : "=r"(a), "=r"(b) : "l"(v));
    lo = __uint_as_float(a); hi = __uint_as_float(b);
}

// ---------------- fp16 bit helpers ----------------
__device__ __forceinline__ unsigned short f2h(float x) {
    unsigned short r;
    asm("cvt.rn.f16.f32 %0, %1;" : "=h"(r) : "f"(x));
    return r;
}
__device__ __forceinline__ float h2f(unsigned short h) {
    float r;
    asm("cvt.f32.f16 %0, %1;" : "=f"(r) : "h"(h));
    return r;
}
__device__ __forceinline__ unsigned pack_hl_h(float a, float b,
                                              unsigned short& la, unsigned short& lb) {
    unsigned short ha = f2h(a), hb = f2h(b);
    la = f2h(a - h2f(ha));
    lb = f2h(b - h2f(hb));
    return (unsigned)ha | ((unsigned)hb << 16);
}

// ---------------- warp-MMA helpers ----------------
__device__ __forceinline__ uint32_t smem_to_u32(const void* smem_ptr) {
    uint32_t addr;
    asm("{ .reg .u64 tmp; cvta.to.shared.u64 tmp, %1; cvt.u32.u64 %0, tmp; }"
        : "=r"(addr) : "l"(smem_ptr));
    return addr;
}
__device__ __forceinline__ void ldsm4(uint32_t* r, uint32_t addr) {
    asm volatile("ldmatrix.sync.aligned.m8n8.x4.shared.b16 {%0,%1,%2,%3}, [%4];"
        : "=r"(r[0]), "=r"(r[1]), "=r"(r[2]), "=r"(r[3]) : "r"(addr));
}
__device__ __forceinline__ void ldsm4t(uint32_t* r, uint32_t addr) {
    asm volatile("ldmatrix.sync.aligned.m8n8.x4.trans.shared.b16 {%0,%1,%2,%3}, [%4];"
        : "=r"(r[0]), "=r"(r[1]), "=r"(r[2]), "=r"(r[3]) : "r"(addr));
}
__device__ __forceinline__ void mma16816h(float* c, const uint32_t* a, const uint32_t* b) {
    asm volatile(
        "mma.sync.aligned.m16n8k16.row.col.f32.f16.f16.f32 "
        "{%0,%1,%2,%3}, {%4,%5,%6,%7}, {%8,%9}, {%0,%1,%2,%3};"
        : "+f"(c[0]), "+f"(c[1]), "+f"(c[2]), "+f"(c[3])
        : "r"(a[0]), "r"(a[1]), "r"(a[2]), "r"(a[3]), "r"(b[0]), "r"(b[1]));
}
#define CP_ASYNC16(dst, src) \
    asm volatile("cp.async.cg.shared.global [%0], [%1], 16;" :: "r"(dst), "l"(src))
#define CP_COMMIT() asm volatile("cp.async.commit_group;" ::: "memory")
#define CP_WAIT(n)  asm volatile("cp.async.wait_group %0;" :: "n"(n) : "memory")

__device__ __forceinline__ uint32_t sw64(uint32_t b)  { return b ^ ((b >> 3) & 0x30); }
__device__ __forceinline__ uint32_t sw128(uint32_t b) { return b ^ ((b >> 3) & 0x70); }
__device__ __forceinline__ uint32_t sw256(uint32_t b) { return b ^ ((b >> 4) & 0x70); }

// generic small-K config: K-chunk 32, 3 stages (Ah, Al, Bh) of 24KB, 2 CTAs/SM
#define H32_A    8192            // 128 rows x 64B
#define H32_B    8192            // 32 rows x 256B
#define H32_STG  24576
#define H32_SMEM (3 * H32_STG + 1024)

// scores config: fp16 2-pass, Kc=64, 3 tiles/stage (Ah, Al, Bh), 2 stages, 2 CTAs/SM
#define SC_T     16384           // 128 rows x 128B
#define SC_STG   (3 * SC_T)      // 48KB
#define SC_SMEM  (2 * SC_STG + 1024)

// ---------------- rope freq table init ----------------
__global__ void init_freq()
{
    int i = blockIdx.x * blockDim.x + threadIdx.x;
    if (i >= NN / 2) return;
    int n0 = i * 2;
    float a = (float)exp2(-(double)n0 / 512.0);
    g_fr[i] = a / TWO_PI_F;
}

// ================= HMMA scores kernel =================
__global__ void __launch_bounds__(256, 2)
scores_hmma(const unsigned short* __restrict__ qh,
            const unsigned short* __restrict__ ql,
            unsigned short* __restrict__ sch,
            unsigned short* __restrict__ scl)
{
    const int br = blockIdx.y;
    const int bc = blockIdx.x;
    const int h  = blockIdx.z;
    if (bc > br) return;

    extern __shared__ char dsm[];
    const int tid  = threadIdx.x;
    const int wid  = tid >> 5;
    const int lane = tid & 31;
    const int wr   = wid & 3;
    const int wc   = wid >> 2;
    const int row0 = br * 128;
    const int col0 = bc * 128;

    const uint32_t raw = smem_to_u32(dsm);
    const uint32_t sb  = (raw + 1023u) & ~1023u;

    const size_t hb = (size_t)h * TT * NN;
    const unsigned short* srcs[3];
    srcs[0] = qh + hb + (size_t)row0 * NN;
    srcs[1] = ql + hb + (size_t)row0 * NN;
    srcs[2] = qh + hb + (size_t)col0 * NN;

    float acc[2][8][4];
#pragma unroll
    for (int mi = 0; mi < 2; mi++)
#pragma unroll
        for (int ni = 0; ni < 8; ni++)
#pragma unroll
            for (int q = 0; q < 4; q++) acc[mi][ni][q] = 0.f;

    const int NITER = NN / 64;

    auto load_stage = [&](int st, int kc0) {
        const uint32_t stg = sb + st * SC_STG;
#pragma unroll
        for (int t3 = 0; t3 < 3; t3++) {
            const unsigned short* src = srcs[t3] + kc0;
            const uint32_t tb = stg + t3 * SC_T;
#pragma unroll
            for (int i = 0; i < 4; i++) {
                int idx = i * 256 + tid;
                int r = idx >> 3;
                int c = idx & 7;
                CP_ASYNC16(tb + sw128(r * 128 + c * 16), src + (size_t)r * NN + c * 8);
            }
        }
    };

    load_stage(0, 0);
    CP_COMMIT();

    for (int it = 0; it < NITER; it++) {
        CP_WAIT(0);
        __syncthreads();
        if (it + 1 < NITER) {
            load_stage((it + 1) & 1, (it + 1) * 64);
            CP_COMMIT();
        }

        const uint32_t stg = sb + (it & 1) * SC_STG;
#pragma unroll
        for (int ks = 0; ks < 4; ks++) {
            const int lrow  = lane & 15;
            const int chunk = ks * 2 + (lane >> 4);

            uint32_t ah[2][4], al[2][4];
#pragma unroll
            for (int mi = 0; mi < 2; mi++) {
                int row = wr * 32 + mi * 16 + lrow;
                uint32_t off = sw128(row * 128 + chunk * 16);
                ldsm4(ah[mi], stg + 0 * SC_T + off);
                ldsm4(al[mi], stg + 1 * SC_T + off);
            }

#pragma unroll
            for (int ng = 0; ng < 4; ng++) {
                int row = wc * 64 + ng * 16 + lrow;
                uint32_t off = sw128(row * 128 + chunk * 16);
                uint32_t t0[4];
                ldsm4(t0, stg + 2 * SC_T + off);
                uint32_t bh0[2], bh1[2];
                bh0[0] = t0[0]; bh0[1] = t0[2];
                bh1[0] = t0[1]; bh1[1] = t0[3];
#pragma unroll
                for (int mi = 0; mi < 2; mi++) {
                    mma16816h(acc[mi][2 * ng],     ah[mi], bh0);
                    mma16816h(acc[mi][2 * ng],     al[mi], bh0);
                    mma16816h(acc[mi][2 * ng + 1], ah[mi], bh1);
                    mma16816h(acc[mi][2 * ng + 1], al[mi], bh1);
                }
            }
        }
    }

    // epilogue: strictly-lower mask, write scores as fp16 hi/lo split
    unsigned short* dh = sch + (size_t)h * TT * TT;
    unsigned short* dl = scl + (size_t)h * TT * TT;
    const int rb = row0 + wr * 32;
    const int cb = col0 + wc * 64;
#pragma unroll
    for (int mi = 0; mi < 2; mi++) {
#pragma unroll
        for (int ni = 0; ni < 8; ni++) {
            int r = rb + mi * 16 + (lane >> 2);
            int s = cb + ni * 8 + (lane & 3) * 2;
#pragma unroll
            for (int half = 0; half < 2; half++) {
                int rr = r + half * 8;
                float v0 = (rr > s)     ? acc[mi][ni][half * 2 + 0] : 0.f;
                float v1 = (rr > s + 1) ? acc[mi][ni][half * 2 + 1] : 0.f;
                unsigned short l0, l1;
                unsigned hv = pack_hl_h(v0, v1, l0, l1);
                size_t base = (size_t)rr * TT + s;
                *(unsigned*)(dh + base) = hv;
                *(unsigned*)(dl + base) = (unsigned)l0 | ((unsigned)l1 << 16);
            }
        }
    }
}

// ================= generic HMMA GEMM (fp16 2-pass, Kc=32, 3-stage, 2 CTAs/SM) ==
template <int HM, int CAUSAL>
__global__ void __launch_bounds__(256, 2)
hmma_gemm(const unsigned short* __restrict__ Ah, const unsigned short* __restrict__ Al,
          const unsigned short* __restrict__ Bh,
          float* __restrict__ C, int K, int lda, int ldb, int ldc,
          long offAz, long offBz, long offCz)
{
    const int z = blockIdx.z;
    Ah += (long)z * offAz;
    Al += (long)z * offAz;
    Bh += (long)z * offBz;
    if (HM == HM_NONE) C += (long)z * offCz;

    extern __shared__ char dsm[];
    const int tid  = threadIdx.x;
    const int wid  = tid >> 5;
    const int lane = tid & 31;
    const int wr   = wid & 3;
    const int wc   = wid >> 2;
    const int row0 = blockIdx.y * 128;
    const int col0 = blockIdx.x * 128;

    const uint32_t raw = smem_to_u32(dsm);
    const uint32_t sb  = (raw + 1023u) & ~1023u;

    const unsigned short* A0 = Ah + (size_t)row0 * lda;
    const unsigned short* A1 = Al + (size_t)row0 * lda;

    float acc[2][8][4];
#pragma unroll
    for (int mi = 0; mi < 2; mi++)
#pragma unroll
        for (int ni = 0; ni < 8; ni++)
#pragma unroll
            for (int q = 0; q < 4; q++) acc[mi][ni][q] = 0.f;

    const int NITER = (CAUSAL ? (row0 + 128) : K) / 32;

    auto load_stage = [&](int st, int k0) {
        const uint32_t stg = sb + st * H32_STG;
#pragma unroll
        for (int i = 0; i < 2; i++) {
            int idx = i * 256 + tid;
            int r = idx >> 2;
            int c = idx & 3;
            uint32_t off = sw64(r * 64 + c * 16);
            CP_ASYNC16(stg + off,          A0 + (size_t)r * lda + k0 + c * 8);
            CP_ASYNC16(stg + H32_A + off,  A1 + (size_t)r * lda + k0 + c * 8);
        }
#pragma unroll
        for (int i = 0; i < 2; i++) {
            int idx = i * 256 + tid;
            int r = idx >> 4;
            int c = idx & 15;
            uint32_t off = sw256(r * 256 + c * 16);
            CP_ASYNC16(stg + 2 * H32_A + off, Bh + (size_t)(k0 + r) * ldb + col0 + c * 8);
        }
    };

    load_stage(0, 0);
    CP_COMMIT();
    if (NITER > 1) { load_stage(1, 32); CP_COMMIT(); }

    for (int it = 0; it < NITER; it++) {
        if (it + 1 < NITER) { CP_WAIT(1); }
        else                { CP_WAIT(0); }
        __syncthreads();
        if (it + 2 < NITER) {
            load_stage((it + 2) % 3, (it + 2) * 32);
            CP_COMMIT();
        }

        const uint32_t stg = sb + (it % 3) * H32_STG;
#pragma unroll
        for (int ks = 0; ks < 2; ks++) {
            const int lrow = lane & 15;

            uint32_t ah[2][4], al[2][4];
#pragma unroll
            for (int mi = 0; mi < 2; mi++) {
                int row = wr * 32 + mi * 16 + lrow;
                uint32_t off = sw64(row * 64 + (ks * 2 + (lane >> 4)) * 16);
                ldsm4(ah[mi], stg + off);
                ldsm4(al[mi], stg + H32_A + off);
            }

#pragma unroll
            for (int ng = 0; ng < 4; ng++) {
                int kk = ks * 16 + lrow;
                int nc = wc * 64 + ng * 16 + (lane >> 4) * 8;
                uint32_t off = sw256(kk * 256 + nc * 2);
                uint32_t t0[4];
                ldsm4t(t0, stg + 2 * H32_A + off);
                uint32_t bh0[2], bh1[2];
                bh0[0] = t0[0]; bh0[1] = t0[1];
                bh1[0] = t0[2]; bh1[1] = t0[3];
#pragma unroll
                for (int mi = 0; mi < 2; mi++) {
                    mma16816h(acc[mi][2 * ng],     ah[mi], bh0);
                    mma16816h(acc[mi][2 * ng],     al[mi], bh0);
                    mma16816h(acc[mi][2 * ng + 1], ah[mi], bh1);
                    mma16816h(acc[mi][2 * ng + 1], al[mi], bh1);
                }
            }
        }
    }

    // ---------------- epilogues ----------------
    const int rb = row0 + wr * 32;
    const int cb = col0 + wc * 64;

    if (HM == HM_NONE) {
#pragma unroll
        for (int mi = 0; mi < 2; mi++) {
#pragma unroll
            for (int ni = 0; ni < 8; ni++) {
                int r = rb + mi * 16 + (lane >> 2);
                int s = cb + ni * 8 + (lane & 3) * 2;
                *(float2*)(C + (size_t)r * ldc + s) =
                    make_float2(acc[mi][ni][0], acc[mi][ni][1]);
                *(float2*)(C + (size_t)(r + 8) * ldc + s) =
                    make_float2(acc[mi][ni][2], acc[mi][ni][3]);
            }
        }
    } else if (HM == HM_ROPE) {
        // write x_sparse fp16 and QR fp16 hi/lo
        unsigned short* Xs = g_xsh + (size_t)z * TT * NN;
        unsigned short* Qh = g_qrh + (size_t)z * TT * NN;
        unsigned short* Ql = g_qrl + (size_t)z * TT * NN;
#pragma unroll
        for (int ni = 0; ni < 8; ni++) {
            int n0 = cb + ni * 8 + (lane & 3) * 2;
            float fr = g_fr[n0 >> 1];
#pragma unroll
            for (int mi = 0; mi < 2; mi++) {
                int rbase = rb + mi * 16 + (lane >> 2);
#pragma unroll
                for (int half = 0; half < 2; half++) {
                    int r = rbase + half * 8;
                    float v0 = fmaxf(acc[mi][ni][half * 2 + 0], 0.f);
                    float v1 = fmaxf(acc[mi][ni][half * 2 + 1], 0.f);
                    size_t base = (size_t)r * NN + n0;
                    *(unsigned*)(Xs + base) = (unsigned)f2h(v0) | ((unsigned)f2h(v1) << 16);
                    float ph   = (float)r * fr;
                    float frac = ph - floorf(ph);
                    float ang  = frac * TWO_PI_F;
                    float si, co;
                    __sincosf(ang, &si, &co);
                    float q0 = v0 * co - v1 * si;
                    float q1 = v1 * co + v0 * si;
                    unsigned short l0, l1;
                    unsigned hv = pack_hl_h(q0, q1, l0, l1);
                    *(unsigned*)(Qh + base) = hv;
                    *(unsigned*)(Ql + base) = (unsigned)l0 | ((unsigned)l1 << 16);
                }
            }
        }
    } else if (HM == HM_MULXY) {
        const unsigned short* xsrc = g_xsh + (size_t)z * TT * NN;
        unsigned short* Xh = g_xyh;
        unsigned short* Xl = g_xyl;
        const int colz = z * NN;
#pragma unroll
        for (int mi = 0; mi < 2; mi++) {
#pragma unroll
            for (int ni = 0; ni < 8; ni++) {
                int n0 = cb + ni * 8 + (lane & 3) * 2;
                int rbase = rb + mi * 16 + (lane >> 2);
#pragma unroll
                for (int half = 0; half < 2; half++) {
                    int r = rbase + half * 8;
                    unsigned xv = *(const unsigned*)(xsrc + (size_t)r * NN + n0);
                    float x0 = h2f((unsigned short)(xv & 0xFFFFu));
                    float x1 = h2f((unsigned short)(xv >> 16));
                    float v0 = fmaxf(acc[mi][ni][half * 2 + 0], 0.f) * x0;
                    float v1 = fmaxf(acc[mi][ni][half * 2 + 1], 0.f) * x1;
                    unsigned short l0, l1;
                    unsigned hv = pack_hl_h(v0, v1, l0, l1);
                    size_t base = (size_t)r * (NHH * NN) + colz + n0;
                    *(unsigned*)(Xh + base) = hv;
                    *(unsigned*)(Xl + base) = (unsigned)l0 | ((unsigned)l1 << 16);
                }
            }
        }
    }
}

// ---------------- weight conversion (fp16 hi only for B operands) -------------
__global__ void cvt_h(const float* __restrict__ src,
                      unsigned short* __restrict__ h, long n)
{
    long i = ((long)blockIdx.x * blockDim.x + threadIdx.x) * 4;
    if (i >= n) return;
    float4 v = *(const float4*)(src + i);
    uint2 hv;
    hv.x = (unsigned)f2h(v.x) | ((unsigned)f2h(v.y) << 16);
    hv.y = (unsigned)f2h(v.z) | ((unsigned)f2h(v.w) << 16);
    *(uint2*)(h + i) = hv;
}

// ---------------- block reduction over 256 threads ----------------
__device__ __forceinline__ float blk_sum(float v, float* sb) {
    int tid = threadIdx.x;
#pragma unroll
    for (int o = 16; o > 0; o >>= 1) v += __shfl_down_sync(0xffffffffu, v, o);
    if ((tid & 31) == 0) sb[tid >> 5] = v;
    __syncthreads();
    if (tid < 32) {
        float w = (tid < 8) ? sb[tid] : 0.f;
#pragma unroll
        for (int o = 4; o > 0; o >>= 1) w += __shfl_down_sync(0xffffffffu, w, o);
        if (tid == 0) sb[0] = w;
    }
    __syncthreads();
    float r = sb[0];
    __syncthreads();
    return r;
}

// ---------------- fp32 SGEMM (kept for lm_head) ----------------
template <int MODE>
__global__ void __launch_bounds__(256)
sgemm_kernel(const float* __restrict__ A, const float* __restrict__ B,
             float* __restrict__ C, int K,
             int lda, int ldb, int ldc,
             long offAz, long offBz, long offCz)
{
    const int z = blockIdx.z;
    A += (long)z * offAz;
    B += (long)z * offBz;
    C += (long)z * offCz;

    const int br = blockIdx.y, bc = blockIdx.x;
    const int row0 = br * 128, col0 = bc * 128;
    const int tid = threadIdx.x;
    const int tx = tid & 15, ty = tid >> 4;

    __shared__ __align__(16) float As[8][132];
    __shared__ __align__(16) float Bs[8][132];

    u64 acc2[8][4];
#pragma unroll
    for (int i = 0; i < 8; i++) {
#pragma unroll
        for (int j = 0; j < 4; j++) acc2[i][j] = 0ull;
    }

    const int ar = tid >> 1;
    const int ak = (tid & 1) * 4;
    const int bkr = tid >> 5;
    const int bcc = (tid & 31) * 4;

    const float* Ap = A + (long)(row0 + ar) * lda + ak;
    const float* Bp = B + (long)bkr * ldb + col0 + bcc;

    float4 a4 = *(const float4*)Ap;  Ap += 8;
    float4 b4 = *(const float4*)Bp;  Bp += (long)8 * ldb;

    for (int k0 = 0; k0 < K; k0 += 8) {
        As[ak + 0][ar] = a4.x; As[ak + 1][ar] = a4.y;
        As[ak + 2][ar] = a4.z; As[ak + 3][ar] = a4.w;
        Bs[bkr][bcc + 0] = b4.x; Bs[bkr][bcc + 1] = b4.y;
        Bs[bkr][bcc + 2] = b4.z; Bs[bkr][bcc + 3] = b4.w;
        __syncthreads();

        if (k0 + 8 < K) {
            a4 = *(const float4*)Ap;  Ap += 8;
            b4 = *(const float4*)Bp;  Bp += (long)8 * ldb;
        }

#pragma unroll
        for (int k = 0; k < 8; k++) {
            float a[8];
            *(float4*)&a[0] = *(const float4*)&As[k][ty * 8];
            *(float4*)&a[4] = *(const float4*)&As[k][ty * 8 + 4];
            ulonglong2 bu0 = *(const ulonglong2*)&Bs[k][tx * 8];
            ulonglong2 bu1 = *(const ulonglong2*)&Bs[k][tx * 8 + 4];
            u64 b2[4];
            b2[0] = bu0.x; b2[1] = bu0.y; b2[2] = bu1.x; b2[3] = bu1.y;
            u64 a2[8];
#pragma unroll
            for (int i = 0; i < 8; i++) a2[i] = dup2(a[i]);
#pragma unroll
            for (int i = 0; i < 8; i++) {
#pragma unroll
                for (int j = 0; j < 4; j++) ffma2(acc2[i][j], a2[i], b2[j]);
            }
        }
        __syncthreads();
    }

    float acc[8][8];
#pragma unroll
    for (int i = 0; i < 8; i++) {
#pragma unroll
        for (int j = 0; j < 4; j++) unpack2(acc2[i][j], acc[i][2 * j], acc[i][2 * j + 1]);
    }

#pragma unroll
    for (int i = 0; i < 8; i++) {
        long base = (long)(row0 + ty * 8 + i) * ldc + col0 + tx * 8;
        *(float4*)(C + base)     = make_float4(acc[i][0], acc[i][1], acc[i][2], acc[i][3]);
        *(float4*)(C + base + 4) = make_float4(acc[i][4], acc[i][5], acc[i][6], acc[i][7]);
    }
}

// ---------------- small elementwise kernels ----------------
__global__ void embed_ln_kernel(const int* __restrict__ idx,
                                const float* __restrict__ embed)
{
    __shared__ float sb[8];
    int t = blockIdx.x, d = threadIdx.x;
    float v   = embed[idx[t] * DD + d];
    float mu  = blk_sum(v, sb) * (1.f / DD);
    float dv  = v - mu;
    float var = blk_sum(dv * dv, sb) * (1.f / DD);
    float o = dv / sqrtf(var + LNEPS);
    g_x[t * DD + d] = o;
    unsigned short hh = f2h(o);
    g_xh[t * DD + d] = hh;
    g_xl[t * DD + d] = f2h(o - h2f(hh));
}

__global__ void ln_rows_kernel(float* __restrict__ buf)
{
    __shared__ float sb[8];
    long r = blockIdx.x;
    int  d = threadIdx.x;
    float v   = buf[r * DD + d];
    float mu  = blk_sum(v, sb) * (1.f / DD);
    float dv  = v - mu;
    float var = blk_sum(dv * dv, sb) * (1.f / DD);
    float o = dv / sqrtf(var + LNEPS);
    buf[r * DD + d] = o;
    unsigned short hh = f2h(o);
    g_ykvh[r * DD + d] = hh;
    g_ykvl[r * DD + d] = f2h(o - h2f(hh));
}

__global__ void mlp_finish_kernel()
{
    __shared__ float sb[8];
    int t = blockIdx.x, d = threadIdx.x;
    float s = 0.f;
#pragma unroll
    for (int kz = 0; kz < SPLITK; kz++)
        s += g_part[(size_t)kz * TT * DD + t * DD + d];

    float mu  = blk_sum(s, sb) * (1.f / DD);
    float dv  = s - mu;
    float var = blk_sum(dv * dv, sb) * (1.f / DD);
    float a   = dv / sqrtf(var + LNEPS);

    float b = g_x[t * DD + d] + a;
    mu  = blk_sum(b, sb) * (1.f / DD);
    dv  = b - mu;
    var = blk_sum(dv * dv, sb) * (1.f / DD);
    float o = dv / sqrtf(var + LNEPS);
    g_x[t * DD + d] = o;
    unsigned short hh = f2h(o);
    g_xh[t * DD + d] = hh;
    g_xl[t * DD + d] = f2h(o - h2f(hh));
}

// ---------------- launch ----------------
extern "C" void kernel_launch(void* const* d_in, const int* in_sizes, int n_in,
                              void* d_out, int out_size)
{
    (void)in_sizes; (void)n_in; (void)out_size;
    const int*   idx       = (const int*)d_in[0];
    const float* embed     = (const float*)d_in[1];
    const float* encoder   = (const float*)d_in[2];
    const float* encoder_v = (const float*)d_in[3];
    const float* decoder   = (const float*)d_in[4];
    const float* lm_head   = (const float*)d_in[5];
    float*       out       = (float*)d_out;

    float* x = 0; float* ykv = 0; float* part = 0;
    unsigned short *sch = 0, *scl = 0;
    unsigned short *qrh = 0, *qrl = 0, *xyh = 0, *xyl = 0;
    unsigned short *xh = 0, *xl = 0, *ykvh = 0, *ykvl = 0;
    unsigned short *ench = 0, *encvh = 0, *dech = 0;
    cudaGetSymbolAddress((void**)&x,      g_x);
    cudaGetSymbolAddress((void**)&sch,    g_sch);
    cudaGetSymbolAddress((void**)&scl,    g_scl);
    cudaGetSymbolAddress((void**)&ykv,    g_ykv);
    cudaGetSymbolAddress((void**)&part,   g_part);
    cudaGetSymbolAddress((void**)&qrh,    g_qrh);
    cudaGetSymbolAddress((void**)&qrl,    g_qrl);
    cudaGetSymbolAddress((void**)&xyh,    g_xyh);
    cudaGetSymbolAddress((void**)&xyl,    g_xyl);
    cudaGetSymbolAddress((void**)&xh,     g_xh);
    cudaGetSymbolAddress((void**)&xl,     g_xl);
    cudaGetSymbolAddress((void**)&ykvh,   g_ykvh);
    cudaGetSymbolAddress((void**)&ykvl,   g_ykvl);
    cudaGetSymbolAddress((void**)&ench,   g_ench);
    cudaGetSymbolAddress((void**)&encvh,  g_encvh);
    cudaGetSymbolAddress((void**)&dech,   g_dech);

    cudaFuncSetAttribute(scores_hmma, cudaFuncAttributeMaxDynamicSharedMemorySize, SC_SMEM);
    cudaFuncSetAttribute(hmma_gemm<HM_NONE, 0>,  cudaFuncAttributeMaxDynamicSharedMemorySize, H32_SMEM);
    cudaFuncSetAttribute(hmma_gemm<HM_NONE, 1>,  cudaFuncAttributeMaxDynamicSharedMemorySize, H32_SMEM);
    cudaFuncSetAttribute(hmma_gemm<HM_ROPE, 0>,  cudaFuncAttributeMaxDynamicSharedMemorySize, H32_SMEM);
    cudaFuncSetAttribute(hmma_gemm<HM_MULXY, 0>, cudaFuncAttributeMaxDynamicSharedMemorySize, H32_SMEM);

    const long WN = (long)NHH * DD * NN;
    init_freq<<<(NN / 2 + 255) / 256, 256>>>();
    cvt_h<<<(int)(WN / 4 / 256), 256>>>(encoder,   ench,  WN);
    cvt_h<<<(int)(WN / 4 / 256), 256>>>(encoder_v, encvh, WN);
    cvt_h<<<(int)(WN / 4 / 256), 256>>>(decoder,   dech,  WN);

    embed_ln_kernel<<<TT, 256>>>(idx, embed);

    for (int l = 0; l < 2; l++) {
        // x_sparse fp16 -> g_xsh; QR fp16 hi/lo -> g_qrh/l  (C unused)
        hmma_gemm<HM_ROPE, 0><<<dim3(NN / 128, TT / 128, NHH), 256, H32_SMEM>>>(
            xh, xl, ench, part, DD, DD, NN, NN,
            0L, (long)DD * NN, 0L);

        // scores = mask .* (QR @ QR^T) — fp16 2-pass -> fp16 hi/lo out
        scores_hmma<<<dim3(TT / 128, TT / 128, NHH), 256, SC_SMEM>>>(qrh, qrl, sch, scl);

        // yKV = scores @ x — causal-bounded fp16 2-pass
        hmma_gemm<HM_NONE, 1><<<dim3(DD / 128, TT / 128, NHH), 256, H32_SMEM>>>(
            sch, scl, xh, ykv, TT, TT, DD, DD,
            (long)TT * TT, 0L, (long)TT * DD);

        ln_rows_kernel<<<NHH * TT, 256>>>(ykv);

        // xy = relu(yKV @ encoder_v) * x_sparse -> fp16 hi/lo  (C unused)
        hmma_gemm<HM_MULXY, 0><<<dim3(NN / 128, TT / 128, NHH), 256, H32_SMEM>>>(
            ykvh, ykvl, encvh, part, DD, DD, NN, 0,
            (long)TT * DD, (long)DD * NN, 0L);

        // yMLP partials = xy @ decoder (split-K 16)
        hmma_gemm<HM_NONE, 0><<<dim3(DD / 128, TT / 128, SPLITK), 256, H32_SMEM>>>(
            xyh, xyl, dech, part, KSPL, NHH * NN, DD, DD,
            (long)KSPL, (long)KSPL * DD, (long)TT * DD);

        mlp_finish_kernel<<<TT, 256>>>();
    }

    sgemm_kernel<EM_NONE><<<dim3(VOC / 128, TT / 128, 1), 256>>>(
        x, lm_head, out, DD, DD, VOC, VOC, 0L, 0L, 0L);
}

// round 15
// speedup vs baseline: 2.0420x; 1.3793x over previous
#include <cuda_runtime.h>
#include <math.h>
#include <stdint.h>

// ---------------- problem constants ----------------
#define NHH   4
#define DD    256
#define NN    8192
#define TT    2048
#define VOC   256
#define SPLITK 16
#define KSPL  2048              // NHH*NN/SPLITK
#define LNEPS 1e-5f
#define TWO_PI_F 6.28318530717958647692f

// ---------------- scratch (static device globals) ----
__device__ float g_x[TT * DD];
__device__ unsigned short g_xh[TT * DD];
__device__ unsigned short g_xl[TT * DD];
__device__ unsigned short g_xsh[(size_t)NHH * TT * NN];   // x_sparse (fp16)
__device__ unsigned short g_sch[(size_t)NHH * TT * TT];   // scores hi (fp16)
__device__ unsigned short g_scl[(size_t)NHH * TT * TT];   // scores lo (fp16)
__device__ float g_ykv[(size_t)NHH * TT * DD];
__device__ unsigned short g_ykvh[(size_t)NHH * TT * DD];
__device__ unsigned short g_ykvl[(size_t)NHH * TT * DD];
__device__ float g_part[(size_t)SPLITK * TT * DD];
__device__ unsigned short g_qrh[(size_t)NHH * TT * NN];   // QR (fp16, single precision level)
__device__ unsigned short g_xyh[(size_t)NHH * TT * NN];
__device__ unsigned short g_xyl[(size_t)NHH * TT * NN];
__device__ unsigned short g_ench[(size_t)NHH * DD * NN];
__device__ unsigned short g_encvh[(size_t)NHH * DD * NN];
__device__ unsigned short g_dech[(size_t)NHH * NN * DD];
__device__ float g_fr[NN / 2];                            // rope freq / 2pi per even n

enum { EM_NONE = 0 };
enum { HM_NONE = 0, HM_ROPE = 1, HM_MULXY = 2 };

typedef unsigned long long u64;

// ---------------- packed f32x2 helpers ----------------
__device__ __forceinline__ void ffma2(u64& d, u64 a, u64 b) {
    asm("fma.rn.f32x2 %0, %1, %2, %0;" : "+l"(d) : "l"(a), "l"(b));
}
__device__ __forceinline__ u64 dup2(float x) {
    u64 r;
    asm("mov.b64 %0, {%1, %1};" : "=l"(r) : "r"(__float_as_uint(x)));
    return r;
}
__device__ __forceinline__ void unpack2(u64 v, float& lo, float& hi) {
    unsigned a, b;
    asm("mov.b64 {%0, %1}, %2;" : "=r"(a), "=r"(b) : "l"(v));
    lo = __uint_as_float(a); hi = __uint_as_float(b);
}

// ---------------- fp16 bit helpers ----------------
__device__ __forceinline__ unsigned short f2h(float x) {
    unsigned short r;
    asm("cvt.rn.f16.f32 %0, %1;" : "=h"(r) : "f"(x));
    return r;
}
__device__ __forceinline__ float h2f(unsigned short h) {
    float r;
    asm("cvt.f32.f16 %0, %1;" : "=f"(r) : "h"(h));
    return r;
}
__device__ __forceinline__ unsigned pack_hl_h(float a, float b,
                                              unsigned short& la, unsigned short& lb) {
    unsigned short ha = f2h(a), hb = f2h(b);
    la = f2h(a - h2f(ha));
    lb = f2h(b - h2f(hb));
    return (unsigned)ha | ((unsigned)hb << 16);
}

// ---------------- warp-MMA helpers ----------------
__device__ __forceinline__ uint32_t smem_to_u32(const void* smem_ptr) {
    uint32_t addr;
    asm("{ .reg .u64 tmp; cvta.to.shared.u64 tmp, %1; cvt.u32.u64 %0, tmp; }"
        : "=r"(addr) : "l"(smem_ptr));
    return addr;
}
__device__ __forceinline__ void ldsm4(uint32_t* r, uint32_t addr) {
    asm volatile("ldmatrix.sync.aligned.m8n8.x4.shared.b16 {%0,%1,%2,%3}, [%4];"
        : "=r"(r[0]), "=r"(r[1]), "=r"(r[2]), "=r"(r[3]) : "r"(addr));
}
__device__ __forceinline__ void ldsm4t(uint32_t* r, uint32_t addr) {
    asm volatile("ldmatrix.sync.aligned.m8n8.x4.trans.shared.b16 {%0,%1,%2,%3}, [%4];"
        : "=r"(r[0]), "=r"(r[1]), "=r"(r[2]), "=r"(r[3]) : "r"(addr));
}
__device__ __forceinline__ void mma16816h(float* c, const uint32_t* a, const uint32_t* b) {
    asm volatile(
        "mma.sync.aligned.m16n8k16.row.col.f32.f16.f16.f32 "
        "{%0,%1,%2,%3}, {%4,%5,%6,%7}, {%8,%9}, {%0,%1,%2,%3};"
        : "+f"(c[0]), "+f"(c[1]), "+f"(c[2]), "+f"(c[3])
        : "r"(a[0]), "r"(a[1]), "r"(a[2]), "r"(a[3]), "r"(b[0]), "r"(b[1]));
}
#define CP_ASYNC16(dst, src) \
    asm volatile("cp.async.cg.shared.global [%0], [%1], 16;" :: "r"(dst), "l"(src))
#define CP_COMMIT() asm volatile("cp.async.commit_group;" ::: "memory")
#define CP_WAIT(n)  asm volatile("cp.async.wait_group %0;" :: "n"(n) : "memory")

__device__ __forceinline__ uint32_t sw64(uint32_t b)  { return b ^ ((b >> 3) & 0x30); }
__device__ __forceinline__ uint32_t sw128(uint32_t b) { return b ^ ((b >> 3) & 0x70); }
__device__ __forceinline__ uint32_t sw256(uint32_t b) { return b ^ ((b >> 4) & 0x70); }

// generic small-K config: K-chunk 32, 3 stages (Ah, Al, Bh) of 24KB, 2 CTAs/SM
#define H32_A    8192            // 128 rows x 64B
#define H32_B    8192            // 32 rows x 256B
#define H32_STG  24576
#define H32_SMEM (3 * H32_STG + 1024)

// scores config: fp16 1-pass hi*hi, Kc=64, 2 tiles/stage (A, B), 2 stages, 2 CTAs/SM
#define SC_T     16384           // 128 rows x 128B
#define SC_STG   (2 * SC_T)      // 32KB
#define SC_SMEM  (2 * SC_STG + 1024)

// ---------------- rope freq table init ----------------
__global__ void init_freq()
{
    int i = blockIdx.x * blockDim.x + threadIdx.x;
    if (i >= NN / 2) return;
    int n0 = i * 2;
    float a = (float)exp2(-(double)n0 / 512.0);
    g_fr[i] = a / TWO_PI_F;
}

// ================= HMMA scores kernel (fp16 1-pass) =================
// scores[h] = mask .* (QR @ QR^T); QR fp16; acc = q_a * q_b (1 MMA pass, fp32 accum)
__global__ void __launch_bounds__(256, 2)
scores_hmma(const unsigned short* __restrict__ qh,
            unsigned short* __restrict__ sch,
            unsigned short* __restrict__ scl)
{
    const int br = blockIdx.y;
    const int bc = blockIdx.x;
    const int h  = blockIdx.z;
    if (bc > br) return;

    extern __shared__ char dsm[];
    const int tid  = threadIdx.x;
    const int wid  = tid >> 5;
    const int lane = tid & 31;
    const int wr   = wid & 3;
    const int wc   = wid >> 2;
    const int row0 = br * 128;
    const int col0 = bc * 128;

    const uint32_t raw = smem_to_u32(dsm);
    const uint32_t sb  = (raw + 1023u) & ~1023u;

    const size_t hb = (size_t)h * TT * NN;
    const unsigned short* srcs[2];
    srcs[0] = qh + hb + (size_t)row0 * NN;
    srcs[1] = qh + hb + (size_t)col0 * NN;

    float acc[2][8][4];
#pragma unroll
    for (int mi = 0; mi < 2; mi++)
#pragma unroll
        for (int ni = 0; ni < 8; ni++)
#pragma unroll
            for (int q = 0; q < 4; q++) acc[mi][ni][q] = 0.f;

    const int NITER = NN / 64;

    auto load_stage = [&](int st, int kc0) {
        const uint32_t stg = sb + st * SC_STG;
#pragma unroll
        for (int t2 = 0; t2 < 2; t2++) {
            const unsigned short* src = srcs[t2] + kc0;
            const uint32_t tb = stg + t2 * SC_T;
#pragma unroll
            for (int i = 0; i < 4; i++) {
                int idx = i * 256 + tid;
                int r = idx >> 3;
                int c = idx & 7;
                CP_ASYNC16(tb + sw128(r * 128 + c * 16), src + (size_t)r * NN + c * 8);
            }
        }
    };

    load_stage(0, 0);
    CP_COMMIT();

    for (int it = 0; it < NITER; it++) {
        CP_WAIT(0);
        __syncthreads();
        if (it + 1 < NITER) {
            load_stage((it + 1) & 1, (it + 1) * 64);
            CP_COMMIT();
        }

        const uint32_t stg = sb + (it & 1) * SC_STG;
#pragma unroll
        for (int ks = 0; ks < 4; ks++) {
            const int lrow  = lane & 15;
            const int chunk = ks * 2 + (lane >> 4);

            uint32_t ah[2][4];
#pragma unroll
            for (int mi = 0; mi < 2; mi++) {
                int row = wr * 32 + mi * 16 + lrow;
                uint32_t off = sw128(row * 128 + chunk * 16);
                ldsm4(ah[mi], stg + 0 * SC_T + off);
            }

#pragma unroll
            for (int ng = 0; ng < 4; ng++) {
                int row = wc * 64 + ng * 16 + lrow;
                uint32_t off = sw128(row * 128 + chunk * 16);
                uint32_t t0[4];
                ldsm4(t0, stg + 1 * SC_T + off);
                uint32_t bh0[2], bh1[2];
                bh0[0] = t0[0]; bh0[1] = t0[2];
                bh1[0] = t0[1]; bh1[1] = t0[3];
#pragma unroll
                for (int mi = 0; mi < 2; mi++) {
                    mma16816h(acc[mi][2 * ng],     ah[mi], bh0);
                    mma16816h(acc[mi][2 * ng + 1], ah[mi], bh1);
                }
            }
        }
    }

    // epilogue: strictly-lower mask, write scores as fp16 hi/lo split
    unsigned short* dh = sch + (size_t)h * TT * TT;
    unsigned short* dl = scl + (size_t)h * TT * TT;
    const int rb = row0 + wr * 32;
    const int cb = col0 + wc * 64;
#pragma unroll
    for (int mi = 0; mi < 2; mi++) {
#pragma unroll
        for (int ni = 0; ni < 8; ni++) {
            int r = rb + mi * 16 + (lane >> 2);
            int s = cb + ni * 8 + (lane & 3) * 2;
#pragma unroll
            for (int half = 0; half < 2; half++) {
                int rr = r + half * 8;
                float v0 = (rr > s)     ? acc[mi][ni][half * 2 + 0] : 0.f;
                float v1 = (rr > s + 1) ? acc[mi][ni][half * 2 + 1] : 0.f;
                unsigned short l0, l1;
                unsigned hv = pack_hl_h(v0, v1, l0, l1);
                size_t base = (size_t)rr * TT + s;
                *(unsigned*)(dh + base) = hv;
                *(unsigned*)(dl + base) = (unsigned)l0 | ((unsigned)l1 << 16);
            }
        }
    }
}

// ================= generic HMMA GEMM (fp16 2-pass, Kc=32, 3-stage, 2 CTAs/SM) ==
template <int HM, int CAUSAL>
__global__ void __launch_bounds__(256, 2)
hmma_gemm(const unsigned short* __restrict__ Ah, const unsigned short* __restrict__ Al,
          const unsigned short* __restrict__ Bh,
          float* __restrict__ C, int K, int lda, int ldb, int ldc,
          long offAz, long offBz, long offCz)
{
    const int z = blockIdx.z;
    Ah += (long)z * offAz;
    Al += (long)z * offAz;
    Bh += (long)z * offBz;
    if (HM == HM_NONE) C += (long)z * offCz;

    extern __shared__ char dsm[];
    const int tid  = threadIdx.x;
    const int wid  = tid >> 5;
    const int lane = tid & 31;
    const int wr   = wid & 3;
    const int wc   = wid >> 2;
    const int row0 = blockIdx.y * 128;
    const int col0 = blockIdx.x * 128;

    const uint32_t raw = smem_to_u32(dsm);
    const uint32_t sb  = (raw + 1023u) & ~1023u;

    const unsigned short* A0 = Ah + (size_t)row0 * lda;
    const unsigned short* A1 = Al + (size_t)row0 * lda;

    float acc[2][8][4];
#pragma unroll
    for (int mi = 0; mi < 2; mi++)
#pragma unroll
        for (int ni = 0; ni < 8; ni++)
#pragma unroll
            for (int q = 0; q < 4; q++) acc[mi][ni][q] = 0.f;

    const int NITER = (CAUSAL ? (row0 + 128) : K) / 32;

    auto load_stage = [&](int st, int k0) {
        const uint32_t stg = sb + st * H32_STG;
#pragma unroll
        for (int i = 0; i < 2; i++) {
            int idx = i * 256 + tid;
            int r = idx >> 2;
            int c = idx & 3;
            uint32_t off = sw64(r * 64 + c * 16);
            CP_ASYNC16(stg + off,          A0 + (size_t)r * lda + k0 + c * 8);
            CP_ASYNC16(stg + H32_A + off,  A1 + (size_t)r * lda + k0 + c * 8);
        }
#pragma unroll
        for (int i = 0; i < 2; i++) {
            int idx = i * 256 + tid;
            int r = idx >> 4;
            int c = idx & 15;
            uint32_t off = sw256(r * 256 + c * 16);
            CP_ASYNC16(stg + 2 * H32_A + off, Bh + (size_t)(k0 + r) * ldb + col0 + c * 8);
        }
    };

    load_stage(0, 0);
    CP_COMMIT();
    if (NITER > 1) { load_stage(1, 32); CP_COMMIT(); }

    for (int it = 0; it < NITER; it++) {
        if (it + 1 < NITER) { CP_WAIT(1); }
        else                { CP_WAIT(0); }
        __syncthreads();
        if (it + 2 < NITER) {
            load_stage((it + 2) % 3, (it + 2) * 32);
            CP_COMMIT();
        }

        const uint32_t stg = sb + (it % 3) * H32_STG;
#pragma unroll
        for (int ks = 0; ks < 2; ks++) {
            const int lrow = lane & 15;

            uint32_t ah[2][4], al[2][4];
#pragma unroll
            for (int mi = 0; mi < 2; mi++) {
                int row = wr * 32 + mi * 16 + lrow;
                uint32_t off = sw64(row * 64 + (ks * 2 + (lane >> 4)) * 16);
                ldsm4(ah[mi], stg + off);
                ldsm4(al[mi], stg + H32_A + off);
            }

#pragma unroll
            for (int ng = 0; ng < 4; ng++) {
                int kk = ks * 16 + lrow;
                int nc = wc * 64 + ng * 16 + (lane >> 4) * 8;
                uint32_t off = sw256(kk * 256 + nc * 2);
                uint32_t t0[4];
                ldsm4t(t0, stg + 2 * H32_A + off);
                uint32_t bh0[2], bh1[2];
                bh0[0] = t0[0]; bh0[1] = t0[1];
                bh1[0] = t0[2]; bh1[1] = t0[3];
#pragma unroll
                for (int mi = 0; mi < 2; mi++) {
                    mma16816h(acc[mi][2 * ng],     ah[mi], bh0);
                    mma16816h(acc[mi][2 * ng],     al[mi], bh0);
                    mma16816h(acc[mi][2 * ng + 1], ah[mi], bh1);
                    mma16816h(acc[mi][2 * ng + 1], al[mi], bh1);
                }
            }
        }
    }

    // ---------------- epilogues ----------------
    const int rb = row0 + wr * 32;
    const int cb = col0 + wc * 64;

    if (HM == HM_NONE) {
#pragma unroll
        for (int mi = 0; mi < 2; mi++) {
#pragma unroll
            for (int ni = 0; ni < 8; ni++) {
                int r = rb + mi * 16 + (lane >> 2);
                int s = cb + ni * 8 + (lane & 3) * 2;
                *(float2*)(C + (size_t)r * ldc + s) =
                    make_float2(acc[mi][ni][0], acc[mi][ni][1]);
                *(float2*)(C + (size_t)(r + 8) * ldc + s) =
                    make_float2(acc[mi][ni][2], acc[mi][ni][3]);
            }
        }
    } else if (HM == HM_ROPE) {
        // write x_sparse fp16 and QR fp16 (hi only)
        unsigned short* Xs = g_xsh + (size_t)z * TT * NN;
        unsigned short* Qh = g_qrh + (size_t)z * TT * NN;
#pragma unroll
        for (int ni = 0; ni < 8; ni++) {
            int n0 = cb + ni * 8 + (lane & 3) * 2;
            float fr = g_fr[n0 >> 1];
#pragma unroll
            for (int mi = 0; mi < 2; mi++) {
                int rbase = rb + mi * 16 + (lane >> 2);
#pragma unroll
                for (int half = 0; half < 2; half++) {
                    int r = rbase + half * 8;
                    float v0 = fmaxf(acc[mi][ni][half * 2 + 0], 0.f);
                    float v1 = fmaxf(acc[mi][ni][half * 2 + 1], 0.f);
                    size_t base = (size_t)r * NN + n0;
                    *(unsigned*)(Xs + base) = (unsigned)f2h(v0) | ((unsigned)f2h(v1) << 16);
                    float ph   = (float)r * fr;
                    float frac = ph - floorf(ph);
                    float ang  = frac * TWO_PI_F;
                    float si, co;
                    __sincosf(ang, &si, &co);
                    float q0 = v0 * co - v1 * si;
                    float q1 = v1 * co + v0 * si;
                    *(unsigned*)(Qh + base) = (unsigned)f2h(q0) | ((unsigned)f2h(q1) << 16);
                }
            }
        }
    } else if (HM == HM_MULXY) {
        const unsigned short* xsrc = g_xsh + (size_t)z * TT * NN;
        unsigned short* Xh = g_xyh;
        unsigned short* Xl = g_xyl;
        const int colz = z * NN;
#pragma unroll
        for (int mi = 0; mi < 2; mi++) {
#pragma unroll
            for (int ni = 0; ni < 8; ni++) {
                int n0 = cb + ni * 8 + (lane & 3) * 2;
                int rbase = rb + mi * 16 + (lane >> 2);
#pragma unroll
                for (int half = 0; half < 2; half++) {
                    int r = rbase + half * 8;
                    unsigned xv = *(const unsigned*)(xsrc + (size_t)r * NN + n0);
                    float x0 = h2f((unsigned short)(xv & 0xFFFFu));
                    float x1 = h2f((unsigned short)(xv >> 16));
                    float v0 = fmaxf(acc[mi][ni][half * 2 + 0], 0.f) * x0;
                    float v1 = fmaxf(acc[mi][ni][half * 2 + 1], 0.f) * x1;
                    unsigned short l0, l1;
                    unsigned hv = pack_hl_h(v0, v1, l0, l1);
                    size_t base = (size_t)r * (NHH * NN) + colz + n0;
                    *(unsigned*)(Xh + base) = hv;
                    *(unsigned*)(Xl + base) = (unsigned)l0 | ((unsigned)l1 << 16);
                }
            }
        }
    }
}

// ---------------- weight conversion (fp16 hi only for B operands) -------------
__global__ void cvt_h(const float* __restrict__ src,
                      unsigned short* __restrict__ h, long n)
{
    long i = ((long)blockIdx.x * blockDim.x + threadIdx.x) * 4;
    if (i >= n) return;
    float4 v = *(const float4*)(src + i);
    uint2 hv;
    hv.x = (unsigned)f2h(v.x) | ((unsigned)f2h(v.y) << 16);
    hv.y = (unsigned)f2h(v.z) | ((unsigned)f2h(v.w) << 16);
    *(uint2*)(h + i) = hv;
}

// ---------------- block reduction over 256 threads ----------------
__device__ __forceinline__ float blk_sum(float v, float* sb) {
    int tid = threadIdx.x;
#pragma unroll
    for (int o = 16; o > 0; o >>= 1) v += __shfl_down_sync(0xffffffffu, v, o);
    if ((tid & 31) == 0) sb[tid >> 5] = v;
    __syncthreads();
    if (tid < 32) {
        float w = (tid < 8) ? sb[tid] : 0.f;
#pragma unroll
        for (int o = 4; o > 0; o >>= 1) w += __shfl_down_sync(0xffffffffu, w, o);
        if (tid == 0) sb[0] = w;
    }
    __syncthreads();
    float r = sb[0];
    __syncthreads();
    return r;
}

// ---------------- fp32 SGEMM (kept for lm_head) ----------------
template <int MODE>
__global__ void __launch_bounds__(256)
sgemm_kernel(const float* __restrict__ A, const float* __restrict__ B,
             float* __restrict__ C, int K,
             int lda, int ldb, int ldc,
             long offAz, long offBz, long offCz)
{
    const int z = blockIdx.z;
    A += (long)z * offAz;
    B += (long)z * offBz;
    C += (long)z * offCz;

    const int br = blockIdx.y, bc = blockIdx.x;
    const int row0 = br * 128, col0 = bc * 128;
    const int tid = threadIdx.x;
    const int tx = tid & 15, ty = tid >> 4;

    __shared__ __align__(16) float As[8][132];
    __shared__ __align__(16) float Bs[8][132];

    u64 acc2[8][4];
#pragma unroll
    for (int i = 0; i < 8; i++) {
#pragma unroll
        for (int j = 0; j < 4; j++) acc2[i][j] = 0ull;
    }

    const int ar = tid >> 1;
    const int ak = (tid & 1) * 4;
    const int bkr = tid >> 5;
    const int bcc = (tid & 31) * 4;

    const float* Ap = A + (long)(row0 + ar) * lda + ak;
    const float* Bp = B + (long)bkr * ldb + col0 + bcc;

    float4 a4 = *(const float4*)Ap;  Ap += 8;
    float4 b4 = *(const float4*)Bp;  Bp += (long)8 * ldb;

    for (int k0 = 0; k0 < K; k0 += 8) {
        As[ak + 0][ar] = a4.x; As[ak + 1][ar] = a4.y;
        As[ak + 2][ar] = a4.z; As[ak + 3][ar] = a4.w;
        Bs[bkr][bcc + 0] = b4.x; Bs[bkr][bcc + 1] = b4.y;
        Bs[bkr][bcc + 2] = b4.z; Bs[bkr][bcc + 3] = b4.w;
        __syncthreads();

        if (k0 + 8 < K) {
            a4 = *(const float4*)Ap;  Ap += 8;
            b4 = *(const float4*)Bp;  Bp += (long)8 * ldb;
        }

#pragma unroll
        for (int k = 0; k < 8; k++) {
            float a[8];
            *(float4*)&a[0] = *(const float4*)&As[k][ty * 8];
            *(float4*)&a[4] = *(const float4*)&As[k][ty * 8 + 4];
            ulonglong2 bu0 = *(const ulonglong2*)&Bs[k][tx * 8];
            ulonglong2 bu1 = *(const ulonglong2*)&Bs[k][tx * 8 + 4];
            u64 b2[4];
            b2[0] = bu0.x; b2[1] = bu0.y; b2[2] = bu1.x; b2[3] = bu1.y;
            u64 a2[8];
#pragma unroll
            for (int i = 0; i < 8; i++) a2[i] = dup2(a[i]);
#pragma unroll
            for (int i = 0; i < 8; i++) {
#pragma unroll
                for (int j = 0; j < 4; j++) ffma2(acc2[i][j], a2[i], b2[j]);
            }
        }
        __syncthreads();
    }

    float acc[8][8];
#pragma unroll
    for (int i = 0; i < 8; i++) {
#pragma unroll
        for (int j = 0; j < 4; j++) unpack2(acc2[i][j], acc[i][2 * j], acc[i][2 * j + 1]);
    }

#pragma unroll
    for (int i = 0; i < 8; i++) {
        long base = (long)(row0 + ty * 8 + i) * ldc + col0 + tx * 8;
        *(float4*)(C + base)     = make_float4(acc[i][0], acc[i][1], acc[i][2], acc[i][3]);
        *(float4*)(C + base + 4) = make_float4(acc[i][4], acc[i][5], acc[i][6], acc[i][7]);
    }
}

// ---------------- small elementwise kernels ----------------
__global__ void embed_ln_kernel(const int* __restrict__ idx,
                                const float* __restrict__ embed)
{
    __shared__ float sb[8];
    int t = blockIdx.x, d = threadIdx.x;
    float v   = embed[idx[t] * DD + d];
    float mu  = blk_sum(v, sb) * (1.f / DD);
    float dv  = v - mu;
    float var = blk_sum(dv * dv, sb) * (1.f / DD);
    float o = dv / sqrtf(var + LNEPS);
    g_x[t * DD + d] = o;
    unsigned short hh = f2h(o);
    g_xh[t * DD + d] = hh;
    g_xl[t * DD + d] = f2h(o - h2f(hh));
}

__global__ void ln_rows_kernel(float* __restrict__ buf)
{
    __shared__ float sb[8];
    long r = blockIdx.x;
    int  d = threadIdx.x;
    float v   = buf[r * DD + d];
    float mu  = blk_sum(v, sb) * (1.f / DD);
    float dv  = v - mu;
    float var = blk_sum(dv * dv, sb) * (1.f / DD);
    float o = dv / sqrtf(var + LNEPS);
    buf[r * DD + d] = o;
    unsigned short hh = f2h(o);
    g_ykvh[r * DD + d] = hh;
    g_ykvl[r * DD + d] = f2h(o - h2f(hh));
}

__global__ void mlp_finish_kernel()
{
    __shared__ float sb[8];
    int t = blockIdx.x, d = threadIdx.x;
    float s = 0.f;
#pragma unroll
    for (int kz = 0; kz < SPLITK; kz++)
        s += g_part[(size_t)kz * TT * DD + t * DD + d];

    float mu  = blk_sum(s, sb) * (1.f / DD);
    float dv  = s - mu;
    float var = blk_sum(dv * dv, sb) * (1.f / DD);
    float a   = dv / sqrtf(var + LNEPS);

    float b = g_x[t * DD + d] + a;
    mu  = blk_sum(b, sb) * (1.f / DD);
    dv  = b - mu;
    var = blk_sum(dv * dv, sb) * (1.f / DD);
    float o = dv / sqrtf(var + LNEPS);
    g_x[t * DD + d] = o;
    unsigned short hh = f2h(o);
    g_xh[t * DD + d] = hh;
    g_xl[t * DD + d] = f2h(o - h2f(hh));
}

// ---------------- launch ----------------
extern "C" void kernel_launch(void* const* d_in, const int* in_sizes, int n_in,
                              void* d_out, int out_size)
{
    (void)in_sizes; (void)n_in; (void)out_size;
    const int*   idx       = (const int*)d_in[0];
    const float* embed     = (const float*)d_in[1];
    const float* encoder   = (const float*)d_in[2];
    const float* encoder_v = (const float*)d_in[3];
    const float* decoder   = (const float*)d_in[4];
    const float* lm_head   = (const float*)d_in[5];
    float*       out       = (float*)d_out;

    float* x = 0; float* ykv = 0; float* part = 0;
    unsigned short *sch = 0, *scl = 0;
    unsigned short *qrh = 0, *xyh = 0, *xyl = 0;
    unsigned short *xh = 0, *xl = 0, *ykvh = 0, *ykvl = 0;
    unsigned short *ench = 0, *encvh = 0, *dech = 0;
    cudaGetSymbolAddress((void**)&x,      g_x);
    cudaGetSymbolAddress((void**)&sch,    g_sch);
    cudaGetSymbolAddress((void**)&scl,    g_scl);
    cudaGetSymbolAddress((void**)&ykv,    g_ykv);
    cudaGetSymbolAddress((void**)&part,   g_part);
    cudaGetSymbolAddress((void**)&qrh,    g_qrh);
    cudaGetSymbolAddress((void**)&xyh,    g_xyh);
    cudaGetSymbolAddress((void**)&xyl,    g_xyl);
    cudaGetSymbolAddress((void**)&xh,     g_xh);
    cudaGetSymbolAddress((void**)&xl,     g_xl);
    cudaGetSymbolAddress((void**)&ykvh,   g_ykvh);
    cudaGetSymbolAddress((void**)&ykvl,   g_ykvl);
    cudaGetSymbolAddress((void**)&ench,   g_ench);
    cudaGetSymbolAddress((void**)&encvh,  g_encvh);
    cudaGetSymbolAddress((void**)&dech,   g_dech);

    cudaFuncSetAttribute(scores_hmma, cudaFuncAttributeMaxDynamicSharedMemorySize, SC_SMEM);
    cudaFuncSetAttribute(hmma_gemm<HM_NONE, 0>,  cudaFuncAttributeMaxDynamicSharedMemorySize, H32_SMEM);
    cudaFuncSetAttribute(hmma_gemm<HM_NONE, 1>,  cudaFuncAttributeMaxDynamicSharedMemorySize, H32_SMEM);
    cudaFuncSetAttribute(hmma_gemm<HM_ROPE, 0>,  cudaFuncAttributeMaxDynamicSharedMemorySize, H32_SMEM);
    cudaFuncSetAttribute(hmma_gemm<HM_MULXY, 0>, cudaFuncAttributeMaxDynamicSharedMemorySize, H32_SMEM);

    const long WN = (long)NHH * DD * NN;
    init_freq<<<(NN / 2 + 255) / 256, 256>>>();
    cvt_h<<<(int)(WN / 4 / 256), 256>>>(encoder,   ench,  WN);
    cvt_h<<<(int)(WN / 4 / 256), 256>>>(encoder_v, encvh, WN);
    cvt_h<<<(int)(WN / 4 / 256), 256>>>(decoder,   dech,  WN);

    embed_ln_kernel<<<TT, 256>>>(idx, embed);

    for (int l = 0; l < 2; l++) {
        // x_sparse fp16 -> g_xsh; QR fp16 -> g_qrh  (C unused)
        hmma_gemm<HM_ROPE, 0><<<dim3(NN / 128, TT / 128, NHH), 256, H32_SMEM>>>(
            xh, xl, ench, part, DD, DD, NN, NN,
            0L, (long)DD * NN, 0L);

        // scores = mask .* (QR @ QR^T) — fp16 1-pass -> fp16 hi/lo out
        scores_hmma<<<dim3(TT / 128, TT / 128, NHH), 256, SC_SMEM>>>(qrh, sch, scl);

        // yKV = scores @ x — causal-bounded fp16 2-pass (scores hi+lo)
        hmma_gemm<HM_NONE, 1><<<dim3(DD / 128, TT / 128, NHH), 256, H32_SMEM>>>(
            sch, scl, xh, ykv, TT, TT, DD, DD,
            (long)TT * TT, 0L, (long)TT * DD);

        ln_rows_kernel<<<NHH * TT, 256>>>(ykv);

        // xy = relu(yKV @ encoder_v) * x_sparse -> fp16 hi/lo  (C unused)
        hmma_gemm<HM_MULXY, 0><<<dim3(NN / 128, TT / 128, NHH), 256, H32_SMEM>>>(
            ykvh, ykvl, encvh, part, DD, DD, NN, 0,
            (long)TT * DD, (long)DD * NN, 0L);

        // yMLP partials = xy @ decoder (split-K 16)
        hmma_gemm<HM_NONE, 0><<<dim3(DD / 128, TT / 128, SPLITK), 256, H32_SMEM>>>(
            xyh, xyl, dech, part, KSPL, NHH * NN, DD, DD,
            (long)KSPL, (long)KSPL * DD, (long)TT * DD);

        mlp_finish_kernel<<<TT, 256>>>();
    }

    sgemm_kernel<EM_NONE><<<dim3(VOC / 128, TT / 128, 1), 256>>>(
        x, lm_head, out, DD, DD, VOC, VOC, 0L, 0L, 0L);
}

// round 16
// speedup vs baseline: 2.1155x; 1.0360x over previous
#include <cuda_runtime.h>
#include <math.h>
#include <stdint.h>

// ---------------- problem constants ----------------
#define NHH   4
#define DD    256
#define NN    8192
#define TT    2048
#define VOC   256
#define SPLITK 16
#define KSPL  2048              // NHH*NN/SPLITK
#define LNEPS 1e-5f
#define TWO_PI_F 6.28318530717958647692f

// ---------------- scratch (static device globals) ----
__device__ float g_x[TT * DD];
__device__ unsigned short g_xh[TT * DD];
__device__ unsigned short g_xl[TT * DD];
__device__ unsigned short g_xsh[(size_t)NHH * TT * NN];   // x_sparse (fp16)
__device__ unsigned short g_sch[(size_t)NHH * TT * TT];   // scores (fp16)
__device__ float g_ykv[(size_t)NHH * TT * DD];
__device__ unsigned short g_ykvh[(size_t)NHH * TT * DD];
__device__ unsigned short g_ykvl[(size_t)NHH * TT * DD];
__device__ float g_part[(size_t)SPLITK * TT * DD];
__device__ unsigned short g_qrh[(size_t)NHH * TT * NN];   // QR (fp16)
__device__ unsigned short g_xyh[(size_t)NHH * TT * NN];
__device__ unsigned short g_xyl[(size_t)NHH * TT * NN];
__device__ unsigned short g_ench[(size_t)NHH * DD * NN];
__device__ unsigned short g_encvh[(size_t)NHH * DD * NN];
__device__ unsigned short g_dech[(size_t)NHH * NN * DD];
__device__ float g_fr[NN / 2];                            // rope freq / 2pi per even n

enum { EM_NONE = 0 };
enum { HM_NONE = 0, HM_ROPE = 1, HM_MULXY = 2 };

typedef unsigned long long u64;

// ---------------- packed f32x2 helpers ----------------
__device__ __forceinline__ void ffma2(u64& d, u64 a, u64 b) {
    asm("fma.rn.f32x2 %0, %1, %2, %0;" : "+l"(d) : "l"(a), "l"(b));
}
__device__ __forceinline__ u64 dup2(float x) {
    u64 r;
    asm("mov.b64 %0, {%1, %1};" : "=l"(r) : "r"(__float_as_uint(x)));
    return r;
}
__device__ __forceinline__ void unpack2(u64 v, float& lo, float& hi) {
    unsigned a, b;
    asm("mov.b64 {%0, %1}, %2;" : "=r"(a), "=r"(b) : "l"(v));
    lo = __uint_as_float(a); hi = __uint_as_float(b);
}

// ---------------- fp16 bit helpers ----------------
__device__ __forceinline__ unsigned short f2h(float x) {
    unsigned short r;
    asm("cvt.rn.f16.f32 %0, %1;" : "=h"(r) : "f"(x));
    return r;
}
__device__ __forceinline__ float h2f(unsigned short h) {
    float r;
    asm("cvt.f32.f16 %0, %1;" : "=f"(r) : "h"(h));
    return r;
}
__device__ __forceinline__ unsigned pack_hl_h(float a, float b,
                                              unsigned short& la, unsigned short& lb) {
    unsigned short ha = f2h(a), hb = f2h(b);
    la = f2h(a - h2f(ha));
    lb = f2h(b - h2f(hb));
    return (unsigned)ha | ((unsigned)hb << 16);
}

// ---------------- warp-MMA helpers ----------------
__device__ __forceinline__ uint32_t smem_to_u32(const void* smem_ptr) {
    uint32_t addr;
    asm("{ .reg .u64 tmp; cvta.to.shared.u64 tmp, %1; cvt.u32.u64 %0, tmp; }"
        : "=r"(addr) : "l"(smem_ptr));
    return addr;
}
__device__ __forceinline__ void ldsm4(uint32_t* r, uint32_t addr) {
    asm volatile("ldmatrix.sync.aligned.m8n8.x4.shared.b16 {%0,%1,%2,%3}, [%4];"
        : "=r"(r[0]), "=r"(r[1]), "=r"(r[2]), "=r"(r[3]) : "r"(addr));
}
__device__ __forceinline__ void ldsm4t(uint32_t* r, uint32_t addr) {
    asm volatile("ldmatrix.sync.aligned.m8n8.x4.trans.shared.b16 {%0,%1,%2,%3}, [%4];"
        : "=r"(r[0]), "=r"(r[1]), "=r"(r[2]), "=r"(r[3]) : "r"(addr));
}
__device__ __forceinline__ void mma16816h(float* c, const uint32_t* a, const uint32_t* b) {
    asm volatile(
        "mma.sync.aligned.m16n8k16.row.col.f32.f16.f16.f32 "
        "{%0,%1,%2,%3}, {%4,%5,%6,%7}, {%8,%9}, {%0,%1,%2,%3};"
        : "+f"(c[0]), "+f"(c[1]), "+f"(c[2]), "+f"(c[3])
        : "r"(a[0]), "r"(a[1]), "r"(a[2]), "r"(a[3]), "r"(b[0]), "r"(b[1]));
}
#define CP_ASYNC16(dst, src) \
    asm volatile("cp.async.cg.shared.global [%0], [%1], 16;" :: "r"(dst), "l"(src))
#define CP_COMMIT() asm volatile("cp.async.commit_group;" ::: "memory")
#define CP_WAIT(n)  asm volatile("cp.async.wait_group %0;" :: "n"(n) : "memory")

__device__ __forceinline__ uint32_t sw64(uint32_t b)  { return b ^ ((b >> 3) & 0x30); }
__device__ __forceinline__ uint32_t sw128(uint32_t b) { return b ^ ((b >> 3) & 0x70); }
__device__ __forceinline__ uint32_t sw256(uint32_t b) { return b ^ ((b >> 4) & 0x70); }

// generic small-K config: K-chunk 32, 3 stages (A[, Al], B) of 24KB, 2 CTAs/SM
#define H32_A    8192            // 128 rows x 64B
#define H32_B    8192            // 32 rows x 256B
#define H32_STG  24576
#define H32_SMEM (3 * H32_STG + 1024)

// scores config: fp16 1-pass hi*hi, Kc=64, 2 tiles/stage (A, B), 2 stages, 2 CTAs/SM
#define SC_T     16384           // 128 rows x 128B
#define SC_STG   (2 * SC_T)      // 32KB
#define SC_SMEM  (2 * SC_STG + 1024)

// ---------------- rope freq table init ----------------
__global__ void init_freq()
{
    int i = blockIdx.x * blockDim.x + threadIdx.x;
    if (i >= NN / 2) return;
    int n0 = i * 2;
    float a = (float)exp2(-(double)n0 / 512.0);
    g_fr[i] = a / TWO_PI_F;
}

// ================= HMMA scores kernel (fp16 1-pass, fp16 out) =================
__global__ void __launch_bounds__(256, 2)
scores_hmma(const unsigned short* __restrict__ qh,
            unsigned short* __restrict__ sch)
{
    const int br = blockIdx.y;
    const int bc = blockIdx.x;
    const int h  = blockIdx.z;
    if (bc > br) return;

    extern __shared__ char dsm[];
    const int tid  = threadIdx.x;
    const int wid  = tid >> 5;
    const int lane = tid & 31;
    const int wr   = wid & 3;
    const int wc   = wid >> 2;
    const int row0 = br * 128;
    const int col0 = bc * 128;

    const uint32_t raw = smem_to_u32(dsm);
    const uint32_t sb  = (raw + 1023u) & ~1023u;

    const size_t hb = (size_t)h * TT * NN;
    const unsigned short* srcs[2];
    srcs[0] = qh + hb + (size_t)row0 * NN;
    srcs[1] = qh + hb + (size_t)col0 * NN;

    float acc[2][8][4];
#pragma unroll
    for (int mi = 0; mi < 2; mi++)
#pragma unroll
        for (int ni = 0; ni < 8; ni++)
#pragma unroll
            for (int q = 0; q < 4; q++) acc[mi][ni][q] = 0.f;

    const int NITER = NN / 64;

    auto load_stage = [&](int st, int kc0) {
        const uint32_t stg = sb + st * SC_STG;
#pragma unroll
        for (int t2 = 0; t2 < 2; t2++) {
            const unsigned short* src = srcs[t2] + kc0;
            const uint32_t tb = stg + t2 * SC_T;
#pragma unroll
            for (int i = 0; i < 4; i++) {
                int idx = i * 256 + tid;
                int r = idx >> 3;
                int c = idx & 7;
                CP_ASYNC16(tb + sw128(r * 128 + c * 16), src + (size_t)r * NN + c * 8);
            }
        }
    };

    load_stage(0, 0);
    CP_COMMIT();

    for (int it = 0; it < NITER; it++) {
        CP_WAIT(0);
        __syncthreads();
        if (it + 1 < NITER) {
            load_stage((it + 1) & 1, (it + 1) * 64);
            CP_COMMIT();
        }

        const uint32_t stg = sb + (it & 1) * SC_STG;
#pragma unroll
        for (int ks = 0; ks < 4; ks++) {
            const int lrow  = lane & 15;
            const int chunk = ks * 2 + (lane >> 4);

            uint32_t ah[2][4];
#pragma unroll
            for (int mi = 0; mi < 2; mi++) {
                int row = wr * 32 + mi * 16 + lrow;
                uint32_t off = sw128(row * 128 + chunk * 16);
                ldsm4(ah[mi], stg + 0 * SC_T + off);
            }

#pragma unroll
            for (int ng = 0; ng < 4; ng++) {
                int row = wc * 64 + ng * 16 + lrow;
                uint32_t off = sw128(row * 128 + chunk * 16);
                uint32_t t0[4];
                ldsm4(t0, stg + 1 * SC_T + off);
                uint32_t bh0[2], bh1[2];
                bh0[0] = t0[0]; bh0[1] = t0[2];
                bh1[0] = t0[1]; bh1[1] = t0[3];
#pragma unroll
                for (int mi = 0; mi < 2; mi++) {
                    mma16816h(acc[mi][2 * ng],     ah[mi], bh0);
                    mma16816h(acc[mi][2 * ng + 1], ah[mi], bh1);
                }
            }
        }
    }

    // epilogue: strictly-lower mask, write scores as fp16 (single level)
    unsigned short* dh = sch + (size_t)h * TT * TT;
    const int rb = row0 + wr * 32;
    const int cb = col0 + wc * 64;
#pragma unroll
    for (int mi = 0; mi < 2; mi++) {
#pragma unroll
        for (int ni = 0; ni < 8; ni++) {
            int r = rb + mi * 16 + (lane >> 2);
            int s = cb + ni * 8 + (lane & 3) * 2;
#pragma unroll
            for (int half = 0; half < 2; half++) {
                int rr = r + half * 8;
                float v0 = (rr > s)     ? acc[mi][ni][half * 2 + 0] : 0.f;
                float v1 = (rr > s + 1) ? acc[mi][ni][half * 2 + 1] : 0.f;
                *(unsigned*)(dh + (size_t)rr * TT + s) =
                    (unsigned)f2h(v0) | ((unsigned)f2h(v1) << 16);
            }
        }
    }
}

// ================= generic HMMA GEMM (Kc=32, 3-stage, 2 CTAs/SM) ==============
// A [M,K] k-contig (64B rows, SW64); AP=2: acc=(Ah+Al)*Bh, AP=1: acc=Ah*Bh.
// B [K,N] n-contig (256B rows, SW256), single fp16 level.
template <int HM, int CAUSAL, int AP>
__global__ void __launch_bounds__(256, 2)
hmma_gemm(const unsigned short* __restrict__ Ah, const unsigned short* __restrict__ Al,
          const unsigned short* __restrict__ Bh,
          float* __restrict__ C, int K, int lda, int ldb, int ldc,
          long offAz, long offBz, long offCz)
{
    const int z = blockIdx.z;
    Ah += (long)z * offAz;
    if (AP == 2) Al += (long)z * offAz;
    Bh += (long)z * offBz;
    if (HM == HM_NONE) C += (long)z * offCz;

    extern __shared__ char dsm[];
    const int tid  = threadIdx.x;
    const int wid  = tid >> 5;
    const int lane = tid & 31;
    const int wr   = wid & 3;
    const int wc   = wid >> 2;
    const int row0 = blockIdx.y * 128;
    const int col0 = blockIdx.x * 128;

    const uint32_t raw = smem_to_u32(dsm);
    const uint32_t sb  = (raw + 1023u) & ~1023u;

    const unsigned short* A0 = Ah + (size_t)row0 * lda;
    const unsigned short* A1 = (AP == 2) ? (Al + (size_t)row0 * lda) : A0;

    float acc[2][8][4];
#pragma unroll
    for (int mi = 0; mi < 2; mi++)
#pragma unroll
        for (int ni = 0; ni < 8; ni++)
#pragma unroll
            for (int q = 0; q < 4; q++) acc[mi][ni][q] = 0.f;

    const int NITER = (CAUSAL ? (row0 + 128) : K) / 32;

    auto load_stage = [&](int st, int k0) {
        const uint32_t stg = sb + st * H32_STG;
#pragma unroll
        for (int i = 0; i < 2; i++) {
            int idx = i * 256 + tid;
            int r = idx >> 2;
            int c = idx & 3;
            uint32_t off = sw64(r * 64 + c * 16);
            CP_ASYNC16(stg + off, A0 + (size_t)r * lda + k0 + c * 8);
            if (AP == 2) CP_ASYNC16(stg + H32_A + off, A1 + (size_t)r * lda + k0 + c * 8);
        }
#pragma unroll
        for (int i = 0; i < 2; i++) {
            int idx = i * 256 + tid;
            int r = idx >> 4;
            int c = idx & 15;
            uint32_t off = sw256(r * 256 + c * 16);
            CP_ASYNC16(stg + 2 * H32_A + off, Bh + (size_t)(k0 + r) * ldb + col0 + c * 8);
        }
    };

    load_stage(0, 0);
    CP_COMMIT();
    if (NITER > 1) { load_stage(1, 32); CP_COMMIT(); }

    for (int it = 0; it < NITER; it++) {
        if (it + 1 < NITER) { CP_WAIT(1); }
        else                { CP_WAIT(0); }
        __syncthreads();
        if (it + 2 < NITER) {
            load_stage((it + 2) % 3, (it + 2) * 32);
            CP_COMMIT();
        }

        const uint32_t stg = sb + (it % 3) * H32_STG;
#pragma unroll
        for (int ks = 0; ks < 2; ks++) {
            const int lrow = lane & 15;

            uint32_t ah[2][4], al[2][4];
#pragma unroll
            for (int mi = 0; mi < 2; mi++) {
                int row = wr * 32 + mi * 16 + lrow;
                uint32_t off = sw64(row * 64 + (ks * 2 + (lane >> 4)) * 16);
                ldsm4(ah[mi], stg + off);
                if (AP == 2) ldsm4(al[mi], stg + H32_A + off);
            }

#pragma unroll
            for (int ng = 0; ng < 4; ng++) {
                int kk = ks * 16 + lrow;
                int nc = wc * 64 + ng * 16 + (lane >> 4) * 8;
                uint32_t off = sw256(kk * 256 + nc * 2);
                uint32_t t0[4];
                ldsm4t(t0, stg + 2 * H32_A + off);
                uint32_t bh0[2], bh1[2];
                bh0[0] = t0[0]; bh0[1] = t0[1];
                bh1[0] = t0[2]; bh1[1] = t0[3];
#pragma unroll
                for (int mi = 0; mi < 2; mi++) {
                    mma16816h(acc[mi][2 * ng],     ah[mi], bh0);
                    if (AP == 2) mma16816h(acc[mi][2 * ng], al[mi], bh0);
                    mma16816h(acc[mi][2 * ng + 1], ah[mi], bh1);
                    if (AP == 2) mma16816h(acc[mi][2 * ng + 1], al[mi], bh1);
                }
            }
        }
    }

    // ---------------- epilogues ----------------
    const int rb = row0 + wr * 32;
    const int cb = col0 + wc * 64;

    if (HM == HM_NONE) {
#pragma unroll
        for (int mi = 0; mi < 2; mi++) {
#pragma unroll
            for (int ni = 0; ni < 8; ni++) {
                int r = rb + mi * 16 + (lane >> 2);
                int s = cb + ni * 8 + (lane & 3) * 2;
                *(float2*)(C + (size_t)r * ldc + s) =
                    make_float2(acc[mi][ni][0], acc[mi][ni][1]);
                *(float2*)(C + (size_t)(r + 8) * ldc + s) =
                    make_float2(acc[mi][ni][2], acc[mi][ni][3]);
            }
        }
    } else if (HM == HM_ROPE) {
        // write x_sparse fp16 and QR fp16
        unsigned short* Xs = g_xsh + (size_t)z * TT * NN;
        unsigned short* Qh = g_qrh + (size_t)z * TT * NN;
#pragma unroll
        for (int ni = 0; ni < 8; ni++) {
            int n0 = cb + ni * 8 + (lane & 3) * 2;
            float fr = g_fr[n0 >> 1];
#pragma unroll
            for (int mi = 0; mi < 2; mi++) {
                int rbase = rb + mi * 16 + (lane >> 2);
#pragma unroll
                for (int half = 0; half < 2; half++) {
                    int r = rbase + half * 8;
                    float v0 = fmaxf(acc[mi][ni][half * 2 + 0], 0.f);
                    float v1 = fmaxf(acc[mi][ni][half * 2 + 1], 0.f);
                    size_t base = (size_t)r * NN + n0;
                    *(unsigned*)(Xs + base) = (unsigned)f2h(v0) | ((unsigned)f2h(v1) << 16);
                    float ph   = (float)r * fr;
                    float frac = ph - floorf(ph);
                    float ang  = frac * TWO_PI_F;
                    float si, co;
                    __sincosf(ang, &si, &co);
                    float q0 = v0 * co - v1 * si;
                    float q1 = v1 * co + v0 * si;
                    *(unsigned*)(Qh + base) = (unsigned)f2h(q0) | ((unsigned)f2h(q1) << 16);
                }
            }
        }
    } else if (HM == HM_MULXY) {
        const unsigned short* xsrc = g_xsh + (size_t)z * TT * NN;
        unsigned short* Xh = g_xyh;
        unsigned short* Xl = g_xyl;
        const int colz = z * NN;
#pragma unroll
        for (int mi = 0; mi < 2; mi++) {
#pragma unroll
            for (int ni = 0; ni < 8; ni++) {
                int n0 = cb + ni * 8 + (lane & 3) * 2;
                int rbase = rb + mi * 16 + (lane >> 2);
#pragma unroll
                for (int half = 0; half < 2; half++) {
                    int r = rbase + half * 8;
                    unsigned xv = *(const unsigned*)(xsrc + (size_t)r * NN + n0);
                    float x0 = h2f((unsigned short)(xv & 0xFFFFu));
                    float x1 = h2f((unsigned short)(xv >> 16));
                    float v0 = fmaxf(acc[mi][ni][half * 2 + 0], 0.f) * x0;
                    float v1 = fmaxf(acc[mi][ni][half * 2 + 1], 0.f) * x1;
                    unsigned short l0, l1;
                    unsigned hv = pack_hl_h(v0, v1, l0, l1);
                    size_t base = (size_t)r * (NHH * NN) + colz + n0;
                    *(unsigned*)(Xh + base) = hv;
                    *(unsigned*)(Xl + base) = (unsigned)l0 | ((unsigned)l1 << 16);
                }
            }
        }
    }
}

// ---------------- weight conversion (fp16 hi only for B operands) -------------
__global__ void cvt_h(const float* __restrict__ src,
                      unsigned short* __restrict__ h, long n)
{
    long i = ((long)blockIdx.x * blockDim.x + threadIdx.x) * 4;
    if (i >= n) return;
    float4 v = *(const float4*)(src + i);
    uint2 hv;
    hv.x = (unsigned)f2h(v.x) | ((unsigned)f2h(v.y) << 16);
    hv.y = (unsigned)f2h(v.z) | ((unsigned)f2h(v.w) << 16);
    *(uint2*)(h + i) = hv;
}

// ---------------- block reduction over 256 threads ----------------
__device__ __forceinline__ float blk_sum(float v, float* sb) {
    int tid = threadIdx.x;
#pragma unroll
    for (int o = 16; o > 0; o >>= 1) v += __shfl_down_sync(0xffffffffu, v, o);
    if ((tid & 31) == 0) sb[tid >> 5] = v;
    __syncthreads();
    if (tid < 32) {
        float w = (tid < 8) ? sb[tid] : 0.f;
#pragma unroll
        for (int o = 4; o > 0; o >>= 1) w += __shfl_down_sync(0xffffffffu, w, o);
        if (tid == 0) sb[0] = w;
    }
    __syncthreads();
    float r = sb[0];
    __syncthreads();
    return r;
}

// ---------------- fp32 SGEMM (kept for lm_head) ----------------
template <int MODE>
__global__ void __launch_bounds__(256)
sgemm_kernel(const float* __restrict__ A, const float* __restrict__ B,
             float* __restrict__ C, int K,
             int lda, int ldb, int ldc,
             long offAz, long offBz, long offCz)
{
    const int z = blockIdx.z;
    A += (long)z * offAz;
    B += (long)z * offBz;
    C += (long)z * offCz;

    const int br = blockIdx.y, bc = blockIdx.x;
    const int row0 = br * 128, col0 = bc * 128;
    const int tid = threadIdx.x;
    const int tx = tid & 15, ty = tid >> 4;

    __shared__ __align__(16) float As[8][132];
    __shared__ __align__(16) float Bs[8][132];

    u64 acc2[8][4];
#pragma unroll
    for (int i = 0; i < 8; i++) {
#pragma unroll
        for (int j = 0; j < 4; j++) acc2[i][j] = 0ull;
    }

    const int ar = tid >> 1;
    const int ak = (tid & 1) * 4;
    const int bkr = tid >> 5;
    const int bcc = (tid & 31) * 4;

    const float* Ap = A + (long)(row0 + ar) * lda + ak;
    const float* Bp = B + (long)bkr * ldb + col0 + bcc;

    float4 a4 = *(const float4*)Ap;  Ap += 8;
    float4 b4 = *(const float4*)Bp;  Bp += (long)8 * ldb;

    for (int k0 = 0; k0 < K; k0 += 8) {
        As[ak + 0][ar] = a4.x; As[ak + 1][ar] = a4.y;
        As[ak + 2][ar] = a4.z; As[ak + 3][ar] = a4.w;
        Bs[bkr][bcc + 0] = b4.x; Bs[bkr][bcc + 1] = b4.y;
        Bs[bkr][bcc + 2] = b4.z; Bs[bkr][bcc + 3] = b4.w;
        __syncthreads();

        if (k0 + 8 < K) {
            a4 = *(const float4*)Ap;  Ap += 8;
            b4 = *(const float4*)Bp;  Bp += (long)8 * ldb;
        }

#pragma unroll
        for (int k = 0; k < 8; k++) {
            float a[8];
            *(float4*)&a[0] = *(const float4*)&As[k][ty * 8];
            *(float4*)&a[4] = *(const float4*)&As[k][ty * 8 + 4];
            ulonglong2 bu0 = *(const ulonglong2*)&Bs[k][tx * 8];
            ulonglong2 bu1 = *(const ulonglong2*)&Bs[k][tx * 8 + 4];
            u64 b2[4];
            b2[0] = bu0.x; b2[1] = bu0.y; b2[2] = bu1.x; b2[3] = bu1.y;
            u64 a2[8];
#pragma unroll
            for (int i = 0; i < 8; i++) a2[i] = dup2(a[i]);
#pragma unroll
            for (int i = 0; i < 8; i++) {
#pragma unroll
                for (int j = 0; j < 4; j++) ffma2(acc2[i][j], a2[i], b2[j]);
            }
        }
        __syncthreads();
    }

    float acc[8][8];
#pragma unroll
    for (int i = 0; i < 8; i++) {
#pragma unroll
        for (int j = 0; j < 4; j++) unpack2(acc2[i][j], acc[i][2 * j], acc[i][2 * j + 1]);
    }

#pragma unroll
    for (int i = 0; i < 8; i++) {
        long base = (long)(row0 + ty * 8 + i) * ldc + col0 + tx * 8;
        *(float4*)(C + base)     = make_float4(acc[i][0], acc[i][1], acc[i][2], acc[i][3]);
        *(float4*)(C + base + 4) = make_float4(acc[i][4], acc[i][5], acc[i][6], acc[i][7]);
    }
}

// ---------------- small elementwise kernels ----------------
__global__ void embed_ln_kernel(const int* __restrict__ idx,
                                const float* __restrict__ embed)
{
    __shared__ float sb[8];
    int t = blockIdx.x, d = threadIdx.x;
    float v   = embed[idx[t] * DD + d];
    float mu  = blk_sum(v, sb) * (1.f / DD);
    float dv  = v - mu;
    float var = blk_sum(dv * dv, sb) * (1.f / DD);
    float o = dv / sqrtf(var + LNEPS);
    g_x[t * DD + d] = o;
    unsigned short hh = f2h(o);
    g_xh[t * DD + d] = hh;
    g_xl[t * DD + d] = f2h(o - h2f(hh));
}

__global__ void ln_rows_kernel(float* __restrict__ buf)
{
    __shared__ float sb[8];
    long r = blockIdx.x;
    int  d = threadIdx.x;
    float v   = buf[r * DD + d];
    float mu  = blk_sum(v, sb) * (1.f / DD);
    float dv  = v - mu;
    float var = blk_sum(dv * dv, sb) * (1.f / DD);
    float o = dv / sqrtf(var + LNEPS);
    buf[r * DD + d] = o;
    unsigned short hh = f2h(o);
    g_ykvh[r * DD + d] = hh;
    g_ykvl[r * DD + d] = f2h(o - h2f(hh));
}

__global__ void mlp_finish_kernel()
{
    __shared__ float sb[8];
    int t = blockIdx.x, d = threadIdx.x;
    float s = 0.f;
#pragma unroll
    for (int kz = 0; kz < SPLITK; kz++)
        s += g_part[(size_t)kz * TT * DD + t * DD + d];

    float mu  = blk_sum(s, sb) * (1.f / DD);
    float dv  = s - mu;
    float var = blk_sum(dv * dv, sb) * (1.f / DD);
    float a   = dv / sqrtf(var + LNEPS);

    float b = g_x[t * DD + d] + a;
    mu  = blk_sum(b, sb) * (1.f / DD);
    dv  = b - mu;
    var = blk_sum(dv * dv, sb) * (1.f / DD);
    float o = dv / sqrtf(var + LNEPS);
    g_x[t * DD + d] = o;
    unsigned short hh = f2h(o);
    g_xh[t * DD + d] = hh;
    g_xl[t * DD + d] = f2h(o - h2f(hh));
}

// ---------------- launch ----------------
extern "C" void kernel_launch(void* const* d_in, const int* in_sizes, int n_in,
                              void* d_out, int out_size)
{
    (void)in_sizes; (void)n_in; (void)out_size;
    const int*   idx       = (const int*)d_in[0];
    const float* embed     = (const float*)d_in[1];
    const float* encoder   = (const float*)d_in[2];
    const float* encoder_v = (const float*)d_in[3];
    const float* decoder   = (const float*)d_in[4];
    const float* lm_head   = (const float*)d_in[5];
    float*       out       = (float*)d_out;

    float* x = 0; float* ykv = 0; float* part = 0;
    unsigned short *sch = 0;
    unsigned short *qrh = 0, *xyh = 0, *xyl = 0;
    unsigned short *xh = 0, *xl = 0, *ykvh = 0, *ykvl = 0;
    unsigned short *ench = 0, *encvh = 0, *dech = 0;
    cudaGetSymbolAddress((void**)&x,      g_x);
    cudaGetSymbolAddress((void**)&sch,    g_sch);
    cudaGetSymbolAddress((void**)&ykv,    g_ykv);
    cudaGetSymbolAddress((void**)&part,   g_part);
    cudaGetSymbolAddress((void**)&qrh,    g_qrh);
    cudaGetSymbolAddress((void**)&xyh,    g_xyh);
    cudaGetSymbolAddress((void**)&xyl,    g_xyl);
    cudaGetSymbolAddress((void**)&xh,     g_xh);
    cudaGetSymbolAddress((void**)&xl,     g_xl);
    cudaGetSymbolAddress((void**)&ykvh,   g_ykvh);
    cudaGetSymbolAddress((void**)&ykvl,   g_ykvl);
    cudaGetSymbolAddress((void**)&ench,   g_ench);
    cudaGetSymbolAddress((void**)&encvh,  g_encvh);
    cudaGetSymbolAddress((void**)&dech,   g_dech);

    cudaFuncSetAttribute(scores_hmma, cudaFuncAttributeMaxDynamicSharedMemorySize, SC_SMEM);
    cudaFuncSetAttribute(hmma_gemm<HM_NONE, 0, 2>,  cudaFuncAttributeMaxDynamicSharedMemorySize, H32_SMEM);
    cudaFuncSetAttribute(hmma_gemm<HM_NONE, 1, 1>,  cudaFuncAttributeMaxDynamicSharedMemorySize, H32_SMEM);
    cudaFuncSetAttribute(hmma_gemm<HM_ROPE, 0, 2>,  cudaFuncAttributeMaxDynamicSharedMemorySize, H32_SMEM);
    cudaFuncSetAttribute(hmma_gemm<HM_MULXY, 0, 2>, cudaFuncAttributeMaxDynamicSharedMemorySize, H32_SMEM);

    const long WN = (long)NHH * DD * NN;
    init_freq<<<(NN / 2 + 255) / 256, 256>>>();
    cvt_h<<<(int)(WN / 4 / 256), 256>>>(encoder,   ench,  WN);
    cvt_h<<<(int)(WN / 4 / 256), 256>>>(encoder_v, encvh, WN);
    cvt_h<<<(int)(WN / 4 / 256), 256>>>(decoder,   dech,  WN);

    embed_ln_kernel<<<TT, 256>>>(idx, embed);

    for (int l = 0; l < 2; l++) {
        // x_sparse fp16 -> g_xsh; QR fp16 -> g_qrh  (C unused)
        hmma_gemm<HM_ROPE, 0, 2><<<dim3(NN / 128, TT / 128, NHH), 256, H32_SMEM>>>(
            xh, xl, ench, part, DD, DD, NN, NN,
            0L, (long)DD * NN, 0L);

        // scores = mask .* (QR @ QR^T) — fp16 1-pass, fp16 out
        scores_hmma<<<dim3(TT / 128, TT / 128, NHH), 256, SC_SMEM>>>(qrh, sch);

        // yKV = scores @ x — causal-bounded, 1-pass scores
        hmma_gemm<HM_NONE, 1, 1><<<dim3(DD / 128, TT / 128, NHH), 256, H32_SMEM>>>(
            sch, sch, xh, ykv, TT, TT, DD, DD,
            (long)TT * TT, 0L, (long)TT * DD);

        ln_rows_kernel<<<NHH * TT, 256>>>(ykv);

        // xy = relu(yKV @ encoder_v) * x_sparse -> fp16 hi/lo  (C unused)
        hmma_gemm<HM_MULXY, 0, 2><<<dim3(NN / 128, TT / 128, NHH), 256, H32_SMEM>>>(
            ykvh, ykvl, encvh, part, DD, DD, NN, 0,
            (long)TT * DD, (long)DD * NN, 0L);

        // yMLP partials = xy @ decoder (split-K 16)
        hmma_gemm<HM_NONE, 0, 2><<<dim3(DD / 128, TT / 128, SPLITK), 256, H32_SMEM>>>(
            xyh, xyl, dech, part, KSPL, NHH * NN, DD, DD,
            (long)KSPL, (long)KSPL * DD, (long)TT * DD);

        mlp_finish_kernel<<<TT, 256>>>();
    }

    sgemm_kernel<EM_NONE><<<dim3(VOC / 128, TT / 128, 1), 256>>>(
        x, lm_head, out, DD, DD, VOC, VOC, 0L, 0L, 0L);
}

// round 17
// speedup vs baseline: 2.6192x; 1.2381x over previous
#include <cuda_runtime.h>
#include <math.h>
#include <stdint.h>

// ---------------- problem constants ----------------
#define NHH   4
#define DD    256
#define NN    8192
#define TT    2048
#define VOC   256
#define SPLITK 16
#define KSPL  2048              // NHH*NN/SPLITK
#define LNEPS 1e-5f
#define TWO_PI_F 6.28318530717958647692f

// ---------------- scratch (static device globals) ----
__device__ float g_x[TT * DD];
__device__ unsigned short g_xh[TT * DD];
__device__ unsigned short g_xsh[(size_t)NHH * TT * NN];   // x_sparse (fp16)
__device__ unsigned short g_sch[(size_t)NHH * TT * TT];   // scores (fp16)
__device__ float g_ykv[(size_t)NHH * TT * DD];
__device__ unsigned short g_ykvh[(size_t)NHH * TT * DD];
__device__ float g_part[(size_t)SPLITK * TT * DD];
__device__ unsigned short g_qrh[(size_t)NHH * TT * NN];   // QR (fp16)
__device__ unsigned short g_xyh[(size_t)NHH * TT * NN];
__device__ unsigned short g_ench[(size_t)NHH * DD * NN];
__device__ unsigned short g_encvh[(size_t)NHH * DD * NN];
__device__ unsigned short g_dech[(size_t)NHH * NN * DD];
__device__ float g_fr[NN / 2];                            // rope freq / 2pi per even n

enum { EM_NONE = 0 };
enum { HM_NONE = 0, HM_ROPE = 1, HM_MULXY = 2 };

typedef unsigned long long u64;

// ---------------- packed f32x2 helpers ----------------
__device__ __forceinline__ void ffma2(u64& d, u64 a, u64 b) {
    asm("fma.rn.f32x2 %0, %1, %2, %0;" : "+l"(d) : "l"(a), "l"(b));
}
__device__ __forceinline__ u64 dup2(float x) {
    u64 r;
    asm("mov.b64 %0, {%1, %1};" : "=l"(r) : "r"(__float_as_uint(x)));
    return r;
}
__device__ __forceinline__ void unpack2(u64 v, float& lo, float& hi) {
    unsigned a, b;
    asm("mov.b64 {%0, %1}, %2;" : "=r"(a), "=r"(b) : "l"(v));
    lo = __uint_as_float(a); hi = __uint_as_float(b);
}

// ---------------- fp16 bit helpers ----------------
__device__ __forceinline__ unsigned short f2h(float x) {
    unsigned short r;
    asm("cvt.rn.f16.f32 %0, %1;" : "=h"(r) : "f"(x));
    return r;
}
__device__ __forceinline__ float h2f(unsigned short h) {
    float r;
    asm("cvt.f32.f16 %0, %1;" : "=f"(r) : "h"(h));
    return r;
}

// ---------------- warp-MMA helpers ----------------
__device__ __forceinline__ uint32_t smem_to_u32(const void* smem_ptr) {
    uint32_t addr;
    asm("{ .reg .u64 tmp; cvta.to.shared.u64 tmp, %1; cvt.u32.u64 %0, tmp; }"
        : "=r"(addr) : "l"(smem_ptr));
    return addr;
}
__device__ __forceinline__ void ldsm4(uint32_t* r, uint32_t addr) {
    asm volatile("ldmatrix.sync.aligned.m8n8.x4.shared.b16 {%0,%1,%2,%3}, [%4];"
        : "=r"(r[0]), "=r"(r[1]), "=r"(r[2]), "=r"(r[3]) : "r"(addr));
}
__device__ __forceinline__ void ldsm4t(uint32_t* r, uint32_t addr) {
    asm volatile("ldmatrix.sync.aligned.m8n8.x4.trans.shared.b16 {%0,%1,%2,%3}, [%4];"
        : "=r"(r[0]), "=r"(r[1]), "=r"(r[2]), "=r"(r[3]) : "r"(addr));
}
__device__ __forceinline__ void mma16816h(float* c, const uint32_t* a, const uint32_t* b) {
    asm volatile(
        "mma.sync.aligned.m16n8k16.row.col.f32.f16.f16.f32 "
        "{%0,%1,%2,%3}, {%4,%5,%6,%7}, {%8,%9}, {%0,%1,%2,%3};"
        : "+f"(c[0]), "+f"(c[1]), "+f"(c[2]), "+f"(c[3])
        : "r"(a[0]), "r"(a[1]), "r"(a[2]), "r"(a[3]), "r"(b[0]), "r"(b[1]));
}
#define CP_ASYNC16(dst, src) \
    asm volatile("cp.async.cg.shared.global [%0], [%1], 16;" :: "r"(dst), "l"(src))
#define CP_COMMIT() asm volatile("cp.async.commit_group;" ::: "memory")
#define CP_WAIT(n)  asm volatile("cp.async.wait_group %0;" :: "n"(n) : "memory")

__device__ __forceinline__ uint32_t sw64(uint32_t b)  { return b ^ ((b >> 3) & 0x30); }
__device__ __forceinline__ uint32_t sw128(uint32_t b) { return b ^ ((b >> 3) & 0x70); }
__device__ __forceinline__ uint32_t sw256(uint32_t b) { return b ^ ((b >> 4) & 0x70); }

// generic small-K config: K-chunk 32, 3 stages (A, B) of 16KB, 2 CTAs/SM
#define H32_A    8192            // 128 rows x 64B
#define H32_STG  16384
#define H32_SMEM (3 * H32_STG + 1024)

// scores config: fp16 1-pass, Kc=64, 2 tiles/stage (A, B), 2 stages, 2 CTAs/SM
#define SC_T     16384           // 128 rows x 128B
#define SC_STG   (2 * SC_T)      // 32KB
#define SC_SMEM  (2 * SC_STG + 1024)

// ---------------- rope freq table init ----------------
__global__ void init_freq()
{
    int i = blockIdx.x * blockDim.x + threadIdx.x;
    if (i >= NN / 2) return;
    int n0 = i * 2;
    float a = (float)exp2(-(double)n0 / 512.0);
    g_fr[i] = a / TWO_PI_F;
}

// ================= HMMA scores kernel (fp16 1-pass, fp16 out) =================
__global__ void __launch_bounds__(256, 2)
scores_hmma(const unsigned short* __restrict__ qh,
            unsigned short* __restrict__ sch)
{
    const int br = blockIdx.y;
    const int bc = blockIdx.x;
    const int h  = blockIdx.z;
    if (bc > br) return;

    extern __shared__ char dsm[];
    const int tid  = threadIdx.x;
    const int wid  = tid >> 5;
    const int lane = tid & 31;
    const int wr   = wid & 3;
    const int wc   = wid >> 2;
    const int row0 = br * 128;
    const int col0 = bc * 128;

    const uint32_t raw = smem_to_u32(dsm);
    const uint32_t sb  = (raw + 1023u) & ~1023u;

    const size_t hb = (size_t)h * TT * NN;
    const unsigned short* srcs[2];
    srcs[0] = qh + hb + (size_t)row0 * NN;
    srcs[1] = qh + hb + (size_t)col0 * NN;

    float acc[2][8][4];
#pragma unroll
    for (int mi = 0; mi < 2; mi++)
#pragma unroll
        for (int ni = 0; ni < 8; ni++)
#pragma unroll
            for (int q = 0; q < 4; q++) acc[mi][ni][q] = 0.f;

    const int NITER = NN / 64;

    auto load_stage = [&](int st, int kc0) {
        const uint32_t stg = sb + st * SC_STG;
#pragma unroll
        for (int t2 = 0; t2 < 2; t2++) {
            const unsigned short* src = srcs[t2] + kc0;
            const uint32_t tb = stg + t2 * SC_T;
#pragma unroll
            for (int i = 0; i < 4; i++) {
                int idx = i * 256 + tid;
                int r = idx >> 3;
                int c = idx & 7;
                CP_ASYNC16(tb + sw128(r * 128 + c * 16), src + (size_t)r * NN + c * 8);
            }
        }
    };

    load_stage(0, 0);
    CP_COMMIT();

    for (int it = 0; it < NITER; it++) {
        CP_WAIT(0);
        __syncthreads();
        if (it + 1 < NITER) {
            load_stage((it + 1) & 1, (it + 1) * 64);
            CP_COMMIT();
        }

        const uint32_t stg = sb + (it & 1) * SC_STG;
#pragma unroll
        for (int ks = 0; ks < 4; ks++) {
            const int lrow  = lane & 15;
            const int chunk = ks * 2 + (lane >> 4);

            uint32_t ah[2][4];
#pragma unroll
            for (int mi = 0; mi < 2; mi++) {
                int row = wr * 32 + mi * 16 + lrow;
                uint32_t off = sw128(row * 128 + chunk * 16);
                ldsm4(ah[mi], stg + 0 * SC_T + off);
            }

#pragma unroll
            for (int ng = 0; ng < 4; ng++) {
                int row = wc * 64 + ng * 16 + lrow;
                uint32_t off = sw128(row * 128 + chunk * 16);
                uint32_t t0[4];
                ldsm4(t0, stg + 1 * SC_T + off);
                uint32_t bh0[2], bh1[2];
                bh0[0] = t0[0]; bh0[1] = t0[2];
                bh1[0] = t0[1]; bh1[1] = t0[3];
#pragma unroll
                for (int mi = 0; mi < 2; mi++) {
                    mma16816h(acc[mi][2 * ng],     ah[mi], bh0);
                    mma16816h(acc[mi][2 * ng + 1], ah[mi], bh1);
                }
            }
        }
    }

    // epilogue: strictly-lower mask, write scores as fp16
    unsigned short* dh = sch + (size_t)h * TT * TT;
    const int rb = row0 + wr * 32;
    const int cb = col0 + wc * 64;
#pragma unroll
    for (int mi = 0; mi < 2; mi++) {
#pragma unroll
        for (int ni = 0; ni < 8; ni++) {
            int r = rb + mi * 16 + (lane >> 2);
            int s = cb + ni * 8 + (lane & 3) * 2;
#pragma unroll
            for (int half = 0; half < 2; half++) {
                int rr = r + half * 8;
                float v0 = (rr > s)     ? acc[mi][ni][half * 2 + 0] : 0.f;
                float v1 = (rr > s + 1) ? acc[mi][ni][half * 2 + 1] : 0.f;
                *(unsigned*)(dh + (size_t)rr * TT + s) =
                    (unsigned)f2h(v0) | ((unsigned)f2h(v1) << 16);
            }
        }
    }
}

// ================= generic HMMA GEMM (fp16 1-pass, Kc=32, 3-stage, 2 CTAs/SM) ==
// A [M,K] k-contig (64B rows, SW64), B [K,N] n-contig (256B rows, SW256).
// acc = A * B (fp32 accum).
template <int HM, int CAUSAL>
__global__ void __launch_bounds__(256, 2)
hmma_gemm(const unsigned short* __restrict__ Ah,
          const unsigned short* __restrict__ Bh,
          float* __restrict__ C, int K, int lda, int ldb, int ldc,
          long offAz, long offBz, long offCz)
{
    const int z = blockIdx.z;
    Ah += (long)z * offAz;
    Bh += (long)z * offBz;
    if (HM == HM_NONE) C += (long)z * offCz;

    extern __shared__ char dsm[];
    const int tid  = threadIdx.x;
    const int wid  = tid >> 5;
    const int lane = tid & 31;
    const int wr   = wid & 3;
    const int wc   = wid >> 2;
    const int row0 = blockIdx.y * 128;
    const int col0 = blockIdx.x * 128;

    const uint32_t raw = smem_to_u32(dsm);
    const uint32_t sb  = (raw + 1023u) & ~1023u;

    const unsigned short* A0 = Ah + (size_t)row0 * lda;

    float acc[2][8][4];
#pragma unroll
    for (int mi = 0; mi < 2; mi++)
#pragma unroll
        for (int ni = 0; ni < 8; ni++)
#pragma unroll
            for (int q = 0; q < 4; q++) acc[mi][ni][q] = 0.f;

    const int NITER = (CAUSAL ? (row0 + 128) : K) / 32;

    auto load_stage = [&](int st, int k0) {
        const uint32_t stg = sb + st * H32_STG;
#pragma unroll
        for (int i = 0; i < 2; i++) {
            int idx = i * 256 + tid;
            int r = idx >> 2;
            int c = idx & 3;
            uint32_t off = sw64(r * 64 + c * 16);
            CP_ASYNC16(stg + off, A0 + (size_t)r * lda + k0 + c * 8);
        }
#pragma unroll
        for (int i = 0; i < 2; i++) {
            int idx = i * 256 + tid;
            int r = idx >> 4;
            int c = idx & 15;
            uint32_t off = sw256(r * 256 + c * 16);
            CP_ASYNC16(stg + H32_A + off, Bh + (size_t)(k0 + r) * ldb + col0 + c * 8);
        }
    };

    load_stage(0, 0);
    CP_COMMIT();
    if (NITER > 1) { load_stage(1, 32); CP_COMMIT(); }

    for (int it = 0; it < NITER; it++) {
        if (it + 1 < NITER) { CP_WAIT(1); }
        else                { CP_WAIT(0); }
        __syncthreads();
        if (it + 2 < NITER) {
            load_stage((it + 2) % 3, (it + 2) * 32);
            CP_COMMIT();
        }

        const uint32_t stg = sb + (it % 3) * H32_STG;
#pragma unroll
        for (int ks = 0; ks < 2; ks++) {
            const int lrow = lane & 15;

            uint32_t ah[2][4];
#pragma unroll
            for (int mi = 0; mi < 2; mi++) {
                int row = wr * 32 + mi * 16 + lrow;
                uint32_t off = sw64(row * 64 + (ks * 2 + (lane >> 4)) * 16);
                ldsm4(ah[mi], stg + off);
            }

#pragma unroll
            for (int ng = 0; ng < 4; ng++) {
                int kk = ks * 16 + lrow;
                int nc = wc * 64 + ng * 16 + (lane >> 4) * 8;
                uint32_t off = sw256(kk * 256 + nc * 2);
                uint32_t t0[4];
                ldsm4t(t0, stg + H32_A + off);
                uint32_t bh0[2], bh1[2];
                bh0[0] = t0[0]; bh0[1] = t0[1];
                bh1[0] = t0[2]; bh1[1] = t0[3];
#pragma unroll
                for (int mi = 0; mi < 2; mi++) {
                    mma16816h(acc[mi][2 * ng],     ah[mi], bh0);
                    mma16816h(acc[mi][2 * ng + 1], ah[mi], bh1);
                }
            }
        }
    }

    // ---------------- epilogues ----------------
    const int rb = row0 + wr * 32;
    const int cb = col0 + wc * 64;

    if (HM == HM_NONE) {
#pragma unroll
        for (int mi = 0; mi < 2; mi++) {
#pragma unroll
            for (int ni = 0; ni < 8; ni++) {
                int r = rb + mi * 16 + (lane >> 2);
                int s = cb + ni * 8 + (lane & 3) * 2;
                *(float2*)(C + (size_t)r * ldc + s) =
                    make_float2(acc[mi][ni][0], acc[mi][ni][1]);
                *(float2*)(C + (size_t)(r + 8) * ldc + s) =
                    make_float2(acc[mi][ni][2], acc[mi][ni][3]);
            }
        }
    } else if (HM == HM_ROPE) {
        unsigned short* Xs = g_xsh + (size_t)z * TT * NN;
        unsigned short* Qh = g_qrh + (size_t)z * TT * NN;
#pragma unroll
        for (int ni = 0; ni < 8; ni++) {
            int n0 = cb + ni * 8 + (lane & 3) * 2;
            float fr = g_fr[n0 >> 1];
#pragma unroll
            for (int mi = 0; mi < 2; mi++) {
                int rbase = rb + mi * 16 + (lane >> 2);
#pragma unroll
                for (int half = 0; half < 2; half++) {
                    int r = rbase + half * 8;
                    float v0 = fmaxf(acc[mi][ni][half * 2 + 0], 0.f);
                    float v1 = fmaxf(acc[mi][ni][half * 2 + 1], 0.f);
                    size_t base = (size_t)r * NN + n0;
                    *(unsigned*)(Xs + base) = (unsigned)f2h(v0) | ((unsigned)f2h(v1) << 16);
                    float ph   = (float)r * fr;
                    float frac = ph - floorf(ph);
                    float ang  = frac * TWO_PI_F;
                    float si, co;
                    __sincosf(ang, &si, &co);
                    float q0 = v0 * co - v1 * si;
                    float q1 = v1 * co + v0 * si;
                    *(unsigned*)(Qh + base) = (unsigned)f2h(q0) | ((unsigned)f2h(q1) << 16);
                }
            }
        }
    } else if (HM == HM_MULXY) {
        const unsigned short* xsrc = g_xsh + (size_t)z * TT * NN;
        unsigned short* Xh = g_xyh;
        const int colz = z * NN;
#pragma unroll
        for (int mi = 0; mi < 2; mi++) {
#pragma unroll
            for (int ni = 0; ni < 8; ni++) {
                int n0 = cb + ni * 8 + (lane & 3) * 2;
                int rbase = rb + mi * 16 + (lane >> 2);
#pragma unroll
                for (int half = 0; half < 2; half++) {
                    int r = rbase + half * 8;
                    unsigned xv = *(const unsigned*)(xsrc + (size_t)r * NN + n0);
                    float x0 = h2f((unsigned short)(xv & 0xFFFFu));
                    float x1 = h2f((unsigned short)(xv >> 16));
                    float v0 = fmaxf(acc[mi][ni][half * 2 + 0], 0.f) * x0;
                    float v1 = fmaxf(acc[mi][ni][half * 2 + 1], 0.f) * x1;
                    size_t base = (size_t)r * (NHH * NN) + colz + n0;
                    *(unsigned*)(Xh + base) = (unsigned)f2h(v0) | ((unsigned)f2h(v1) << 16);
                }
            }
        }
    }
}

// ---------------- weight conversion (fp16) ----------------
__global__ void cvt_h(const float* __restrict__ src,
                      unsigned short* __restrict__ h, long n)
{
    long i = ((long)blockIdx.x * blockDim.x + threadIdx.x) * 4;
    if (i >= n) return;
    float4 v = *(const float4*)(src + i);
    uint2 hv;
    hv.x = (unsigned)f2h(v.x) | ((unsigned)f2h(v.y) << 16);
    hv.y = (unsigned)f2h(v.z) | ((unsigned)f2h(v.w) << 16);
    *(uint2*)(h + i) = hv;
}

// ---------------- block reduction over 256 threads ----------------
__device__ __forceinline__ float blk_sum(float v, float* sb) {
    int tid = threadIdx.x;
#pragma unroll
    for (int o = 16; o > 0; o >>= 1) v += __shfl_down_sync(0xffffffffu, v, o);
    if ((tid & 31) == 0) sb[tid >> 5] = v;
    __syncthreads();
    if (tid < 32) {
        float w = (tid < 8) ? sb[tid] : 0.f;
#pragma unroll
        for (int o = 4; o > 0; o >>= 1) w += __shfl_down_sync(0xffffffffu, w, o);
        if (tid == 0) sb[0] = w;
    }
    __syncthreads();
    float r = sb[0];
    __syncthreads();
    return r;
}

// ---------------- fp32 SGEMM (kept for lm_head) ----------------
template <int MODE>
__global__ void __launch_bounds__(256)
sgemm_kernel(const float* __restrict__ A, const float* __restrict__ B,
             float* __restrict__ C, int K,
             int lda, int ldb, int ldc,
             long offAz, long offBz, long offCz)
{
    const int z = blockIdx.z;
    A += (long)z * offAz;
    B += (long)z * offBz;
    C += (long)z * offCz;

    const int br = blockIdx.y, bc = blockIdx.x;
    const int row0 = br * 128, col0 = bc * 128;
    const int tid = threadIdx.x;
    const int tx = tid & 15, ty = tid >> 4;

    __shared__ __align__(16) float As[8][132];
    __shared__ __align__(16) float Bs[8][132];

    u64 acc2[8][4];
#pragma unroll
    for (int i = 0; i < 8; i++) {
#pragma unroll
        for (int j = 0; j < 4; j++) acc2[i][j] = 0ull;
    }

    const int ar = tid >> 1;
    const int ak = (tid & 1) * 4;
    const int bkr = tid >> 5;
    const int bcc = (tid & 31) * 4;

    const float* Ap = A + (long)(row0 + ar) * lda + ak;
    const float* Bp = B + (long)bkr * ldb + col0 + bcc;

    float4 a4 = *(const float4*)Ap;  Ap += 8;
    float4 b4 = *(const float4*)Bp;  Bp += (long)8 * ldb;

    for (int k0 = 0; k0 < K; k0 += 8) {
        As[ak + 0][ar] = a4.x; As[ak + 1][ar] = a4.y;
        As[ak + 2][ar] = a4.z; As[ak + 3][ar] = a4.w;
        Bs[bkr][bcc + 0] = b4.x; Bs[bkr][bcc + 1] = b4.y;
        Bs[bkr][bcc + 2] = b4.z; Bs[bkr][bcc + 3] = b4.w;
        __syncthreads();

        if (k0 + 8 < K) {
            a4 = *(const float4*)Ap;  Ap += 8;
            b4 = *(const float4*)Bp;  Bp += (long)8 * ldb;
        }

#pragma unroll
        for (int k = 0; k < 8; k++) {
            float a[8];
            *(float4*)&a[0] = *(const float4*)&As[k][ty * 8];
            *(float4*)&a[4] = *(const float4*)&As[k][ty * 8 + 4];
            ulonglong2 bu0 = *(const ulonglong2*)&Bs[k][tx * 8];
            ulonglong2 bu1 = *(const ulonglong2*)&Bs[k][tx * 8 + 4];
            u64 b2[4];
            b2[0] = bu0.x; b2[1] = bu0.y; b2[2] = bu1.x; b2[3] = bu1.y;
            u64 a2[8];
#pragma unroll
            for (int i = 0; i < 8; i++) a2[i] = dup2(a[i]);
#pragma unroll
            for (int i = 0; i < 8; i++) {
#pragma unroll
                for (int j = 0; j < 4; j++) ffma2(acc2[i][j], a2[i], b2[j]);
            }
        }
        __syncthreads();
    }

    float acc[8][8];
#pragma unroll
    for (int i = 0; i < 8; i++) {
#pragma unroll
        for (int j = 0; j < 4; j++) unpack2(acc2[i][j], acc[i][2 * j], acc[i][2 * j + 1]);
    }

#pragma unroll
    for (int i = 0; i < 8; i++) {
        long base = (long)(row0 + ty * 8 + i) * ldc + col0 + tx * 8;
        *(float4*)(C + base)     = make_float4(acc[i][0], acc[i][1], acc[i][2], acc[i][3]);
        *(float4*)(C + base + 4) = make_float4(acc[i][4], acc[i][5], acc[i][6], acc[i][7]);
    }
}

// ---------------- small elementwise kernels ----------------
__global__ void embed_ln_kernel(const int* __restrict__ idx,
                                const float* __restrict__ embed)
{
    __shared__ float sb[8];
    int t = blockIdx.x, d = threadIdx.x;
    float v   = embed[idx[t] * DD + d];
    float mu  = blk_sum(v, sb) * (1.f / DD);
    float dv  = v - mu;
    float var = blk_sum(dv * dv, sb) * (1.f / DD);
    float o = dv / sqrtf(var + LNEPS);
    g_x[t * DD + d] = o;
    g_xh[t * DD + d] = f2h(o);
}

__global__ void ln_rows_kernel(float* __restrict__ buf)
{
    __shared__ float sb[8];
    long r = blockIdx.x;
    int  d = threadIdx.x;
    float v   = buf[r * DD + d];
    float mu  = blk_sum(v, sb) * (1.f / DD);
    float dv  = v - mu;
    float var = blk_sum(dv * dv, sb) * (1.f / DD);
    float o = dv / sqrtf(var + LNEPS);
    buf[r * DD + d] = o;
    g_ykvh[r * DD + d] = f2h(o);
}

__global__ void mlp_finish_kernel()
{
    __shared__ float sb[8];
    int t = blockIdx.x, d = threadIdx.x;
    float s = 0.f;
#pragma unroll
    for (int kz = 0; kz < SPLITK; kz++)
        s += g_part[(size_t)kz * TT * DD + t * DD + d];

    float mu  = blk_sum(s, sb) * (1.f / DD);
    float dv  = s - mu;
    float var = blk_sum(dv * dv, sb) * (1.f / DD);
    float a   = dv / sqrtf(var + LNEPS);

    float b = g_x[t * DD + d] + a;
    mu  = blk_sum(b, sb) * (1.f / DD);
    dv  = b - mu;
    var = blk_sum(dv * dv, sb) * (1.f / DD);
    float o = dv / sqrtf(var + LNEPS);
    g_x[t * DD + d] = o;
    g_xh[t * DD + d] = f2h(o);
}

// ---------------- launch ----------------
extern "C" void kernel_launch(void* const* d_in, const int* in_sizes, int n_in,
                              void* d_out, int out_size)
{
    (void)in_sizes; (void)n_in; (void)out_size;
    const int*   idx       = (const int*)d_in[0];
    const float* embed     = (const float*)d_in[1];
    const float* encoder   = (const float*)d_in[2];
    const float* encoder_v = (const float*)d_in[3];
    const float* decoder   = (const float*)d_in[4];
    const float* lm_head   = (const float*)d_in[5];
    float*       out       = (float*)d_out;

    float* x = 0; float* ykv = 0; float* part = 0;
    unsigned short *sch = 0;
    unsigned short *qrh = 0, *xyh = 0;
    unsigned short *xh = 0, *ykvh = 0;
    unsigned short *ench = 0, *encvh = 0, *dech = 0;
    cudaGetSymbolAddress((void**)&x,      g_x);
    cudaGetSymbolAddress((void**)&sch,    g_sch);
    cudaGetSymbolAddress((void**)&ykv,    g_ykv);
    cudaGetSymbolAddress((void**)&part,   g_part);
    cudaGetSymbolAddress((void**)&qrh,    g_qrh);
    cudaGetSymbolAddress((void**)&xyh,    g_xyh);
    cudaGetSymbolAddress((void**)&xh,     g_xh);
    cudaGetSymbolAddress((void**)&ykvh,   g_ykvh);
    cudaGetSymbolAddress((void**)&ench,   g_ench);
    cudaGetSymbolAddress((void**)&encvh,  g_encvh);
    cudaGetSymbolAddress((void**)&dech,   g_dech);

    cudaFuncSetAttribute(scores_hmma, cudaFuncAttributeMaxDynamicSharedMemorySize, SC_SMEM);
    cudaFuncSetAttribute(hmma_gemm<HM_NONE, 0>,  cudaFuncAttributeMaxDynamicSharedMemorySize, H32_SMEM);
    cudaFuncSetAttribute(hmma_gemm<HM_NONE, 1>,  cudaFuncAttributeMaxDynamicSharedMemorySize, H32_SMEM);
    cudaFuncSetAttribute(hmma_gemm<HM_ROPE, 0>,  cudaFuncAttributeMaxDynamicSharedMemorySize, H32_SMEM);
    cudaFuncSetAttribute(hmma_gemm<HM_MULXY, 0>, cudaFuncAttributeMaxDynamicSharedMemorySize, H32_SMEM);

    const long WN = (long)NHH * DD * NN;
    init_freq<<<(NN / 2 + 255) / 256, 256>>>();
    cvt_h<<<(int)(WN / 4 / 256), 256>>>(encoder,   ench,  WN);
    cvt_h<<<(int)(WN / 4 / 256), 256>>>(encoder_v, encvh, WN);
    cvt_h<<<(int)(WN / 4 / 256), 256>>>(decoder,   dech,  WN);

    embed_ln_kernel<<<TT, 256>>>(idx, embed);

    for (int l = 0; l < 2; l++) {
        // x_sparse fp16 -> g_xsh; QR fp16 -> g_qrh  (C unused)
        hmma_gemm<HM_ROPE, 0><<<dim3(NN / 128, TT / 128, NHH), 256, H32_SMEM>>>(
            xh, ench, part, DD, DD, NN, NN,
            0L, (long)DD * NN, 0L);

        // scores = mask .* (QR @ QR^T) — fp16 1-pass, fp16 out
        scores_hmma<<<dim3(TT / 128, TT / 128, NHH), 256, SC_SMEM>>>(qrh, sch);

        // yKV = scores @ x — causal-bounded
        hmma_gemm<HM_NONE, 1><<<dim3(DD / 128, TT / 128, NHH), 256, H32_SMEM>>>(
            sch, xh, ykv, TT, TT, DD, DD,
            (long)TT * TT, 0L, (long)TT * DD);

        ln_rows_kernel<<<NHH * TT, 256>>>(ykv);

        // xy = relu(yKV @ encoder_v) * x_sparse -> fp16  (C unused)
        hmma_gemm<HM_MULXY, 0><<<dim3(NN / 128, TT / 128, NHH), 256, H32_SMEM>>>(
            ykvh, encvh, part, DD, DD, NN, 0,
            (long)TT * DD, (long)DD * NN, 0L);

        // yMLP partials = xy @ decoder (split-K 16)
        hmma_gemm<HM_NONE, 0><<<dim3(DD / 128, TT / 128, SPLITK), 256, H32_SMEM>>>(
            xyh, dech, part, KSPL, NHH * NN, DD, DD,
            (long)KSPL, (long)KSPL * DD, (long)TT * DD);

        mlp_finish_kernel<<<TT, 256>>>();
    }

    sgemm_kernel<EM_NONE><<<dim3(VOC / 128, TT / 128, 1), 256>>>(
        x, lm_head, out, DD, DD, VOC, VOC, 0L, 0L, 0L);
}